// round 6
// baseline (speedup 1.0000x reference)
#include <cuda_runtime.h>
#include <math.h>

// ---------------- problem constants ----------------
#define TN    131072     // local tx nodes
#define ELN   524288     // local edges
#define NNODE 50000      // global contract nodes
#define EGN   400000     // global edges
#define BB    8192       // batch of contracts
#define HH    128        // hidden dim
#define FGN   7          // global feat dim
#define HCN   64         // classifier hidden
#define CC    2          // classes

#define CDIV(a,b) (((a)+(b)-1)/(b))

// ---------------- scratch (device globals) ----------------
__device__ float g_h   [TN*HH];
__device__ float g_z   [TN*HH];
__device__ float g_ssrc[TN*4];
__device__ float g_sdst[TN*4];
__device__ float g_emb [BB*HH];
__device__ float g_cat [BB*(HH+FGN)];
__device__ float g_tmp [BB*HH];
__device__ float g_fused[BB*HH];
__device__ float g_gx  [NNODE*HH];
__device__ float g_gz  [NNODE*HH];
// CSR scratch
__device__ int   g_deg   [TN];
__device__ int   g_rowptr[TN+1];
__device__ int   g_fill  [TN];
__device__ int   g_psrc  [ELN];
__device__ float g_pea   [ELN];
__device__ int   g_bsum  [256];
__device__ int   g_gdeg   [NNODE];
__device__ int   g_growptr[NNODE+1];
__device__ int   g_gfill  [NNODE];
__device__ int   g_gpsrc  [EGN];
__device__ int   g_gbsum  [256];

// ---------------- helpers ----------------
__device__ __forceinline__ unsigned f2tf32(float f) {
    unsigned r;
    asm("cvt.rna.tf32.f32 %0, %1;" : "=r"(r) : "f"(f));
    return r;
}

// ================= CSR construction =================
__global__ void hist_k(const int* __restrict__ dst, int* __restrict__ deg, int E) {
    int e = blockIdx.x * blockDim.x + threadIdx.x;
    if (e < E) atomicAdd(&deg[dst[e]], 1);
}
__global__ void scan1_k(const int* __restrict__ deg, int* __restrict__ bsum, int n) {
    __shared__ int s[256];
    int base = blockIdx.x * 1024, t = threadIdx.x;
    int sum = 0;
#pragma unroll
    for (int i = 0; i < 4; i++) {
        int idx = base + t * 4 + i;
        if (idx < n) sum += deg[idx];
    }
    s[t] = sum; __syncthreads();
    for (int o = 128; o > 0; o >>= 1) { if (t < o) s[t] += s[t + o]; __syncthreads(); }
    if (t == 0) bsum[blockIdx.x] = s[0];
}
__global__ void scan2_k(int* __restrict__ bsum, int nb, int* __restrict__ rowptr,
                        int n, int E) {
    if (threadIdx.x == 0) {
        int acc = 0;
        for (int i = 0; i < nb; i++) { int v = bsum[i]; bsum[i] = acc; acc += v; }
        rowptr[n] = E;
    }
}
__global__ void scan3_k(const int* __restrict__ deg, const int* __restrict__ bsum,
                        int* __restrict__ rowptr, int* __restrict__ fill, int n) {
    __shared__ int s[256];
    int base = blockIdx.x * 1024, t = threadIdx.x;
    int v[4]; int sum = 0;
#pragma unroll
    for (int i = 0; i < 4; i++) {
        int idx = base + t * 4 + i;
        v[i] = (idx < n) ? deg[idx] : 0;
        sum += v[i];
    }
    s[t] = sum; __syncthreads();
    for (int o = 1; o < 256; o <<= 1) {
        int x = (t >= o) ? s[t - o] : 0;
        __syncthreads();
        s[t] += x;
        __syncthreads();
    }
    int excl = ((t == 0) ? 0 : s[t - 1]) + bsum[blockIdx.x];
#pragma unroll
    for (int i = 0; i < 4; i++) {
        int idx = base + t * 4 + i;
        if (idx < n) { rowptr[idx] = excl; fill[idx] = excl; }
        excl += v[i];
    }
}
__global__ void scatedge_k(const int* __restrict__ src, const int* __restrict__ dst,
                           const float* __restrict__ eattr, int* __restrict__ fill,
                           int* __restrict__ psrc, float* __restrict__ pea, int E) {
    int e = blockIdx.x * blockDim.x + threadIdx.x;
    if (e < E) {
        int p = atomicAdd(&fill[dst[e]], 1);
        psrc[p] = src[e];
        if (pea) pea[p] = eattr[e];
    }
}

// ================= tf32 MMA GEMM =================
#define A_PAD 36
#define W_PAD 136
__global__ __launch_bounds__(256, 2)
void gemm_mma(const float* __restrict__ A, const float* __restrict__ W,
              const float* __restrict__ bias, float* __restrict__ C,
              int M, int K) {
    __shared__ unsigned As[128 * A_PAD];
    __shared__ unsigned Ws[32 * W_PAD];
    const int tid  = threadIdx.x;
    const int warp = tid >> 5, lane = tid & 31;
    const int bm   = blockIdx.x * 128;
    const int wm   = (warp >> 1) * 32;
    const int wn   = (warp & 1) * 64;
    const int g    = lane >> 2;
    const int ct   = lane & 3;
    const bool vec = (K & 31) == 0;

    float c[2][8][4];
#pragma unroll
    for (int mt = 0; mt < 2; mt++)
#pragma unroll
        for (int nt = 0; nt < 8; nt++)
#pragma unroll
            for (int r = 0; r < 4; r++) c[mt][nt][r] = 0.f;

    for (int k0 = 0; k0 < K; k0 += 32) {
        if (vec) {
            // A: 128 rows x 8 float4
#pragma unroll
            for (int i = tid; i < 128 * 8; i += 256) {
                int m = i >> 3, kq = (i & 7) * 4;
                int gr = bm + m;
                float4 v = (gr < M) ? *(const float4*)(A + (size_t)gr * K + k0 + kq)
                                    : make_float4(0.f, 0.f, 0.f, 0.f);
                uint4 u = make_uint4(f2tf32(v.x), f2tf32(v.y), f2tf32(v.z), f2tf32(v.w));
                *(uint4*)&As[m * A_PAD + kq] = u;
            }
            // W: 32 rows x 32 float4
#pragma unroll
            for (int i = tid; i < 32 * 32; i += 256) {
                int k = i >> 5, nq = (i & 31) * 4;
                float4 v = *(const float4*)(W + (size_t)(k0 + k) * 128 + nq);
                uint4 u = make_uint4(f2tf32(v.x), f2tf32(v.y), f2tf32(v.z), f2tf32(v.w));
                *(uint4*)&Ws[k * W_PAD + nq] = u;
            }
        } else {
#pragma unroll
            for (int i = tid; i < 128 * 32; i += 256) {
                int m = i >> 5, k = i & 31;
                int gr = bm + m, gk = k0 + k;
                float v = (gr < M && gk < K) ? A[(size_t)gr * K + gk] : 0.f;
                As[m * A_PAD + k] = f2tf32(v);
            }
#pragma unroll
            for (int i = tid; i < 32 * 128; i += 256) {
                int k = i >> 7, n = i & 127;
                int gk = k0 + k;
                float v = (gk < K) ? W[gk * 128 + n] : 0.f;
                Ws[k * W_PAD + n] = f2tf32(v);
            }
        }
        __syncthreads();
#pragma unroll
        for (int ks = 0; ks < 32; ks += 8) {
            unsigned b[8][2];
#pragma unroll
            for (int nt = 0; nt < 8; nt++) {
                int n = wn + nt * 8 + g;
                b[nt][0] = Ws[(ks + ct) * W_PAD + n];
                b[nt][1] = Ws[(ks + ct + 4) * W_PAD + n];
            }
#pragma unroll
            for (int mt = 0; mt < 2; mt++) {
                int r0 = wm + mt * 16 + g;
                unsigned a0 = As[r0 * A_PAD + ks + ct];
                unsigned a1 = As[(r0 + 8) * A_PAD + ks + ct];
                unsigned a2 = As[r0 * A_PAD + ks + ct + 4];
                unsigned a3 = As[(r0 + 8) * A_PAD + ks + ct + 4];
#pragma unroll
                for (int nt = 0; nt < 8; nt++) {
                    asm volatile(
                        "mma.sync.aligned.m16n8k8.row.col.f32.tf32.tf32.f32 "
                        "{%0,%1,%2,%3}, {%4,%5,%6,%7}, {%8,%9}, {%0,%1,%2,%3};"
                        : "+f"(c[mt][nt][0]), "+f"(c[mt][nt][1]),
                          "+f"(c[mt][nt][2]), "+f"(c[mt][nt][3])
                        : "r"(a0), "r"(a1), "r"(a2), "r"(a3),
                          "r"(b[nt][0]), "r"(b[nt][1]));
                }
            }
        }
        __syncthreads();
    }
#pragma unroll
    for (int mt = 0; mt < 2; mt++) {
        int row0 = bm + wm + mt * 16 + g;
        int row1 = row0 + 8;
#pragma unroll
        for (int nt = 0; nt < 8; nt++) {
            int col = wn + nt * 8 + 2 * ct;
            float b0 = bias ? bias[col] : 0.f;
            float b1 = bias ? bias[col + 1] : 0.f;
            if (row0 < M)
                *(float2*)(C + (size_t)row0 * 128 + col) =
                    make_float2(c[mt][nt][0] + b0, c[mt][nt][1] + b1);
            if (row1 < M)
                *(float2*)(C + (size_t)row1 * 128 + col) =
                    make_float2(c[mt][nt][2] + b0, c[mt][nt][3] + b1);
        }
    }
}

// ---------------- SIMT GEMM for tiny-K projections ----------------
__global__ __launch_bounds__(256, 2)
void gemm_tile(const float* __restrict__ A, const float* __restrict__ W,
               const float* __restrict__ bias, float* __restrict__ C,
               int M, int K) {
    __shared__ float As[16 * 132];
    __shared__ float Ws[16 * 132];
    const int bm  = blockIdx.x * 128;
    const int tid = threadIdx.x;
    const int tr  = (tid >> 4) * 8;
    const int tc  = (tid & 15) * 8;
    float acc[8][8];
#pragma unroll
    for (int x = 0; x < 8; x++)
#pragma unroll
        for (int y = 0; y < 8; y++) acc[x][y] = 0.f;

    for (int k0 = 0; k0 < K; k0 += 16) {
        for (int i = tid; i < 128 * 16; i += 256) {
            int m = i >> 4, kk = i & 15;
            int gr = bm + m, gk = k0 + kk;
            As[kk * 132 + m] = (gr < M && gk < K) ? A[(size_t)gr * K + gk] : 0.f;
        }
        for (int i = tid; i < 16 * 128; i += 256) {
            int kk = i >> 7, n = i & 127;
            int gk = k0 + kk;
            Ws[kk * 132 + n] = (gk < K) ? W[gk * 128 + n] : 0.f;
        }
        __syncthreads();
#pragma unroll
        for (int kk = 0; kk < 16; kk++) {
            float a[8], w[8];
#pragma unroll
            for (int x = 0; x < 8; x++) a[x] = As[kk * 132 + tr + x];
#pragma unroll
            for (int y = 0; y < 8; y++) w[y] = Ws[kk * 132 + tc + y];
#pragma unroll
            for (int x = 0; x < 8; x++)
#pragma unroll
                for (int y = 0; y < 8; y++) acc[x][y] += a[x] * w[y];
        }
        __syncthreads();
    }
#pragma unroll
    for (int x = 0; x < 8; x++) {
        int gr = bm + tr + x;
        if (gr < M) {
#pragma unroll
            for (int y = 0; y < 8; y++) {
                float v = acc[x][y];
                if (bias) v += bias[tc + y];
                C[(size_t)gr * 128 + tc + y] = v;
            }
        }
    }
}

// ---------------- per-node attention scores (float4 loads) ----------------
template <int NH, int HD>
__global__ void scores_k(const float* __restrict__ z, const float* __restrict__ as_,
                         const float* __restrict__ ad_, float* __restrict__ ssrc,
                         float* __restrict__ sdst, int n) {
    int i = blockIdx.x * blockDim.x + threadIdx.x;
    if (i >= n * NH) return;
    int node = i / NH, h = i % NH;
    const float4* zp = (const float4*)(z + (size_t)node * HH + h * HD);
    const float4* ap = (const float4*)(as_ + h * HD);
    const float4* dp = (const float4*)(ad_ + h * HD);
    float s = 0.f, t = 0.f;
#pragma unroll
    for (int d = 0; d < HD / 4; d++) {
        float4 zv = zp[d], av = ap[d], dv = dp[d];
        s += zv.x * av.x + zv.y * av.y + zv.z * av.z + zv.w * av.w;
        t += zv.x * dv.x + zv.y * dv.y + zv.z * dv.z + zv.w * dv.w;
    }
    ssrc[i] = s; sdst[i] = t;
}

// ---------------- fused single-pass GAT aggregation (prefetch + MLP) ----------------
// warp per dst node; lane = 4 channels. Edge indices/attrs prefetched in one
// coalesced load per 32-edge chunk, broadcast via shfl -> per-iteration loads
// independent -> deep MLP.
template <int NH, int HD, bool HAS_E>
__global__ void gat_fused(const int* __restrict__ rowptr, const int* __restrict__ psrc,
                          const float* __restrict__ pea,
                          const float* __restrict__ eW, const float* __restrict__ ae,
                          const float* __restrict__ ssrc, const float* __restrict__ sdst,
                          const float* __restrict__ z, const float* __restrict__ bias,
                          float* __restrict__ h, int n) {
    __shared__ float ce_s[NH];
    if (HAS_E && threadIdx.x < NH) {
        int hh = threadIdx.x;
        float s = 0.f;
#pragma unroll
        for (int d = 0; d < HD; d++) s += eW[hh * HD + d] * ae[hh * HD + d];
        ce_s[hh] = s;
    }
    if (HAS_E) __syncthreads();

    int node = blockIdx.x * 8 + (threadIdx.x >> 5);
    if (node >= n) return;
    int lane = threadIdx.x & 31;
    int c = lane * 4;
    int head = c / HD;

    float sd = sdst[(size_t)node * NH + head];
    float ce = HAS_E ? ce_s[head] : 0.f;

    float4 acc = make_float4(0.f, 0.f, 0.f, 0.f);
    float den = 0.f;
    int lo = rowptr[node], hi = rowptr[node + 1];

    for (int base = lo; base < hi; base += 32) {
        int m = hi - base; if (m > 32) m = 32;
        int sreg = 0; float ereg = 0.f;
        if (lane < m) {
            sreg = psrc[base + lane];
            if (HAS_E) ereg = pea[base + lane];
        }
#pragma unroll 4
        for (int j = 0; j < m; j++) {
            int s = __shfl_sync(0xffffffffu, sreg, j);
            float sc = ssrc[(size_t)s * NH + head] + sd;
            if (HAS_E) {
                float ea = __shfl_sync(0xffffffffu, ereg, j);
                sc += ea * ce;
            }
            sc = sc > 0.f ? sc : 0.2f * sc;
            float ex = __expf(sc);
            den += ex;
            float4 zv = *(const float4*)(z + (size_t)s * HH + c);
            acc.x += ex * zv.x; acc.y += ex * zv.y;
            acc.z += ex * zv.z; acc.w += ex * zv.w;
        }
    }
    float inv = 1.f / fmaxf(den, 1e-16f);
    float4 hv = *(const float4*)(h + (size_t)node * HH + c);
    float4 bv = *(const float4*)(bias + c);
    acc.x = hv.x + bv.x + acc.x * inv;
    acc.y = hv.y + bv.y + acc.y * inv;
    acc.z = hv.z + bv.z + acc.z * inv;
    acc.w = hv.w + bv.w + acc.w * inv;
    acc.x = acc.x > 0.f ? acc.x : __expf(acc.x) - 1.f;
    acc.y = acc.y > 0.f ? acc.y : __expf(acc.y) - 1.f;
    acc.z = acc.z > 0.f ? acc.z : __expf(acc.z) - 1.f;
    acc.w = acc.w > 0.f ? acc.w : __expf(acc.w) - 1.f;
    *(float4*)(h + (size_t)node * HH + c) = acc;
}

// ---------------- mean pooling via binary search on sorted node_batch ----------------
__global__ void pool_k(const float* __restrict__ h, const int* __restrict__ nb,
                       float* __restrict__ emb) {
    int b = blockIdx.x, t = threadIdx.x;   // 128 threads
    int lo = 0, hi = TN;
    while (lo < hi) { int mid = (lo + hi) >> 1; if (nb[mid] < b) lo = mid + 1; else hi = mid; }
    int start = lo;
    hi = TN;
    while (lo < hi) { int mid = (lo + hi) >> 1; if (nb[mid] < b + 1) lo = mid + 1; else hi = mid; }
    int end = lo;
    float s = 0.f;
    for (int i = start; i < end; i++) s += h[(size_t)i * HH + t];
    emb[(size_t)b * HH + t] = s / fmaxf((float)(end - start), 1.f);
}

// ---------------- concat [emb | gf[cid]] ----------------
__global__ void concat_k(const float* __restrict__ emb, const float* __restrict__ gf,
                         const int* __restrict__ cid, float* __restrict__ cat) {
    int i = blockIdx.x * blockDim.x + threadIdx.x;
    if (i >= BB * (HH + FGN)) return;
    int b = i / (HH + FGN), j = i % (HH + FGN);
    cat[i] = (j < HH) ? emb[(size_t)b * HH + j]
                      : gf[(size_t)cid[b] * FGN + (j - HH)];
}

// ---------------- LayerNorm(128) + ReLU ----------------
__global__ void ln_relu_k(const float* __restrict__ X, const float* __restrict__ g,
                          const float* __restrict__ be, float* __restrict__ Y) {
    int row = blockIdx.x, t = threadIdx.x;
    float v = X[(size_t)row * HH + t];
    __shared__ float red[HH];
    red[t] = v; __syncthreads();
    for (int s = 64; s > 0; s >>= 1) { if (t < s) red[t] += red[t + s]; __syncthreads(); }
    float mean = red[0] / 128.f;
    __syncthreads();
    float dv = v - mean;
    red[t] = dv * dv; __syncthreads();
    for (int s = 64; s > 0; s >>= 1) { if (t < s) red[t] += red[t + s]; __syncthreads(); }
    float var = red[0] / 128.f;
    float y = dv * rsqrtf(var + 1e-5f) * g[t] + be[t];
    Y[(size_t)row * HH + t] = fmaxf(y, 0.f);
}

// ---------------- scatter fused batch embeddings into gx ----------------
__global__ void scatfused_k(float* __restrict__ gx, const float* __restrict__ fused,
                            const int* __restrict__ cid) {
    int i = blockIdx.x * blockDim.x + threadIdx.x;
    if (i >= BB * HH) return;
    int b = i >> 7;
    gx[(size_t)cid[b] * HH + (i & 127)] = fused[i];
}

// ---------------- classifier ----------------
__global__ void classifier_k(const float* __restrict__ gx, const int* __restrict__ cid,
                             const float* __restrict__ W1, const float* __restrict__ b1,
                             const float* __restrict__ W2, const float* __restrict__ b2,
                             float* __restrict__ out) {
    int b = blockIdx.x, t = threadIdx.x;  // 64 threads
    __shared__ float row[HH];
    __shared__ float hc[HCN];
    const float* srcp = gx + (size_t)cid[b] * HH;
    row[t] = srcp[t];
    row[t + 64] = srcp[t + 64];
    __syncthreads();
    float s = b1[t];
#pragma unroll
    for (int k = 0; k < HH; k++) s += row[k] * W1[k * HCN + t];
    hc[t] = fmaxf(s, 0.f);
    __syncthreads();
    if (t < CC) {
        float s2 = b2[t];
#pragma unroll
        for (int k = 0; k < HCN; k++) s2 += hc[k] * W2[k * CC + t];
        out[b * CC + t] = s2;
    }
}

// ---------------- launch ----------------
extern "C" void kernel_launch(void* const* d_in, const int* in_sizes, int n_in,
                              void* d_out, int out_size) {
    const float* x_local    = (const float*)d_in[0];
    const float* eattr      = (const float*)d_in[1];
    const float* gfeat      = (const float*)d_in[2];
    const float* loc_in_W   = (const float*)d_in[3];
    const float* loc_in_b   = (const float*)d_in[4];
    const float* loc_W      = (const float*)d_in[5];
    const float* loc_asrc   = (const float*)d_in[6];
    const float* loc_adst   = (const float*)d_in[7];
    const float* loc_eW     = (const float*)d_in[8];
    const float* loc_ae     = (const float*)d_in[9];
    const float* loc_b      = (const float*)d_in[10];
    const float* fp_W       = (const float*)d_in[11];
    const float* fp_b       = (const float*)d_in[12];
    const float* fp_g       = (const float*)d_in[13];
    const float* fp_beta    = (const float*)d_in[14];
    const float* gp_W       = (const float*)d_in[15];
    const float* gp_b       = (const float*)d_in[16];
    const float* gp_g       = (const float*)d_in[17];
    const float* gp_beta    = (const float*)d_in[18];
    const float* glob_W     = (const float*)d_in[19];
    const float* glob_asrc  = (const float*)d_in[20];
    const float* glob_adst  = (const float*)d_in[21];
    const float* glob_b     = (const float*)d_in[22];
    const float* cls_W1     = (const float*)d_in[23];
    const float* cls_b1     = (const float*)d_in[24];
    const float* cls_W2     = (const float*)d_in[25];
    const float* cls_b2     = (const float*)d_in[26];
    const int*   eil        = (const int*)d_in[27];
    const int*   node_batch = (const int*)d_in[28];
    const int*   cid        = (const int*)d_in[29];
    const int*   gei        = (const int*)d_in[30];

    const int* lsrc = eil;
    const int* ldst = eil + ELN;
    const int* gsrc = gei;
    const int* gdst = gei + EGN;

    float *p_h, *p_z, *p_ssrc, *p_sdst;
    float *p_emb, *p_cat, *p_tmp, *p_fused, *p_gx, *p_gz, *p_pea;
    int *p_deg, *p_rowptr, *p_fill, *p_psrc, *p_bsum;
    int *p_gdeg, *p_growptr, *p_gfill, *p_gpsrc, *p_gbsum;
    cudaGetSymbolAddress((void**)&p_h, g_h);
    cudaGetSymbolAddress((void**)&p_z, g_z);
    cudaGetSymbolAddress((void**)&p_ssrc, g_ssrc);
    cudaGetSymbolAddress((void**)&p_sdst, g_sdst);
    cudaGetSymbolAddress((void**)&p_emb, g_emb);
    cudaGetSymbolAddress((void**)&p_cat, g_cat);
    cudaGetSymbolAddress((void**)&p_tmp, g_tmp);
    cudaGetSymbolAddress((void**)&p_fused, g_fused);
    cudaGetSymbolAddress((void**)&p_gx, g_gx);
    cudaGetSymbolAddress((void**)&p_gz, g_gz);
    cudaGetSymbolAddress((void**)&p_pea, g_pea);
    cudaGetSymbolAddress((void**)&p_deg, g_deg);
    cudaGetSymbolAddress((void**)&p_rowptr, g_rowptr);
    cudaGetSymbolAddress((void**)&p_fill, g_fill);
    cudaGetSymbolAddress((void**)&p_psrc, g_psrc);
    cudaGetSymbolAddress((void**)&p_bsum, g_bsum);
    cudaGetSymbolAddress((void**)&p_gdeg, g_gdeg);
    cudaGetSymbolAddress((void**)&p_growptr, g_growptr);
    cudaGetSymbolAddress((void**)&p_gfill, g_gfill);
    cudaGetSymbolAddress((void**)&p_gpsrc, g_gpsrc);
    cudaGetSymbolAddress((void**)&p_gbsum, g_gbsum);

    // ---- build CSR (dst-sorted, pre-permuted payloads) ----
    cudaMemsetAsync(p_deg, 0, TN * sizeof(int));
    hist_k<<<CDIV(ELN, 256), 256>>>(ldst, p_deg, ELN);
    scan1_k<<<CDIV(TN, 1024), 256>>>(p_deg, p_bsum, TN);
    scan2_k<<<1, 32>>>(p_bsum, CDIV(TN, 1024), p_rowptr, TN, ELN);
    scan3_k<<<CDIV(TN, 1024), 256>>>(p_deg, p_bsum, p_rowptr, p_fill, TN);
    scatedge_k<<<CDIV(ELN, 256), 256>>>(lsrc, ldst, eattr, p_fill, p_psrc, p_pea, ELN);

    cudaMemsetAsync(p_gdeg, 0, NNODE * sizeof(int));
    hist_k<<<CDIV(EGN, 256), 256>>>(gdst, p_gdeg, EGN);
    scan1_k<<<CDIV(NNODE, 1024), 256>>>(p_gdeg, p_gbsum, NNODE);
    scan2_k<<<1, 32>>>(p_gbsum, CDIV(NNODE, 1024), p_growptr, NNODE, EGN);
    scan3_k<<<CDIV(NNODE, 1024), 256>>>(p_gdeg, p_gbsum, p_growptr, p_gfill, NNODE);
    scatedge_k<<<CDIV(EGN, 256), 256>>>(gsrc, gdst, (const float*)nullptr, p_gfill,
                                        p_gpsrc, (float*)nullptr, EGN);

    // ---- local encoder: input projection (K=4, SIMT) ----
    gemm_tile<<<CDIV(TN, 128), 256>>>(x_local, loc_in_W, loc_in_b, p_h, TN, 4);

    // ---- 2x local GATConv ----
    for (int l = 0; l < 2; l++) {
        gemm_mma<<<CDIV(TN, 128), 256>>>(p_h, loc_W + l * HH * HH, nullptr, p_z, TN, HH);
        scores_k<4, 32><<<CDIV(TN * 4, 256), 256>>>(p_z, loc_asrc + l * HH,
                                                    loc_adst + l * HH, p_ssrc, p_sdst, TN);
        gat_fused<4, 32, true><<<CDIV(TN, 8), 256>>>(p_rowptr, p_psrc, p_pea,
                                                     loc_eW + l * HH, loc_ae + l * HH,
                                                     p_ssrc, p_sdst, p_z,
                                                     loc_b + l * HH, p_h, TN);
    }

    // ---- contract mean pooling ----
    pool_k<<<BB, 128>>>(p_h, node_batch, p_emb);

    // ---- fused MLP ----
    concat_k<<<CDIV(BB * (HH + FGN), 256), 256>>>(p_emb, gfeat, cid, p_cat);
    gemm_mma<<<CDIV(BB, 128), 256>>>(p_cat, fp_W, fp_b, p_tmp, BB, HH + FGN);
    ln_relu_k<<<BB, HH>>>(p_tmp, fp_g, fp_beta, p_fused);

    // ---- global projection + scatter ----
    gemm_tile<<<CDIV(NNODE, 128), 256>>>(gfeat, gp_W, gp_b, p_gz, NNODE, FGN);
    ln_relu_k<<<NNODE, HH>>>(p_gz, gp_g, gp_beta, p_gx);
    scatfused_k<<<CDIV(BB * HH, 256), 256>>>(p_gx, p_fused, cid);

    // ---- 2x global GATConv ----
    for (int l = 0; l < 2; l++) {
        gemm_mma<<<CDIV(NNODE, 128), 256>>>(p_gx, glob_W + l * HH * HH, nullptr, p_gz, NNODE, HH);
        scores_k<2, 64><<<CDIV(NNODE * 2, 256), 256>>>(p_gz, glob_asrc + l * HH,
                                                       glob_adst + l * HH, p_ssrc, p_sdst, NNODE);
        gat_fused<2, 64, false><<<CDIV(NNODE, 8), 256>>>(p_growptr, p_gpsrc, (float*)nullptr,
                                                         (float*)nullptr, (float*)nullptr,
                                                         p_ssrc, p_sdst, p_gz,
                                                         glob_b + l * HH, p_gx, NNODE);
    }

    // ---- classifier ----
    classifier_k<<<BB, 64>>>(p_gx, cid, cls_W1, cls_b1, cls_W2, cls_b2, (float*)d_out);
}

// round 7
// speedup vs baseline: 1.2410x; 1.2410x over previous
#include <cuda_runtime.h>
#include <math.h>

// ---------------- problem constants ----------------
#define TN    131072     // local tx nodes
#define ELN   524288     // local edges
#define NNODE 50000      // global contract nodes
#define EGN   400000     // global edges
#define BB    8192       // batch of contracts
#define HH    128        // hidden dim
#define FGN   7          // global feat dim
#define HCN   64         // classifier hidden
#define CC    2          // classes

#define CDIV(a,b) (((a)+(b)-1)/(b))

// ---------------- scratch (device globals) ----------------
__device__ float g_h   [TN*HH];
__device__ float g_z   [TN*HH];
__device__ float g_ssrc[TN*4];
__device__ float g_sdst[TN*4];
__device__ float g_emb [BB*HH];
__device__ float g_cat [BB*(HH+FGN)];
__device__ float g_tmp [BB*HH];
__device__ float g_fused[BB*HH];
__device__ float g_gx  [NNODE*HH];
__device__ float g_gz  [NNODE*HH];
// CSR scratch
__device__ int   g_deg   [TN];
__device__ int   g_rowptr[TN+1];
__device__ int   g_fill  [TN];
__device__ int   g_psrc  [ELN];
__device__ float g_pea   [ELN];
__device__ int   g_bsum  [256];
__device__ int   g_gdeg   [NNODE];
__device__ int   g_growptr[NNODE+1];
__device__ int   g_gfill  [NNODE];
__device__ int   g_gpsrc  [EGN];
__device__ int   g_gbsum  [256];

// ---------------- helpers ----------------
__device__ __forceinline__ unsigned f2tf32(float f) {
    unsigned r;
    asm("cvt.rna.tf32.f32 %0, %1;" : "=r"(r) : "f"(f));
    return r;
}

// ================= CSR construction =================
__global__ void hist_k(const int* __restrict__ dst, int* __restrict__ deg, int E) {
    int e = blockIdx.x * blockDim.x + threadIdx.x;
    if (e < E) atomicAdd(&deg[dst[e]], 1);
}
__global__ void scan1_k(const int* __restrict__ deg, int* __restrict__ bsum, int n) {
    __shared__ int s[256];
    int base = blockIdx.x * 1024, t = threadIdx.x;
    int sum = 0;
#pragma unroll
    for (int i = 0; i < 4; i++) {
        int idx = base + t * 4 + i;
        if (idx < n) sum += deg[idx];
    }
    s[t] = sum; __syncthreads();
    for (int o = 128; o > 0; o >>= 1) { if (t < o) s[t] += s[t + o]; __syncthreads(); }
    if (t == 0) bsum[blockIdx.x] = s[0];
}
__global__ void scan2_k(int* __restrict__ bsum, int nb, int* __restrict__ rowptr,
                        int n, int E) {
    if (threadIdx.x == 0) {
        int acc = 0;
        for (int i = 0; i < nb; i++) { int v = bsum[i]; bsum[i] = acc; acc += v; }
        rowptr[n] = E;
    }
}
__global__ void scan3_k(const int* __restrict__ deg, const int* __restrict__ bsum,
                        int* __restrict__ rowptr, int* __restrict__ fill, int n) {
    __shared__ int s[256];
    int base = blockIdx.x * 1024, t = threadIdx.x;
    int v[4]; int sum = 0;
#pragma unroll
    for (int i = 0; i < 4; i++) {
        int idx = base + t * 4 + i;
        v[i] = (idx < n) ? deg[idx] : 0;
        sum += v[i];
    }
    s[t] = sum; __syncthreads();
    for (int o = 1; o < 256; o <<= 1) {
        int x = (t >= o) ? s[t - o] : 0;
        __syncthreads();
        s[t] += x;
        __syncthreads();
    }
    int excl = ((t == 0) ? 0 : s[t - 1]) + bsum[blockIdx.x];
#pragma unroll
    for (int i = 0; i < 4; i++) {
        int idx = base + t * 4 + i;
        if (idx < n) { rowptr[idx] = excl; fill[idx] = excl; }
        excl += v[i];
    }
}
__global__ void scatedge_k(const int* __restrict__ src, const int* __restrict__ dst,
                           const float* __restrict__ eattr, int* __restrict__ fill,
                           int* __restrict__ psrc, float* __restrict__ pea, int E) {
    int e = blockIdx.x * blockDim.x + threadIdx.x;
    if (e < E) {
        int p = atomicAdd(&fill[dst[e]], 1);
        psrc[p] = src[e];
        if (pea) pea[p] = eattr[e];
    }
}

// ================= tf32 MMA GEMM with fused attention scores =================
// NH=0: plain GEMM. NH>0: epilogue also emits ssrc/sdst per (row, head).
#define A_PAD 36
#define W_PAD 136
template <int NH>
__global__ __launch_bounds__(256, 2)
void gemm_mma(const float* __restrict__ A, const float* __restrict__ W,
              const float* __restrict__ bias, float* __restrict__ C,
              int M, int K,
              const float* __restrict__ asrc, const float* __restrict__ adst,
              float* __restrict__ ssrc, float* __restrict__ sdst) {
    __shared__ unsigned As[128 * A_PAD];
    __shared__ unsigned Ws[32 * W_PAD];
    const int tid  = threadIdx.x;
    const int warp = tid >> 5, lane = tid & 31;
    const int bm   = blockIdx.x * 128;
    const int wm   = (warp >> 1) * 32;
    const int wn   = (warp & 1) * 64;
    const int g    = lane >> 2;
    const int ct   = lane & 3;
    const bool vec = (K & 31) == 0;

    float c[2][8][4];
#pragma unroll
    for (int mt = 0; mt < 2; mt++)
#pragma unroll
        for (int nt = 0; nt < 8; nt++)
#pragma unroll
            for (int r = 0; r < 4; r++) c[mt][nt][r] = 0.f;

    for (int k0 = 0; k0 < K; k0 += 32) {
        if (vec) {
#pragma unroll
            for (int i = tid; i < 128 * 8; i += 256) {
                int m = i >> 3, kq = (i & 7) * 4;
                int gr = bm + m;
                float4 v = (gr < M) ? *(const float4*)(A + (size_t)gr * K + k0 + kq)
                                    : make_float4(0.f, 0.f, 0.f, 0.f);
                uint4 u = make_uint4(f2tf32(v.x), f2tf32(v.y), f2tf32(v.z), f2tf32(v.w));
                *(uint4*)&As[m * A_PAD + kq] = u;
            }
#pragma unroll
            for (int i = tid; i < 32 * 32; i += 256) {
                int k = i >> 5, nq = (i & 31) * 4;
                float4 v = *(const float4*)(W + (size_t)(k0 + k) * 128 + nq);
                uint4 u = make_uint4(f2tf32(v.x), f2tf32(v.y), f2tf32(v.z), f2tf32(v.w));
                *(uint4*)&Ws[k * W_PAD + nq] = u;
            }
        } else {
#pragma unroll
            for (int i = tid; i < 128 * 32; i += 256) {
                int m = i >> 5, k = i & 31;
                int gr = bm + m, gk = k0 + k;
                float v = (gr < M && gk < K) ? A[(size_t)gr * K + gk] : 0.f;
                As[m * A_PAD + k] = f2tf32(v);
            }
#pragma unroll
            for (int i = tid; i < 32 * 128; i += 256) {
                int k = i >> 7, n = i & 127;
                int gk = k0 + k;
                float v = (gk < K) ? W[gk * 128 + n] : 0.f;
                Ws[k * W_PAD + n] = f2tf32(v);
            }
        }
        __syncthreads();
#pragma unroll
        for (int ks = 0; ks < 32; ks += 8) {
            unsigned b[8][2];
#pragma unroll
            for (int nt = 0; nt < 8; nt++) {
                int n = wn + nt * 8 + g;
                b[nt][0] = Ws[(ks + ct) * W_PAD + n];
                b[nt][1] = Ws[(ks + ct + 4) * W_PAD + n];
            }
#pragma unroll
            for (int mt = 0; mt < 2; mt++) {
                int r0 = wm + mt * 16 + g;
                unsigned a0 = As[r0 * A_PAD + ks + ct];
                unsigned a1 = As[(r0 + 8) * A_PAD + ks + ct];
                unsigned a2 = As[r0 * A_PAD + ks + ct + 4];
                unsigned a3 = As[(r0 + 8) * A_PAD + ks + ct + 4];
#pragma unroll
                for (int nt = 0; nt < 8; nt++) {
                    asm volatile(
                        "mma.sync.aligned.m16n8k8.row.col.f32.tf32.tf32.f32 "
                        "{%0,%1,%2,%3}, {%4,%5,%6,%7}, {%8,%9}, {%0,%1,%2,%3};"
                        : "+f"(c[mt][nt][0]), "+f"(c[mt][nt][1]),
                          "+f"(c[mt][nt][2]), "+f"(c[mt][nt][3])
                        : "r"(a0), "r"(a1), "r"(a2), "r"(a3),
                          "r"(b[nt][0]), "r"(b[nt][1]));
                }
            }
        }
        __syncthreads();
    }

    // score partials [mt][rowhalf][h2]
    const int NH2 = (NH == 4) ? 2 : 1;
    float ps[2][2][2], pd[2][2][2];
    if (NH > 0) {
#pragma unroll
        for (int a = 0; a < 2; a++)
#pragma unroll
            for (int b = 0; b < 2; b++)
#pragma unroll
                for (int d = 0; d < 2; d++) { ps[a][b][d] = 0.f; pd[a][b][d] = 0.f; }
    }

#pragma unroll
    for (int mt = 0; mt < 2; mt++) {
        int row0 = bm + wm + mt * 16 + g;
        int row1 = row0 + 8;
#pragma unroll
        for (int nt = 0; nt < 8; nt++) {
            int col = wn + nt * 8 + 2 * ct;
            float b0 = bias ? bias[col] : 0.f;
            float b1 = bias ? bias[col + 1] : 0.f;
            float v00 = c[mt][nt][0] + b0, v01 = c[mt][nt][1] + b1;
            float v10 = c[mt][nt][2] + b0, v11 = c[mt][nt][3] + b1;
            if (row0 < M) *(float2*)(C + (size_t)row0 * 128 + col) = make_float2(v00, v01);
            if (row1 < M) *(float2*)(C + (size_t)row1 * 128 + col) = make_float2(v10, v11);
            if (NH > 0) {
                float a0s = asrc[col], a1s = asrc[col + 1];
                float a0d = adst[col], a1d = adst[col + 1];
                int h2 = (NH == 4) ? (nt >> 2) : 0;
                ps[mt][0][h2] += v00 * a0s + v01 * a1s;
                ps[mt][1][h2] += v10 * a0s + v11 * a1s;
                pd[mt][0][h2] += v00 * a0d + v01 * a1d;
                pd[mt][1][h2] += v10 * a0d + v11 * a1d;
            }
        }
    }
    if (NH > 0) {
#pragma unroll
        for (int mt = 0; mt < 2; mt++)
#pragma unroll
            for (int rh = 0; rh < 2; rh++)
#pragma unroll
                for (int h2 = 0; h2 < NH2; h2++) {
                    float s = ps[mt][rh][h2], d = pd[mt][rh][h2];
                    s += __shfl_xor_sync(0xffffffffu, s, 1);
                    s += __shfl_xor_sync(0xffffffffu, s, 2);
                    d += __shfl_xor_sync(0xffffffffu, d, 1);
                    d += __shfl_xor_sync(0xffffffffu, d, 2);
                    ps[mt][rh][h2] = s; pd[mt][rh][h2] = d;
                }
        if (ct == 0) {
            int headbase = wn / (128 / (NH > 0 ? NH : 1));
#pragma unroll
            for (int mt = 0; mt < 2; mt++)
#pragma unroll
                for (int rh = 0; rh < 2; rh++) {
                    int row = bm + wm + mt * 16 + g + rh * 8;
                    if (row < M) {
#pragma unroll
                        for (int h2 = 0; h2 < NH2; h2++) {
                            int head = headbase + h2;
                            ssrc[(size_t)row * NH + head] = ps[mt][rh][h2];
                            sdst[(size_t)row * NH + head] = pd[mt][rh][h2];
                        }
                    }
                }
        }
    }
}

// ---------------- SIMT GEMM for tiny-K projections (+optional fused LN+ReLU) --------
__global__ __launch_bounds__(256, 2)
void gemm_tile(const float* __restrict__ A, const float* __restrict__ W,
               const float* __restrict__ bias, float* __restrict__ C,
               int M, int K,
               const float* __restrict__ gamma, const float* __restrict__ beta) {
    __shared__ float As[16 * 132];
    __shared__ float Ws[16 * 132];
    const int bm  = blockIdx.x * 128;
    const int tid = threadIdx.x;
    const int tr  = (tid >> 4) * 8;
    const int tc  = (tid & 15) * 8;
    float acc[8][8];
#pragma unroll
    for (int x = 0; x < 8; x++)
#pragma unroll
        for (int y = 0; y < 8; y++) acc[x][y] = 0.f;

    for (int k0 = 0; k0 < K; k0 += 16) {
        for (int i = tid; i < 128 * 16; i += 256) {
            int m = i >> 4, kk = i & 15;
            int gr = bm + m, gk = k0 + kk;
            As[kk * 132 + m] = (gr < M && gk < K) ? A[(size_t)gr * K + gk] : 0.f;
        }
        for (int i = tid; i < 16 * 128; i += 256) {
            int kk = i >> 7, n = i & 127;
            int gk = k0 + kk;
            Ws[kk * 132 + n] = (gk < K) ? W[gk * 128 + n] : 0.f;
        }
        __syncthreads();
#pragma unroll
        for (int kk = 0; kk < 16; kk++) {
            float a[8], w[8];
#pragma unroll
            for (int x = 0; x < 8; x++) a[x] = As[kk * 132 + tr + x];
#pragma unroll
            for (int y = 0; y < 8; y++) w[y] = Ws[kk * 132 + tc + y];
#pragma unroll
            for (int x = 0; x < 8; x++)
#pragma unroll
                for (int y = 0; y < 8; y++) acc[x][y] += a[x] * w[y];
        }
        __syncthreads();
    }

    if (gamma) {
        // fused bias + LayerNorm(128) + ReLU. Row spans the 16 lanes of a
        // half-warp shfl group (width=16).
#pragma unroll
        for (int x = 0; x < 8; x++) {
            int gr = bm + tr + x;
            float vv[8]; float sum = 0.f;
#pragma unroll
            for (int y = 0; y < 8; y++) {
                vv[y] = acc[x][y] + (bias ? bias[tc + y] : 0.f);
                sum += vv[y];
            }
#pragma unroll
            for (int k = 1; k < 16; k <<= 1) sum += __shfl_xor_sync(0xffffffffu, sum, k, 16);
            float mean = sum * (1.f / 128.f);
            float sq = 0.f;
#pragma unroll
            for (int y = 0; y < 8; y++) { float d = vv[y] - mean; sq += d * d; }
#pragma unroll
            for (int k = 1; k < 16; k <<= 1) sq += __shfl_xor_sync(0xffffffffu, sq, k, 16);
            float rstd = rsqrtf(sq * (1.f / 128.f) + 1e-5f);
            if (gr < M) {
#pragma unroll
                for (int y = 0; y < 8; y++) {
                    float yv = (vv[y] - mean) * rstd * gamma[tc + y] + beta[tc + y];
                    C[(size_t)gr * 128 + tc + y] = fmaxf(yv, 0.f);
                }
            }
        }
    } else {
#pragma unroll
        for (int x = 0; x < 8; x++) {
            int gr = bm + tr + x;
            if (gr < M) {
#pragma unroll
                for (int y = 0; y < 8; y++) {
                    float v = acc[x][y];
                    if (bias) v += bias[tc + y];
                    C[(size_t)gr * 128 + tc + y] = v;
                }
            }
        }
    }
}

// ---------------- fused single-pass GAT aggregation ----------------
template <int NH, int HD, bool HAS_E>
__global__ void gat_fused(const int* __restrict__ rowptr, const int* __restrict__ psrc,
                          const float* __restrict__ pea,
                          const float* __restrict__ eW, const float* __restrict__ ae,
                          const float* __restrict__ ssrc, const float* __restrict__ sdst,
                          const float* __restrict__ z, const float* __restrict__ bias,
                          float* __restrict__ h, int n) {
    __shared__ float ce_s[NH];
    if (HAS_E && threadIdx.x < NH) {
        int hh = threadIdx.x;
        float s = 0.f;
#pragma unroll
        for (int d = 0; d < HD; d++) s += eW[hh * HD + d] * ae[hh * HD + d];
        ce_s[hh] = s;
    }
    if (HAS_E) __syncthreads();

    int node = blockIdx.x * 8 + (threadIdx.x >> 5);
    if (node >= n) return;
    int lane = threadIdx.x & 31;
    int c = lane * 4;
    int head = c / HD;

    float sd = sdst[(size_t)node * NH + head];
    float ce = HAS_E ? ce_s[head] : 0.f;

    float4 acc = make_float4(0.f, 0.f, 0.f, 0.f);
    float den = 0.f;
    int lo = rowptr[node], hi = rowptr[node + 1];
    for (int j = lo; j < hi; j++) {
        int s = psrc[j];
        float sc = ssrc[(size_t)s * NH + head] + sd;
        if (HAS_E) sc += pea[j] * ce;
        sc = sc > 0.f ? sc : 0.2f * sc;
        float ex = __expf(sc);
        den += ex;
        float4 zv = *(const float4*)(z + (size_t)s * HH + c);
        acc.x += ex * zv.x; acc.y += ex * zv.y;
        acc.z += ex * zv.z; acc.w += ex * zv.w;
    }
    float inv = 1.f / fmaxf(den, 1e-16f);
    float4 hv = *(const float4*)(h + (size_t)node * HH + c);
    float4 bv = *(const float4*)(bias + c);
    acc.x = hv.x + bv.x + acc.x * inv;
    acc.y = hv.y + bv.y + acc.y * inv;
    acc.z = hv.z + bv.z + acc.z * inv;
    acc.w = hv.w + bv.w + acc.w * inv;
    acc.x = acc.x > 0.f ? acc.x : __expf(acc.x) - 1.f;
    acc.y = acc.y > 0.f ? acc.y : __expf(acc.y) - 1.f;
    acc.z = acc.z > 0.f ? acc.z : __expf(acc.z) - 1.f;
    acc.w = acc.w > 0.f ? acc.w : __expf(acc.w) - 1.f;
    *(float4*)(h + (size_t)node * HH + c) = acc;
}

// ---------------- mean pooling via binary search on sorted node_batch ----------------
__global__ void pool_k(const float* __restrict__ h, const int* __restrict__ nb,
                       float* __restrict__ emb) {
    int b = blockIdx.x, t = threadIdx.x;
    int lo = 0, hi = TN;
    while (lo < hi) { int mid = (lo + hi) >> 1; if (nb[mid] < b) lo = mid + 1; else hi = mid; }
    int start = lo;
    hi = TN;
    while (lo < hi) { int mid = (lo + hi) >> 1; if (nb[mid] < b + 1) lo = mid + 1; else hi = mid; }
    int end = lo;
    float s = 0.f;
    for (int i = start; i < end; i++) s += h[(size_t)i * HH + t];
    emb[(size_t)b * HH + t] = s / fmaxf((float)(end - start), 1.f);
}

// ---------------- concat [emb | gf[cid]] ----------------
__global__ void concat_k(const float* __restrict__ emb, const float* __restrict__ gf,
                         const int* __restrict__ cid, float* __restrict__ cat) {
    int i = blockIdx.x * blockDim.x + threadIdx.x;
    if (i >= BB * (HH + FGN)) return;
    int b = i / (HH + FGN), j = i % (HH + FGN);
    cat[i] = (j < HH) ? emb[(size_t)b * HH + j]
                      : gf[(size_t)cid[b] * FGN + (j - HH)];
}

// ---------------- LayerNorm(128) + ReLU (fp path) ----------------
__global__ void ln_relu_k(const float* __restrict__ X, const float* __restrict__ g,
                          const float* __restrict__ be, float* __restrict__ Y) {
    int row = blockIdx.x, t = threadIdx.x;
    float v = X[(size_t)row * HH + t];
    __shared__ float red[HH];
    red[t] = v; __syncthreads();
    for (int s = 64; s > 0; s >>= 1) { if (t < s) red[t] += red[t + s]; __syncthreads(); }
    float mean = red[0] / 128.f;
    __syncthreads();
    float dv = v - mean;
    red[t] = dv * dv; __syncthreads();
    for (int s = 64; s > 0; s >>= 1) { if (t < s) red[t] += red[t + s]; __syncthreads(); }
    float var = red[0] / 128.f;
    float y = dv * rsqrtf(var + 1e-5f) * g[t] + be[t];
    Y[(size_t)row * HH + t] = fmaxf(y, 0.f);
}

// ---------------- scatter fused batch embeddings into gx ----------------
__global__ void scatfused_k(float* __restrict__ gx, const float* __restrict__ fused,
                            const int* __restrict__ cid) {
    int i = blockIdx.x * blockDim.x + threadIdx.x;
    if (i >= BB * HH) return;
    int b = i >> 7;
    gx[(size_t)cid[b] * HH + (i & 127)] = fused[i];
}

// ---------------- classifier: 8 contracts per block ----------------
__global__ __launch_bounds__(256)
void classifier_k(const float* __restrict__ gx, const int* __restrict__ cid,
                  const float* __restrict__ W1, const float* __restrict__ b1,
                  const float* __restrict__ W2, const float* __restrict__ b2,
                  float* __restrict__ out) {
    __shared__ float row[4][HH];
    __shared__ float hc[4][HCN];
    int tid = threadIdx.x;
    int grp = tid >> 6, t = tid & 63;
    for (int it = 0; it < 2; it++) {
        int b = blockIdx.x * 8 + it * 4 + grp;
        __syncthreads();
        const float* srcp = gx + (size_t)cid[b] * HH;
        row[grp][t] = srcp[t];
        row[grp][t + 64] = srcp[t + 64];
        __syncthreads();
        float s = b1[t];
#pragma unroll
        for (int k = 0; k < HH; k++) s += row[grp][k] * W1[k * HCN + t];
        hc[grp][t] = fmaxf(s, 0.f);
        __syncthreads();
        if (t < CC) {
            float s2 = b2[t];
#pragma unroll
            for (int k = 0; k < HCN; k++) s2 += hc[grp][k] * W2[k * CC + t];
            out[b * CC + t] = s2;
        }
    }
}

// ---------------- launch ----------------
extern "C" void kernel_launch(void* const* d_in, const int* in_sizes, int n_in,
                              void* d_out, int out_size) {
    const float* x_local    = (const float*)d_in[0];
    const float* eattr      = (const float*)d_in[1];
    const float* gfeat      = (const float*)d_in[2];
    const float* loc_in_W   = (const float*)d_in[3];
    const float* loc_in_b   = (const float*)d_in[4];
    const float* loc_W      = (const float*)d_in[5];
    const float* loc_asrc   = (const float*)d_in[6];
    const float* loc_adst   = (const float*)d_in[7];
    const float* loc_eW     = (const float*)d_in[8];
    const float* loc_ae     = (const float*)d_in[9];
    const float* loc_b      = (const float*)d_in[10];
    const float* fp_W       = (const float*)d_in[11];
    const float* fp_b       = (const float*)d_in[12];
    const float* fp_g       = (const float*)d_in[13];
    const float* fp_beta    = (const float*)d_in[14];
    const float* gp_W       = (const float*)d_in[15];
    const float* gp_b       = (const float*)d_in[16];
    const float* gp_g       = (const float*)d_in[17];
    const float* gp_beta    = (const float*)d_in[18];
    const float* glob_W     = (const float*)d_in[19];
    const float* glob_asrc  = (const float*)d_in[20];
    const float* glob_adst  = (const float*)d_in[21];
    const float* glob_b     = (const float*)d_in[22];
    const float* cls_W1     = (const float*)d_in[23];
    const float* cls_b1     = (const float*)d_in[24];
    const float* cls_W2     = (const float*)d_in[25];
    const float* cls_b2     = (const float*)d_in[26];
    const int*   eil        = (const int*)d_in[27];
    const int*   node_batch = (const int*)d_in[28];
    const int*   cid        = (const int*)d_in[29];
    const int*   gei        = (const int*)d_in[30];

    const int* lsrc = eil;
    const int* ldst = eil + ELN;
    const int* gsrc = gei;
    const int* gdst = gei + EGN;

    float *p_h, *p_z, *p_ssrc, *p_sdst;
    float *p_emb, *p_cat, *p_tmp, *p_fused, *p_gx, *p_gz, *p_pea;
    int *p_deg, *p_rowptr, *p_fill, *p_psrc, *p_bsum;
    int *p_gdeg, *p_growptr, *p_gfill, *p_gpsrc, *p_gbsum;
    cudaGetSymbolAddress((void**)&p_h, g_h);
    cudaGetSymbolAddress((void**)&p_z, g_z);
    cudaGetSymbolAddress((void**)&p_ssrc, g_ssrc);
    cudaGetSymbolAddress((void**)&p_sdst, g_sdst);
    cudaGetSymbolAddress((void**)&p_emb, g_emb);
    cudaGetSymbolAddress((void**)&p_cat, g_cat);
    cudaGetSymbolAddress((void**)&p_tmp, g_tmp);
    cudaGetSymbolAddress((void**)&p_fused, g_fused);
    cudaGetSymbolAddress((void**)&p_gx, g_gx);
    cudaGetSymbolAddress((void**)&p_gz, g_gz);
    cudaGetSymbolAddress((void**)&p_pea, g_pea);
    cudaGetSymbolAddress((void**)&p_deg, g_deg);
    cudaGetSymbolAddress((void**)&p_rowptr, g_rowptr);
    cudaGetSymbolAddress((void**)&p_fill, g_fill);
    cudaGetSymbolAddress((void**)&p_psrc, g_psrc);
    cudaGetSymbolAddress((void**)&p_bsum, g_bsum);
    cudaGetSymbolAddress((void**)&p_gdeg, g_gdeg);
    cudaGetSymbolAddress((void**)&p_growptr, g_growptr);
    cudaGetSymbolAddress((void**)&p_gfill, g_gfill);
    cudaGetSymbolAddress((void**)&p_gpsrc, g_gpsrc);
    cudaGetSymbolAddress((void**)&p_gbsum, g_gbsum);

    // ---- input projection first (K=4) so launch slot 5 = big gemm_mma ----
    gemm_tile<<<CDIV(TN, 128), 256>>>(x_local, loc_in_W, loc_in_b, p_h, TN, 4,
                                      nullptr, nullptr);

    // local CSR (interleaved so ncu -s captures gemm_mma below)
    cudaMemsetAsync(p_deg, 0, TN * sizeof(int));
    hist_k<<<CDIV(ELN, 256), 256>>>(ldst, p_deg, ELN);
    scan1_k<<<CDIV(TN, 1024), 256>>>(p_deg, p_bsum, TN);

    // ---- local layer 0 GEMM (+fused scores) — profiling target ----
    gemm_mma<4><<<CDIV(TN, 128), 256>>>(p_h, loc_W, nullptr, p_z, TN, HH,
                                        loc_asrc, loc_adst, p_ssrc, p_sdst);

    scan2_k<<<1, 32>>>(p_bsum, CDIV(TN, 1024), p_rowptr, TN, ELN);
    scan3_k<<<CDIV(TN, 1024), 256>>>(p_deg, p_bsum, p_rowptr, p_fill, TN);
    scatedge_k<<<CDIV(ELN, 256), 256>>>(lsrc, ldst, eattr, p_fill, p_psrc, p_pea, ELN);

    // global CSR
    cudaMemsetAsync(p_gdeg, 0, NNODE * sizeof(int));
    hist_k<<<CDIV(EGN, 256), 256>>>(gdst, p_gdeg, EGN);
    scan1_k<<<CDIV(NNODE, 1024), 256>>>(p_gdeg, p_gbsum, NNODE);
    scan2_k<<<1, 32>>>(p_gbsum, CDIV(NNODE, 1024), p_growptr, NNODE, EGN);
    scan3_k<<<CDIV(NNODE, 1024), 256>>>(p_gdeg, p_gbsum, p_growptr, p_gfill, NNODE);
    scatedge_k<<<CDIV(EGN, 256), 256>>>(gsrc, gdst, (const float*)nullptr, p_gfill,
                                        p_gpsrc, (float*)nullptr, EGN);

    // ---- local layer 0 aggregate ----
    gat_fused<4, 32, true><<<CDIV(TN, 8), 256>>>(p_rowptr, p_psrc, p_pea,
                                                 loc_eW, loc_ae,
                                                 p_ssrc, p_sdst, p_z, loc_b, p_h, TN);
    // ---- local layer 1 ----
    gemm_mma<4><<<CDIV(TN, 128), 256>>>(p_h, loc_W + HH * HH, nullptr, p_z, TN, HH,
                                        loc_asrc + HH, loc_adst + HH, p_ssrc, p_sdst);
    gat_fused<4, 32, true><<<CDIV(TN, 8), 256>>>(p_rowptr, p_psrc, p_pea,
                                                 loc_eW + HH, loc_ae + HH,
                                                 p_ssrc, p_sdst, p_z, loc_b + HH, p_h, TN);

    // ---- contract mean pooling ----
    pool_k<<<BB, 128>>>(p_h, node_batch, p_emb);

    // ---- fused MLP ----
    concat_k<<<CDIV(BB * (HH + FGN), 256), 256>>>(p_emb, gfeat, cid, p_cat);
    gemm_mma<0><<<CDIV(BB, 128), 256>>>(p_cat, fp_W, fp_b, p_tmp, BB, HH + FGN,
                                        nullptr, nullptr, nullptr, nullptr);
    ln_relu_k<<<BB, HH>>>(p_tmp, fp_g, fp_beta, p_fused);

    // ---- global projection (fused LN+ReLU) + scatter ----
    gemm_tile<<<CDIV(NNODE, 128), 256>>>(gfeat, gp_W, gp_b, p_gx, NNODE, FGN,
                                         gp_g, gp_beta);
    scatfused_k<<<CDIV(BB * HH, 256), 256>>>(p_gx, p_fused, cid);

    // ---- 2x global GATConv ----
    for (int l = 0; l < 2; l++) {
        gemm_mma<2><<<CDIV(NNODE, 128), 256>>>(p_gx, glob_W + l * HH * HH, nullptr,
                                               p_gz, NNODE, HH,
                                               glob_asrc + l * HH, glob_adst + l * HH,
                                               p_ssrc, p_sdst);
        gat_fused<2, 64, false><<<CDIV(NNODE, 8), 256>>>(p_growptr, p_gpsrc, (float*)nullptr,
                                                         (float*)nullptr, (float*)nullptr,
                                                         p_ssrc, p_sdst, p_gz,
                                                         glob_b + l * HH, p_gx, NNODE);
    }

    // ---- classifier ----
    classifier_k<<<CDIV(BB, 8), 256>>>(p_gx, cid, cls_W1, cls_b1, cls_W2, cls_b2,
                                       (float*)d_out);
}

// round 9
// speedup vs baseline: 1.3114x; 1.0568x over previous
#include <cuda_runtime.h>
#include <math.h>

// ---------------- problem constants ----------------
#define TN    131072     // local tx nodes
#define ELN   524288     // local edges
#define NNODE 50000      // global contract nodes
#define EGN   400000     // global edges
#define BB    8192       // batch of contracts
#define HH    128        // hidden dim
#define FGN   7          // global feat dim
#define HCN   64         // classifier hidden
#define CC    2          // classes
#define CATP  144        // padded concat row stride (16B multiple)

#define CDIV(a,b) (((a)+(b)-1)/(b))

// ---------------- scratch (device globals) ----------------
__device__ float g_h   [TN*HH];
__device__ float g_z   [TN*HH];
__device__ float g_ssrc[TN*4];
__device__ float g_sdst[TN*4];
__device__ float g_emb [BB*HH];
__device__ float g_cat [BB*CATP];
__device__ float g_tmp [BB*HH];
__device__ float g_fused[BB*HH];
__device__ float g_gx  [NNODE*HH];
__device__ float g_gz  [NNODE*HH];
// CSR scratch
__device__ int   g_deg   [TN];
__device__ int   g_rowptr[TN+1];
__device__ int   g_fill  [TN];
__device__ int   g_psrc  [ELN];
__device__ float g_pea   [ELN];
__device__ int   g_bsum  [256];
__device__ int   g_gdeg   [NNODE];
__device__ int   g_growptr[NNODE+1];
__device__ int   g_gfill  [NNODE];
__device__ int   g_gpsrc  [EGN];
__device__ int   g_gbsum  [256];

// ---------------- helpers ----------------
__device__ __forceinline__ unsigned f2tf32(float f) {
    unsigned r;
    asm("cvt.rna.tf32.f32 %0, %1;" : "=r"(r) : "f"(f));
    return r;
}
__device__ __forceinline__ void cp_async16(unsigned dst, const void* src, int bytes) {
    asm volatile("cp.async.cg.shared.global [%0], [%1], 16, %2;"
                 :: "r"(dst), "l"(src), "r"(bytes) : "memory");
}
__device__ __forceinline__ void cp_commit() {
    asm volatile("cp.async.commit_group;" ::: "memory");
}
__device__ __forceinline__ void cp_wait1() {
    asm volatile("cp.async.wait_group 1;" ::: "memory");
}
__device__ __forceinline__ void cp_wait0() {
    asm volatile("cp.async.wait_group 0;" ::: "memory");
}

// ================= CSR construction =================
__global__ void hist_k(const int* __restrict__ dst, int* __restrict__ deg, int E) {
    int e = blockIdx.x * blockDim.x + threadIdx.x;
    if (e < E) atomicAdd(&deg[dst[e]], 1);
}
__global__ void scan1_k(const int* __restrict__ deg, int* __restrict__ bsum, int n) {
    __shared__ int s[256];
    int base = blockIdx.x * 1024, t = threadIdx.x;
    int sum = 0;
#pragma unroll
    for (int i = 0; i < 4; i++) {
        int idx = base + t * 4 + i;
        if (idx < n) sum += deg[idx];
    }
    s[t] = sum; __syncthreads();
    for (int o = 128; o > 0; o >>= 1) { if (t < o) s[t] += s[t + o]; __syncthreads(); }
    if (t == 0) bsum[blockIdx.x] = s[0];
}
__global__ void scan2_k(int* __restrict__ bsum, int nb, int* __restrict__ rowptr,
                        int n, int E) {
    if (threadIdx.x == 0) {
        int acc = 0;
        for (int i = 0; i < nb; i++) { int v = bsum[i]; bsum[i] = acc; acc += v; }
        rowptr[n] = E;
    }
}
__global__ void scan3_k(const int* __restrict__ deg, const int* __restrict__ bsum,
                        int* __restrict__ rowptr, int* __restrict__ fill, int n) {
    __shared__ int s[256];
    int base = blockIdx.x * 1024, t = threadIdx.x;
    int v[4]; int sum = 0;
#pragma unroll
    for (int i = 0; i < 4; i++) {
        int idx = base + t * 4 + i;
        v[i] = (idx < n) ? deg[idx] : 0;
        sum += v[i];
    }
    s[t] = sum; __syncthreads();
    for (int o = 1; o < 256; o <<= 1) {
        int x = (t >= o) ? s[t - o] : 0;
        __syncthreads();
        s[t] += x;
        __syncthreads();
    }
    int excl = ((t == 0) ? 0 : s[t - 1]) + bsum[blockIdx.x];
#pragma unroll
    for (int i = 0; i < 4; i++) {
        int idx = base + t * 4 + i;
        if (idx < n) { rowptr[idx] = excl; fill[idx] = excl; }
        excl += v[i];
    }
}
__global__ void scatedge_k(const int* __restrict__ src, const int* __restrict__ dst,
                           const float* __restrict__ eattr, int* __restrict__ fill,
                           int* __restrict__ psrc, float* __restrict__ pea, int E) {
    int e = blockIdx.x * blockDim.x + threadIdx.x;
    if (e < E) {
        int p = atomicAdd(&fill[dst[e]], 1);
        psrc[p] = src[e];
        if (pea) pea[p] = eattr[e];
    }
}

// ================= tf32 MMA GEMM, cp.async 3-stage pipeline =================
// BM=64, BN=128, BK=16. 8 warps: warp tile 16x64 (grid 4x2).
// lda must be a multiple of 4 (16B-aligned rows for cp.async).
// NH=0: plain GEMM. NH>0: epilogue emits ssrc/sdst per (row, head).
#define APAD 20
#define WPAD 136
#define ABUF (64 * APAD)
#define WBUF (16 * WPAD)
template <int NH>
__global__ __launch_bounds__(256, 3)
void gemm_mma(const float* __restrict__ A, const float* __restrict__ W,
              const float* __restrict__ bias, float* __restrict__ C,
              int M, int K, int lda,
              const float* __restrict__ asrc, const float* __restrict__ adst,
              float* __restrict__ ssrc, float* __restrict__ sdst) {
    __shared__ __align__(16) float As[3 * ABUF];
    __shared__ __align__(16) float Ws[3 * WBUF];
    const int tid  = threadIdx.x;
    const int warp = tid >> 5, lane = tid & 31;
    const int bm   = blockIdx.x * 64;
    const int wm   = (warp >> 1) * 16;
    const int wn   = (warp & 1) * 64;
    const int g    = lane >> 2;
    const int ct   = lane & 3;
    const int nk   = (K + 15) / 16;

    const unsigned asb = (unsigned)__cvta_generic_to_shared(As);
    const unsigned wsb = (unsigned)__cvta_generic_to_shared(Ws);

    float c[8][4];
#pragma unroll
    for (int nt = 0; nt < 8; nt++)
#pragma unroll
        for (int r = 0; r < 4; r++) c[nt][r] = 0.f;

    auto issue = [&](int buf, int t) {
        int k0 = t * 16;
        {
            int m = tid >> 2, kq = (tid & 3) * 4;
            int gr = bm + m, gk = k0 + kq;
            int bytes = 0;
            const float* src = A;
            if (gr < M && gk < K) {
                int rem = K - gk;
                bytes = rem >= 4 ? 16 : rem * 4;
                src = A + (size_t)gr * lda + gk;    // lda%4==0 -> 16B aligned
            }
            cp_async16(asb + (unsigned)(buf * ABUF + m * APAD + kq) * 4u, src, bytes);
        }
#pragma unroll
        for (int i = tid; i < 512; i += 256) {
            int k = i >> 5, nq = (i & 31) * 4;
            int gk = k0 + k;
            int bytes = (gk < K) ? 16 : 0;
            const float* src = (gk < K) ? (W + (size_t)gk * 128 + nq) : W;
            cp_async16(wsb + (unsigned)(buf * WBUF + k * WPAD + nq) * 4u, src, bytes);
        }
        cp_commit();
    };

    issue(0, 0);
    if (nk > 1) issue(1, 1);

    for (int t = 0; t < nk; t++) {
        if (t + 1 < nk) cp_wait1(); else cp_wait0();
        __syncthreads();
        if (t + 2 < nk) issue((t + 2) % 3, t + 2);

        const float* Ab = As + (t % 3) * ABUF;
        const float* Wb = Ws + (t % 3) * WBUF;
#pragma unroll
        for (int ks = 0; ks < 16; ks += 8) {
            unsigned b[8][2];
#pragma unroll
            for (int nt = 0; nt < 8; nt++) {
                int n = wn + nt * 8 + g;
                b[nt][0] = f2tf32(Wb[(ks + ct) * WPAD + n]);
                b[nt][1] = f2tf32(Wb[(ks + ct + 4) * WPAD + n]);
            }
            unsigned a0 = f2tf32(Ab[(wm + g) * APAD + ks + ct]);
            unsigned a1 = f2tf32(Ab[(wm + g + 8) * APAD + ks + ct]);
            unsigned a2 = f2tf32(Ab[(wm + g) * APAD + ks + ct + 4]);
            unsigned a3 = f2tf32(Ab[(wm + g + 8) * APAD + ks + ct + 4]);
#pragma unroll
            for (int nt = 0; nt < 8; nt++) {
                asm volatile(
                    "mma.sync.aligned.m16n8k8.row.col.f32.tf32.tf32.f32 "
                    "{%0,%1,%2,%3}, {%4,%5,%6,%7}, {%8,%9}, {%0,%1,%2,%3};"
                    : "+f"(c[nt][0]), "+f"(c[nt][1]), "+f"(c[nt][2]), "+f"(c[nt][3])
                    : "r"(a0), "r"(a1), "r"(a2), "r"(a3),
                      "r"(b[nt][0]), "r"(b[nt][1]));
            }
        }
        __syncthreads();
    }

    // epilogue: store C (+bias) and optionally fused attention scores
    const int NH2 = (NH == 4) ? 2 : 1;
    float ps[2][2], pd[2][2];
    if (NH > 0) {
#pragma unroll
        for (int a = 0; a < 2; a++)
#pragma unroll
            for (int d = 0; d < 2; d++) { ps[a][d] = 0.f; pd[a][d] = 0.f; }
    }
    int r0 = bm + wm + g, r1 = r0 + 8;
#pragma unroll
    for (int nt = 0; nt < 8; nt++) {
        int col = wn + nt * 8 + 2 * ct;
        float b0 = bias ? bias[col] : 0.f;
        float b1 = bias ? bias[col + 1] : 0.f;
        float v00 = c[nt][0] + b0, v01 = c[nt][1] + b1;
        float v10 = c[nt][2] + b0, v11 = c[nt][3] + b1;
        if (r0 < M) *(float2*)(C + (size_t)r0 * 128 + col) = make_float2(v00, v01);
        if (r1 < M) *(float2*)(C + (size_t)r1 * 128 + col) = make_float2(v10, v11);
        if (NH > 0) {
            float a0s = asrc[col], a1s = asrc[col + 1];
            float a0d = adst[col], a1d = adst[col + 1];
            int h2 = (NH == 4) ? (nt >> 2) : 0;
            ps[0][h2] += v00 * a0s + v01 * a1s;
            ps[1][h2] += v10 * a0s + v11 * a1s;
            pd[0][h2] += v00 * a0d + v01 * a1d;
            pd[1][h2] += v10 * a0d + v11 * a1d;
        }
    }
    if (NH > 0) {
#pragma unroll
        for (int rh = 0; rh < 2; rh++)
#pragma unroll
            for (int h2 = 0; h2 < NH2; h2++) {
                float s = ps[rh][h2], d = pd[rh][h2];
                s += __shfl_xor_sync(0xffffffffu, s, 1);
                s += __shfl_xor_sync(0xffffffffu, s, 2);
                d += __shfl_xor_sync(0xffffffffu, d, 1);
                d += __shfl_xor_sync(0xffffffffu, d, 2);
                ps[rh][h2] = s; pd[rh][h2] = d;
            }
        if (ct == 0) {
            int headbase = (wn * NH) >> 7;
#pragma unroll
            for (int rh = 0; rh < 2; rh++) {
                int row = (rh == 0) ? r0 : r1;
                if (row < M) {
#pragma unroll
                    for (int h2 = 0; h2 < NH2; h2++) {
                        int head = headbase + h2;
                        ssrc[(size_t)row * NH + head] = ps[rh][h2];
                        sdst[(size_t)row * NH + head] = pd[rh][h2];
                    }
                }
            }
        }
    }
}

// ---------------- SIMT GEMM for tiny-K projections (+optional fused LN+ReLU) --------
__global__ __launch_bounds__(256, 2)
void gemm_tile(const float* __restrict__ A, const float* __restrict__ W,
               const float* __restrict__ bias, float* __restrict__ C,
               int M, int K,
               const float* __restrict__ gamma, const float* __restrict__ beta) {
    __shared__ float As[16 * 132];
    __shared__ float Ws[16 * 132];
    const int bm  = blockIdx.x * 128;
    const int tid = threadIdx.x;
    const int tr  = (tid >> 4) * 8;
    const int tc  = (tid & 15) * 8;
    float acc[8][8];
#pragma unroll
    for (int x = 0; x < 8; x++)
#pragma unroll
        for (int y = 0; y < 8; y++) acc[x][y] = 0.f;

    for (int k0 = 0; k0 < K; k0 += 16) {
        for (int i = tid; i < 128 * 16; i += 256) {
            int m = i >> 4, kk = i & 15;
            int gr = bm + m, gk = k0 + kk;
            As[kk * 132 + m] = (gr < M && gk < K) ? A[(size_t)gr * K + gk] : 0.f;
        }
        for (int i = tid; i < 16 * 128; i += 256) {
            int kk = i >> 7, n = i & 127;
            int gk = k0 + kk;
            Ws[kk * 132 + n] = (gk < K) ? W[gk * 128 + n] : 0.f;
        }
        __syncthreads();
#pragma unroll
        for (int kk = 0; kk < 16; kk++) {
            float a[8], w[8];
#pragma unroll
            for (int x = 0; x < 8; x++) a[x] = As[kk * 132 + tr + x];
#pragma unroll
            for (int y = 0; y < 8; y++) w[y] = Ws[kk * 132 + tc + y];
#pragma unroll
            for (int x = 0; x < 8; x++)
#pragma unroll
                for (int y = 0; y < 8; y++) acc[x][y] += a[x] * w[y];
        }
        __syncthreads();
    }

    if (gamma) {
#pragma unroll
        for (int x = 0; x < 8; x++) {
            int gr = bm + tr + x;
            float vv[8]; float sum = 0.f;
#pragma unroll
            for (int y = 0; y < 8; y++) {
                vv[y] = acc[x][y] + (bias ? bias[tc + y] : 0.f);
                sum += vv[y];
            }
#pragma unroll
            for (int k = 1; k < 16; k <<= 1) sum += __shfl_xor_sync(0xffffffffu, sum, k, 16);
            float mean = sum * (1.f / 128.f);
            float sq = 0.f;
#pragma unroll
            for (int y = 0; y < 8; y++) { float d = vv[y] - mean; sq += d * d; }
#pragma unroll
            for (int k = 1; k < 16; k <<= 1) sq += __shfl_xor_sync(0xffffffffu, sq, k, 16);
            float rstd = rsqrtf(sq * (1.f / 128.f) + 1e-5f);
            if (gr < M) {
#pragma unroll
                for (int y = 0; y < 8; y++) {
                    float yv = (vv[y] - mean) * rstd * gamma[tc + y] + beta[tc + y];
                    C[(size_t)gr * 128 + tc + y] = fmaxf(yv, 0.f);
                }
            }
        }
    } else {
#pragma unroll
        for (int x = 0; x < 8; x++) {
            int gr = bm + tr + x;
            if (gr < M) {
#pragma unroll
                for (int y = 0; y < 8; y++) {
                    float v = acc[x][y];
                    if (bias) v += bias[tc + y];
                    C[(size_t)gr * 128 + tc + y] = v;
                }
            }
        }
    }
}

// ---------------- fused single-pass GAT aggregation ----------------
template <int NH, int HD, bool HAS_E>
__global__ void gat_fused(const int* __restrict__ rowptr, const int* __restrict__ psrc,
                          const float* __restrict__ pea,
                          const float* __restrict__ eW, const float* __restrict__ ae,
                          const float* __restrict__ ssrc, const float* __restrict__ sdst,
                          const float* __restrict__ z, const float* __restrict__ bias,
                          float* __restrict__ h, int n) {
    __shared__ float ce_s[NH];
    if (HAS_E && threadIdx.x < NH) {
        int hh = threadIdx.x;
        float s = 0.f;
#pragma unroll
        for (int d = 0; d < HD; d++) s += eW[hh * HD + d] * ae[hh * HD + d];
        ce_s[hh] = s;
    }
    if (HAS_E) __syncthreads();

    int node = blockIdx.x * 8 + (threadIdx.x >> 5);
    if (node >= n) return;
    int lane = threadIdx.x & 31;
    int c = lane * 4;
    int head = c / HD;

    float sd = sdst[(size_t)node * NH + head];
    float ce = HAS_E ? ce_s[head] : 0.f;

    float4 acc = make_float4(0.f, 0.f, 0.f, 0.f);
    float den = 0.f;
    int lo = rowptr[node], hi = rowptr[node + 1];
    for (int j = lo; j < hi; j++) {
        int s = psrc[j];
        float sc = ssrc[(size_t)s * NH + head] + sd;
        if (HAS_E) sc += pea[j] * ce;
        sc = sc > 0.f ? sc : 0.2f * sc;
        float ex = __expf(sc);
        den += ex;
        float4 zv = *(const float4*)(z + (size_t)s * HH + c);
        acc.x += ex * zv.x; acc.y += ex * zv.y;
        acc.z += ex * zv.z; acc.w += ex * zv.w;
    }
    float inv = 1.f / fmaxf(den, 1e-16f);
    float4 hv = *(const float4*)(h + (size_t)node * HH + c);
    float4 bv = *(const float4*)(bias + c);
    acc.x = hv.x + bv.x + acc.x * inv;
    acc.y = hv.y + bv.y + acc.y * inv;
    acc.z = hv.z + bv.z + acc.z * inv;
    acc.w = hv.w + bv.w + acc.w * inv;
    acc.x = acc.x > 0.f ? acc.x : __expf(acc.x) - 1.f;
    acc.y = acc.y > 0.f ? acc.y : __expf(acc.y) - 1.f;
    acc.z = acc.z > 0.f ? acc.z : __expf(acc.z) - 1.f;
    acc.w = acc.w > 0.f ? acc.w : __expf(acc.w) - 1.f;
    *(float4*)(h + (size_t)node * HH + c) = acc;
}

// ---------------- mean pooling via binary search on sorted node_batch ----------------
__global__ void pool_k(const float* __restrict__ h, const int* __restrict__ nb,
                       float* __restrict__ emb) {
    int b = blockIdx.x, t = threadIdx.x;
    int lo = 0, hi = TN;
    while (lo < hi) { int mid = (lo + hi) >> 1; if (nb[mid] < b) lo = mid + 1; else hi = mid; }
    int start = lo;
    hi = TN;
    while (lo < hi) { int mid = (lo + hi) >> 1; if (nb[mid] < b + 1) lo = mid + 1; else hi = mid; }
    int end = lo;
    float s = 0.f;
    for (int i = start; i < end; i++) s += h[(size_t)i * HH + t];
    emb[(size_t)b * HH + t] = s / fmaxf((float)(end - start), 1.f);
}

// ---------------- concat [emb | gf[cid]] into padded rows ----------------
__global__ void concat_k(const float* __restrict__ emb, const float* __restrict__ gf,
                         const int* __restrict__ cid, float* __restrict__ cat) {
    int i = blockIdx.x * blockDim.x + threadIdx.x;
    if (i >= BB * (HH + FGN)) return;
    int b = i / (HH + FGN), j = i % (HH + FGN);
    cat[(size_t)b * CATP + j] = (j < HH) ? emb[(size_t)b * HH + j]
                                         : gf[(size_t)cid[b] * FGN + (j - HH)];
}

// ---------------- LayerNorm(128) + ReLU ----------------
__global__ void ln_relu_k(const float* __restrict__ X, const float* __restrict__ g,
                          const float* __restrict__ be, float* __restrict__ Y) {
    int row = blockIdx.x, t = threadIdx.x;
    float v = X[(size_t)row * HH + t];
    __shared__ float red[HH];
    red[t] = v; __syncthreads();
    for (int s = 64; s > 0; s >>= 1) { if (t < s) red[t] += red[t + s]; __syncthreads(); }
    float mean = red[0] / 128.f;
    __syncthreads();
    float dv = v - mean;
    red[t] = dv * dv; __syncthreads();
    for (int s = 64; s > 0; s >>= 1) { if (t < s) red[t] += red[t + s]; __syncthreads(); }
    float var = red[0] / 128.f;
    float y = dv * rsqrtf(var + 1e-5f) * g[t] + be[t];
    Y[(size_t)row * HH + t] = fmaxf(y, 0.f);
}

// ---------------- scatter fused batch embeddings into gx ----------------
__global__ void scatfused_k(float* __restrict__ gx, const float* __restrict__ fused,
                            const int* __restrict__ cid) {
    int i = blockIdx.x * blockDim.x + threadIdx.x;
    if (i >= BB * HH) return;
    int b = i >> 7;
    gx[(size_t)cid[b] * HH + (i & 127)] = fused[i];
}

// ---------------- classifier: 8 contracts per block ----------------
__global__ __launch_bounds__(256)
void classifier_k(const float* __restrict__ gx, const int* __restrict__ cid,
                  const float* __restrict__ W1, const float* __restrict__ b1,
                  const float* __restrict__ W2, const float* __restrict__ b2,
                  float* __restrict__ out) {
    __shared__ float row[4][HH];
    __shared__ float hc[4][HCN];
    int tid = threadIdx.x;
    int grp = tid >> 6, t = tid & 63;
    for (int it = 0; it < 2; it++) {
        int b = blockIdx.x * 8 + it * 4 + grp;
        __syncthreads();
        const float* srcp = gx + (size_t)cid[b] * HH;
        row[grp][t] = srcp[t];
        row[grp][t + 64] = srcp[t + 64];
        __syncthreads();
        float s = b1[t];
#pragma unroll
        for (int k = 0; k < HH; k++) s += row[grp][k] * W1[k * HCN + t];
        hc[grp][t] = fmaxf(s, 0.f);
        __syncthreads();
        if (t < CC) {
            float s2 = b2[t];
#pragma unroll
            for (int k = 0; k < HCN; k++) s2 += hc[grp][k] * W2[k * CC + t];
            out[b * CC + t] = s2;
        }
    }
}

// ---------------- launch ----------------
extern "C" void kernel_launch(void* const* d_in, const int* in_sizes, int n_in,
                              void* d_out, int out_size) {
    const float* x_local    = (const float*)d_in[0];
    const float* eattr      = (const float*)d_in[1];
    const float* gfeat      = (const float*)d_in[2];
    const float* loc_in_W   = (const float*)d_in[3];
    const float* loc_in_b   = (const float*)d_in[4];
    const float* loc_W      = (const float*)d_in[5];
    const float* loc_asrc   = (const float*)d_in[6];
    const float* loc_adst   = (const float*)d_in[7];
    const float* loc_eW     = (const float*)d_in[8];
    const float* loc_ae     = (const float*)d_in[9];
    const float* loc_b      = (const float*)d_in[10];
    const float* fp_W       = (const float*)d_in[11];
    const float* fp_b       = (const float*)d_in[12];
    const float* fp_g       = (const float*)d_in[13];
    const float* fp_beta    = (const float*)d_in[14];
    const float* gp_W       = (const float*)d_in[15];
    const float* gp_b       = (const float*)d_in[16];
    const float* gp_g       = (const float*)d_in[17];
    const float* gp_beta    = (const float*)d_in[18];
    const float* glob_W     = (const float*)d_in[19];
    const float* glob_asrc  = (const float*)d_in[20];
    const float* glob_adst  = (const float*)d_in[21];
    const float* glob_b     = (const float*)d_in[22];
    const float* cls_W1     = (const float*)d_in[23];
    const float* cls_b1     = (const float*)d_in[24];
    const float* cls_W2     = (const float*)d_in[25];
    const float* cls_b2     = (const float*)d_in[26];
    const int*   eil        = (const int*)d_in[27];
    const int*   node_batch = (const int*)d_in[28];
    const int*   cid        = (const int*)d_in[29];
    const int*   gei        = (const int*)d_in[30];

    const int* lsrc = eil;
    const int* ldst = eil + ELN;
    const int* gsrc = gei;
    const int* gdst = gei + EGN;

    float *p_h, *p_z, *p_ssrc, *p_sdst;
    float *p_emb, *p_cat, *p_tmp, *p_fused, *p_gx, *p_gz, *p_pea;
    int *p_deg, *p_rowptr, *p_fill, *p_psrc, *p_bsum;
    int *p_gdeg, *p_growptr, *p_gfill, *p_gpsrc, *p_gbsum;
    cudaGetSymbolAddress((void**)&p_h, g_h);
    cudaGetSymbolAddress((void**)&p_z, g_z);
    cudaGetSymbolAddress((void**)&p_ssrc, g_ssrc);
    cudaGetSymbolAddress((void**)&p_sdst, g_sdst);
    cudaGetSymbolAddress((void**)&p_emb, g_emb);
    cudaGetSymbolAddress((void**)&p_cat, g_cat);
    cudaGetSymbolAddress((void**)&p_tmp, g_tmp);
    cudaGetSymbolAddress((void**)&p_fused, g_fused);
    cudaGetSymbolAddress((void**)&p_gx, g_gx);
    cudaGetSymbolAddress((void**)&p_gz, g_gz);
    cudaGetSymbolAddress((void**)&p_pea, g_pea);
    cudaGetSymbolAddress((void**)&p_deg, g_deg);
    cudaGetSymbolAddress((void**)&p_rowptr, g_rowptr);
    cudaGetSymbolAddress((void**)&p_fill, g_fill);
    cudaGetSymbolAddress((void**)&p_psrc, g_psrc);
    cudaGetSymbolAddress((void**)&p_bsum, g_bsum);
    cudaGetSymbolAddress((void**)&p_gdeg, g_gdeg);
    cudaGetSymbolAddress((void**)&p_growptr, g_growptr);
    cudaGetSymbolAddress((void**)&p_gfill, g_gfill);
    cudaGetSymbolAddress((void**)&p_gpsrc, g_gpsrc);
    cudaGetSymbolAddress((void**)&p_gbsum, g_gbsum);

    // ---- input projection first (K=4) so launch slot 5 = big gemm_mma ----
    gemm_tile<<<CDIV(TN, 128), 256>>>(x_local, loc_in_W, loc_in_b, p_h, TN, 4,
                                      nullptr, nullptr);

    // local CSR (interleaved so ncu -s captures gemm_mma below)
    cudaMemsetAsync(p_deg, 0, TN * sizeof(int));
    hist_k<<<CDIV(ELN, 256), 256>>>(ldst, p_deg, ELN);
    scan1_k<<<CDIV(TN, 1024), 256>>>(p_deg, p_bsum, TN);

    // ---- local layer 0 GEMM (+fused scores) — profiling target ----
    gemm_mma<4><<<CDIV(TN, 64), 256>>>(p_h, loc_W, nullptr, p_z, TN, HH, HH,
                                       loc_asrc, loc_adst, p_ssrc, p_sdst);

    scan2_k<<<1, 32>>>(p_bsum, CDIV(TN, 1024), p_rowptr, TN, ELN);
    scan3_k<<<CDIV(TN, 1024), 256>>>(p_deg, p_bsum, p_rowptr, p_fill, TN);
    scatedge_k<<<CDIV(ELN, 256), 256>>>(lsrc, ldst, eattr, p_fill, p_psrc, p_pea, ELN);

    // global CSR
    cudaMemsetAsync(p_gdeg, 0, NNODE * sizeof(int));
    hist_k<<<CDIV(EGN, 256), 256>>>(gdst, p_gdeg, EGN);
    scan1_k<<<CDIV(NNODE, 1024), 256>>>(p_gdeg, p_gbsum, NNODE);
    scan2_k<<<1, 32>>>(p_gbsum, CDIV(NNODE, 1024), p_growptr, NNODE, EGN);
    scan3_k<<<CDIV(NNODE, 1024), 256>>>(p_gdeg, p_gbsum, p_growptr, p_gfill, NNODE);
    scatedge_k<<<CDIV(EGN, 256), 256>>>(gsrc, gdst, (const float*)nullptr, p_gfill,
                                        p_gpsrc, (float*)nullptr, EGN);

    // ---- local layer 0 aggregate ----
    gat_fused<4, 32, true><<<CDIV(TN, 8), 256>>>(p_rowptr, p_psrc, p_pea,
                                                 loc_eW, loc_ae,
                                                 p_ssrc, p_sdst, p_z, loc_b, p_h, TN);
    // ---- local layer 1 ----
    gemm_mma<4><<<CDIV(TN, 64), 256>>>(p_h, loc_W + HH * HH, nullptr, p_z, TN, HH, HH,
                                       loc_asrc + HH, loc_adst + HH, p_ssrc, p_sdst);
    gat_fused<4, 32, true><<<CDIV(TN, 8), 256>>>(p_rowptr, p_psrc, p_pea,
                                                 loc_eW + HH, loc_ae + HH,
                                                 p_ssrc, p_sdst, p_z, loc_b + HH, p_h, TN);

    // ---- contract mean pooling ----
    pool_k<<<BB, 128>>>(p_h, node_batch, p_emb);

    // ---- fused MLP (padded-lda MMA GEMM) ----
    concat_k<<<CDIV(BB * (HH + FGN), 256), 256>>>(p_emb, gfeat, cid, p_cat);
    gemm_mma<0><<<CDIV(BB, 64), 256>>>(p_cat, fp_W, fp_b, p_tmp, BB, HH + FGN, CATP,
                                       nullptr, nullptr, nullptr, nullptr);
    ln_relu_k<<<BB, HH>>>(p_tmp, fp_g, fp_beta, p_fused);

    // ---- global projection (fused LN+ReLU) + scatter ----
    gemm_tile<<<CDIV(NNODE, 128), 256>>>(gfeat, gp_W, gp_b, p_gx, NNODE, FGN,
                                         gp_g, gp_beta);
    scatfused_k<<<CDIV(BB * HH, 256), 256>>>(p_gx, p_fused, cid);

    // ---- 2x global GATConv ----
    for (int l = 0; l < 2; l++) {
        gemm_mma<2><<<CDIV(NNODE, 64), 256>>>(p_gx, glob_W + l * HH * HH, nullptr,
                                              p_gz, NNODE, HH, HH,
                                              glob_asrc + l * HH, glob_adst + l * HH,
                                              p_ssrc, p_sdst);
        gat_fused<2, 64, false><<<CDIV(NNODE, 8), 256>>>(p_growptr, p_gpsrc, (float*)nullptr,
                                                         (float*)nullptr, (float*)nullptr,
                                                         p_ssrc, p_sdst, p_gz,
                                                         glob_b + l * HH, p_gx, NNODE);
    }

    // ---- classifier ----
    classifier_k<<<CDIV(BB, 8), 256>>>(p_gx, cid, cls_W1, cls_b1, cls_W2, cls_b2,
                                       (float*)d_out);
}

// round 10
// speedup vs baseline: 1.3428x; 1.0239x over previous
#include <cuda_runtime.h>
#include <math.h>

// ---------------- problem constants ----------------
#define TN    131072     // local tx nodes
#define ELN   524288     // local edges
#define NNODE 50000      // global contract nodes
#define EGN   400000     // global edges
#define BB    8192       // batch of contracts
#define HH    128        // hidden dim
#define FGN   7          // global feat dim
#define HCN   64         // classifier hidden
#define CC    2          // classes
#define CATP  144        // padded concat row stride (16B multiple)

#define CDIV(a,b) (((a)+(b)-1)/(b))

// pre-rounded weight buffer offsets (floats)
#define WT_LOC0 0
#define WT_LOC1 16384
#define WT_FP   32768
#define WT_G0   50048
#define WT_G1   66432
#define WT_TOT  82816

// ---------------- scratch (device globals) ----------------
__device__ float g_h   [TN*HH];
__device__ float g_z   [TN*HH];
__device__ float g_ssrc[TN*4];
__device__ float g_sdst[TN*4];
__device__ float g_emb [BB*HH];
__device__ float g_cat [BB*CATP];
__device__ float g_tmp [BB*HH];
__device__ float g_fused[BB*HH];
__device__ float g_gx  [NNODE*HH];
__device__ float g_gz  [NNODE*HH];
__device__ float g_wtf [WT_TOT];
// CSR scratch
__device__ int   g_deg   [TN];
__device__ int   g_rowptr[TN+1];
__device__ int   g_fill  [TN];
__device__ int   g_psrc  [ELN];
__device__ float g_pea   [ELN];
__device__ int   g_bsum  [256];
__device__ int   g_gdeg   [NNODE];
__device__ int   g_growptr[NNODE+1];
__device__ int   g_gfill  [NNODE];
__device__ int   g_gpsrc  [EGN];
__device__ int   g_gbsum  [256];

// ---------------- helpers ----------------
__device__ __forceinline__ unsigned f2tf32(float f) {
    unsigned r;
    asm("cvt.rna.tf32.f32 %0, %1;" : "=r"(r) : "f"(f));
    return r;
}
__device__ __forceinline__ void cp_async16(unsigned dst, const void* src, int bytes) {
    asm volatile("cp.async.cg.shared.global [%0], [%1], 16, %2;"
                 :: "r"(dst), "l"(src), "r"(bytes) : "memory");
}
__device__ __forceinline__ void cp_commit() {
    asm volatile("cp.async.commit_group;" ::: "memory");
}
__device__ __forceinline__ void cp_wait1() {
    asm volatile("cp.async.wait_group 1;" ::: "memory");
}
__device__ __forceinline__ void cp_wait0() {
    asm volatile("cp.async.wait_group 0;" ::: "memory");
}

// ---------------- weight pre-rounding to tf32 bit-pattern + deg zeroing ----------
__global__ void wconv_k(const float* __restrict__ locW, const float* __restrict__ fpW,
                        const float* __restrict__ globW, float* __restrict__ wt,
                        int* __restrict__ deg, int* __restrict__ gdeg) {
    int i = blockIdx.x * blockDim.x + threadIdx.x;
    if (i < 32768)       wt[i] = __uint_as_float(f2tf32(locW[i]));
    else if (i < 50048)  wt[i] = __uint_as_float(f2tf32(fpW[i - 32768]));
    else if (i < WT_TOT) wt[i] = __uint_as_float(f2tf32(globW[i - 50048]));
    if (i < TN)    deg[i]  = 0;
    if (i < NNODE) gdeg[i] = 0;
}

// ================= CSR construction =================
__global__ void hist_k(const int* __restrict__ dst, int* __restrict__ deg, int E) {
    int e = blockIdx.x * blockDim.x + threadIdx.x;
    if (e < E) atomicAdd(&deg[dst[e]], 1);
}
__global__ void scan1_k(const int* __restrict__ deg, int* __restrict__ bsum, int n) {
    __shared__ int s[256];
    int base = blockIdx.x * 1024, t = threadIdx.x;
    int sum = 0;
#pragma unroll
    for (int i = 0; i < 4; i++) {
        int idx = base + t * 4 + i;
        if (idx < n) sum += deg[idx];
    }
    s[t] = sum; __syncthreads();
    for (int o = 128; o > 0; o >>= 1) { if (t < o) s[t] += s[t + o]; __syncthreads(); }
    if (t == 0) bsum[blockIdx.x] = s[0];
}
__global__ void scan2_k(int* __restrict__ bsum, int nb, int* __restrict__ rowptr,
                        int n, int E) {
    if (threadIdx.x == 0) {
        int acc = 0;
        for (int i = 0; i < nb; i++) { int v = bsum[i]; bsum[i] = acc; acc += v; }
        rowptr[n] = E;
    }
}
__global__ void scan3_k(const int* __restrict__ deg, const int* __restrict__ bsum,
                        int* __restrict__ rowptr, int* __restrict__ fill, int n) {
    __shared__ int s[256];
    int base = blockIdx.x * 1024, t = threadIdx.x;
    int v[4]; int sum = 0;
#pragma unroll
    for (int i = 0; i < 4; i++) {
        int idx = base + t * 4 + i;
        v[i] = (idx < n) ? deg[idx] : 0;
        sum += v[i];
    }
    s[t] = sum; __syncthreads();
    for (int o = 1; o < 256; o <<= 1) {
        int x = (t >= o) ? s[t - o] : 0;
        __syncthreads();
        s[t] += x;
        __syncthreads();
    }
    int excl = ((t == 0) ? 0 : s[t - 1]) + bsum[blockIdx.x];
#pragma unroll
    for (int i = 0; i < 4; i++) {
        int idx = base + t * 4 + i;
        if (idx < n) { rowptr[idx] = excl; fill[idx] = excl; }
        excl += v[i];
    }
}
__global__ void scatedge_k(const int* __restrict__ src, const int* __restrict__ dst,
                           const float* __restrict__ eattr, int* __restrict__ fill,
                           int* __restrict__ psrc, float* __restrict__ pea, int E) {
    int e = blockIdx.x * blockDim.x + threadIdx.x;
    if (e < E) {
        int p = atomicAdd(&fill[dst[e]], 1);
        psrc[p] = src[e];
        if (pea) pea[p] = eattr[e];
    }
}

// ================= tf32 MMA GEMM, cp.async 3-stage pipeline =================
// BM=64, BN=128, BK=16. 8 warps: warp tile 16x64 (grid 4x2).
// W must be pre-rounded tf32 bit-patterns (g_wtf) — fed raw to the MMA.
// A converted consume-side with cvt.rna. lda must be a multiple of 4.
#define APAD 20
#define WPAD 136
#define ABUF (64 * APAD)
#define WBUF (16 * WPAD)
template <int NH>
__global__ __launch_bounds__(256, 3)
void gemm_mma(const float* __restrict__ A, const float* __restrict__ W,
              const float* __restrict__ bias, float* __restrict__ C,
              int M, int K, int lda,
              const float* __restrict__ asrc, const float* __restrict__ adst,
              float* __restrict__ ssrc, float* __restrict__ sdst) {
    __shared__ __align__(16) float As[3 * ABUF];
    __shared__ __align__(16) float Ws[3 * WBUF];
    const int tid  = threadIdx.x;
    const int warp = tid >> 5, lane = tid & 31;
    const int bm   = blockIdx.x * 64;
    const int wm   = (warp >> 1) * 16;
    const int wn   = (warp & 1) * 64;
    const int g    = lane >> 2;
    const int ct   = lane & 3;
    const int nk   = (K + 15) / 16;

    const unsigned asb = (unsigned)__cvta_generic_to_shared(As);
    const unsigned wsb = (unsigned)__cvta_generic_to_shared(Ws);

    float c[8][4];
#pragma unroll
    for (int nt = 0; nt < 8; nt++)
#pragma unroll
        for (int r = 0; r < 4; r++) c[nt][r] = 0.f;

    auto issue = [&](int buf, int t) {
        int k0 = t * 16;
        {
            int m = tid >> 2, kq = (tid & 3) * 4;
            int gr = bm + m, gk = k0 + kq;
            int bytes = 0;
            const float* src = A;
            if (gr < M && gk < K) {
                int rem = K - gk;
                bytes = rem >= 4 ? 16 : rem * 4;
                src = A + (size_t)gr * lda + gk;
            }
            cp_async16(asb + (unsigned)(buf * ABUF + m * APAD + kq) * 4u, src, bytes);
        }
#pragma unroll
        for (int i = tid; i < 512; i += 256) {
            int k = i >> 5, nq = (i & 31) * 4;
            int gk = k0 + k;
            int bytes = (gk < K) ? 16 : 0;
            const float* src = (gk < K) ? (W + (size_t)gk * 128 + nq) : W;
            cp_async16(wsb + (unsigned)(buf * WBUF + k * WPAD + nq) * 4u, src, bytes);
        }
        cp_commit();
    };

    issue(0, 0);
    if (nk > 1) issue(1, 1);

    for (int t = 0; t < nk; t++) {
        if (t + 1 < nk) cp_wait1(); else cp_wait0();
        __syncthreads();
        if (t + 2 < nk) issue((t + 2) % 3, t + 2);

        const float* Ab = As + (t % 3) * ABUF;
        const unsigned* Wb = (const unsigned*)(Ws + (t % 3) * WBUF);
#pragma unroll
        for (int ks = 0; ks < 16; ks += 8) {
            unsigned b[8][2];
#pragma unroll
            for (int nt = 0; nt < 8; nt++) {
                int n = wn + nt * 8 + g;
                b[nt][0] = Wb[(ks + ct) * WPAD + n];       // pre-rounded: raw feed
                b[nt][1] = Wb[(ks + ct + 4) * WPAD + n];
            }
            unsigned a0 = f2tf32(Ab[(wm + g) * APAD + ks + ct]);
            unsigned a1 = f2tf32(Ab[(wm + g + 8) * APAD + ks + ct]);
            unsigned a2 = f2tf32(Ab[(wm + g) * APAD + ks + ct + 4]);
            unsigned a3 = f2tf32(Ab[(wm + g + 8) * APAD + ks + ct + 4]);
#pragma unroll
            for (int nt = 0; nt < 8; nt++) {
                asm volatile(
                    "mma.sync.aligned.m16n8k8.row.col.f32.tf32.tf32.f32 "
                    "{%0,%1,%2,%3}, {%4,%5,%6,%7}, {%8,%9}, {%0,%1,%2,%3};"
                    : "+f"(c[nt][0]), "+f"(c[nt][1]), "+f"(c[nt][2]), "+f"(c[nt][3])
                    : "r"(a0), "r"(a1), "r"(a2), "r"(a3),
                      "r"(b[nt][0]), "r"(b[nt][1]));
            }
        }
        __syncthreads();
    }

    // epilogue: store C (+bias) and optionally fused attention scores
    const int NH2 = (NH == 4) ? 2 : 1;
    float ps[2][2], pd[2][2];
    if (NH > 0) {
#pragma unroll
        for (int a = 0; a < 2; a++)
#pragma unroll
            for (int d = 0; d < 2; d++) { ps[a][d] = 0.f; pd[a][d] = 0.f; }
    }
    int r0 = bm + wm + g, r1 = r0 + 8;
#pragma unroll
    for (int nt = 0; nt < 8; nt++) {
        int col = wn + nt * 8 + 2 * ct;
        float b0 = bias ? bias[col] : 0.f;
        float b1 = bias ? bias[col + 1] : 0.f;
        float v00 = c[nt][0] + b0, v01 = c[nt][1] + b1;
        float v10 = c[nt][2] + b0, v11 = c[nt][3] + b1;
        if (r0 < M) *(float2*)(C + (size_t)r0 * 128 + col) = make_float2(v00, v01);
        if (r1 < M) *(float2*)(C + (size_t)r1 * 128 + col) = make_float2(v10, v11);
        if (NH > 0) {
            float a0s = asrc[col], a1s = asrc[col + 1];
            float a0d = adst[col], a1d = adst[col + 1];
            int h2 = (NH == 4) ? (nt >> 2) : 0;
            ps[0][h2] += v00 * a0s + v01 * a1s;
            ps[1][h2] += v10 * a0s + v11 * a1s;
            pd[0][h2] += v00 * a0d + v01 * a1d;
            pd[1][h2] += v10 * a0d + v11 * a1d;
        }
    }
    if (NH > 0) {
#pragma unroll
        for (int rh = 0; rh < 2; rh++)
#pragma unroll
            for (int h2 = 0; h2 < NH2; h2++) {
                float s = ps[rh][h2], d = pd[rh][h2];
                s += __shfl_xor_sync(0xffffffffu, s, 1);
                s += __shfl_xor_sync(0xffffffffu, s, 2);
                d += __shfl_xor_sync(0xffffffffu, d, 1);
                d += __shfl_xor_sync(0xffffffffu, d, 2);
                ps[rh][h2] = s; pd[rh][h2] = d;
            }
        if (ct == 0) {
            int headbase = (wn * NH) >> 7;
#pragma unroll
            for (int rh = 0; rh < 2; rh++) {
                int row = (rh == 0) ? r0 : r1;
                if (row < M) {
#pragma unroll
                    for (int h2 = 0; h2 < NH2; h2++) {
                        int head = headbase + h2;
                        ssrc[(size_t)row * NH + head] = ps[rh][h2];
                        sdst[(size_t)row * NH + head] = pd[rh][h2];
                    }
                }
            }
        }
    }
}

// ---------------- SIMT GEMM for tiny-K projections (+optional fused LN+ReLU) --------
__global__ __launch_bounds__(256, 2)
void gemm_tile(const float* __restrict__ A, const float* __restrict__ W,
               const float* __restrict__ bias, float* __restrict__ C,
               int M, int K,
               const float* __restrict__ gamma, const float* __restrict__ beta) {
    __shared__ float As[16 * 132];
    __shared__ float Ws[16 * 132];
    const int bm  = blockIdx.x * 128;
    const int tid = threadIdx.x;
    const int tr  = (tid >> 4) * 8;
    const int tc  = (tid & 15) * 8;
    float acc[8][8];
#pragma unroll
    for (int x = 0; x < 8; x++)
#pragma unroll
        for (int y = 0; y < 8; y++) acc[x][y] = 0.f;

    for (int k0 = 0; k0 < K; k0 += 16) {
        for (int i = tid; i < 128 * 16; i += 256) {
            int m = i >> 4, kk = i & 15;
            int gr = bm + m, gk = k0 + kk;
            As[kk * 132 + m] = (gr < M && gk < K) ? A[(size_t)gr * K + gk] : 0.f;
        }
        for (int i = tid; i < 16 * 128; i += 256) {
            int kk = i >> 7, n = i & 127;
            int gk = k0 + kk;
            Ws[kk * 132 + n] = (gk < K) ? W[gk * 128 + n] : 0.f;
        }
        __syncthreads();
#pragma unroll
        for (int kk = 0; kk < 16; kk++) {
            float a[8], w[8];
#pragma unroll
            for (int x = 0; x < 8; x++) a[x] = As[kk * 132 + tr + x];
#pragma unroll
            for (int y = 0; y < 8; y++) w[y] = Ws[kk * 132 + tc + y];
#pragma unroll
            for (int x = 0; x < 8; x++)
#pragma unroll
                for (int y = 0; y < 8; y++) acc[x][y] += a[x] * w[y];
        }
        __syncthreads();
    }

    if (gamma) {
#pragma unroll
        for (int x = 0; x < 8; x++) {
            int gr = bm + tr + x;
            float vv[8]; float sum = 0.f;
#pragma unroll
            for (int y = 0; y < 8; y++) {
                vv[y] = acc[x][y] + (bias ? bias[tc + y] : 0.f);
                sum += vv[y];
            }
#pragma unroll
            for (int k = 1; k < 16; k <<= 1) sum += __shfl_xor_sync(0xffffffffu, sum, k, 16);
            float mean = sum * (1.f / 128.f);
            float sq = 0.f;
#pragma unroll
            for (int y = 0; y < 8; y++) { float d = vv[y] - mean; sq += d * d; }
#pragma unroll
            for (int k = 1; k < 16; k <<= 1) sq += __shfl_xor_sync(0xffffffffu, sq, k, 16);
            float rstd = rsqrtf(sq * (1.f / 128.f) + 1e-5f);
            if (gr < M) {
#pragma unroll
                for (int y = 0; y < 8; y++) {
                    float yv = (vv[y] - mean) * rstd * gamma[tc + y] + beta[tc + y];
                    C[(size_t)gr * 128 + tc + y] = fmaxf(yv, 0.f);
                }
            }
        }
    } else {
#pragma unroll
        for (int x = 0; x < 8; x++) {
            int gr = bm + tr + x;
            if (gr < M) {
#pragma unroll
                for (int y = 0; y < 8; y++) {
                    float v = acc[x][y];
                    if (bias) v += bias[tc + y];
                    C[(size_t)gr * 128 + tc + y] = v;
                }
            }
        }
    }
}

// ---------------- fused single-pass GAT aggregation ----------------
template <int NH, int HD, bool HAS_E>
__global__ void gat_fused(const int* __restrict__ rowptr, const int* __restrict__ psrc,
                          const float* __restrict__ pea,
                          const float* __restrict__ eW, const float* __restrict__ ae,
                          const float* __restrict__ ssrc, const float* __restrict__ sdst,
                          const float* __restrict__ z, const float* __restrict__ bias,
                          float* __restrict__ h, int n) {
    __shared__ float ce_s[NH];
    if (HAS_E && threadIdx.x < NH) {
        int hh = threadIdx.x;
        float s = 0.f;
#pragma unroll
        for (int d = 0; d < HD; d++) s += eW[hh * HD + d] * ae[hh * HD + d];
        ce_s[hh] = s;
    }
    if (HAS_E) __syncthreads();

    int node = blockIdx.x * 8 + (threadIdx.x >> 5);
    if (node >= n) return;
    int lane = threadIdx.x & 31;
    int c = lane * 4;
    int head = c / HD;

    float sd = sdst[(size_t)node * NH + head];
    float ce = HAS_E ? ce_s[head] : 0.f;

    float4 acc = make_float4(0.f, 0.f, 0.f, 0.f);
    float den = 0.f;
    int lo = rowptr[node], hi = rowptr[node + 1];
    for (int j = lo; j < hi; j++) {
        int s = psrc[j];
        float sc = ssrc[(size_t)s * NH + head] + sd;
        if (HAS_E) sc += pea[j] * ce;
        sc = sc > 0.f ? sc : 0.2f * sc;
        float ex = __expf(sc);
        den += ex;
        float4 zv = *(const float4*)(z + (size_t)s * HH + c);
        acc.x += ex * zv.x; acc.y += ex * zv.y;
        acc.z += ex * zv.z; acc.w += ex * zv.w;
    }
    float inv = 1.f / fmaxf(den, 1e-16f);
    float4 hv = *(const float4*)(h + (size_t)node * HH + c);
    float4 bv = *(const float4*)(bias + c);
    acc.x = hv.x + bv.x + acc.x * inv;
    acc.y = hv.y + bv.y + acc.y * inv;
    acc.z = hv.z + bv.z + acc.z * inv;
    acc.w = hv.w + bv.w + acc.w * inv;
    acc.x = acc.x > 0.f ? acc.x : __expf(acc.x) - 1.f;
    acc.y = acc.y > 0.f ? acc.y : __expf(acc.y) - 1.f;
    acc.z = acc.z > 0.f ? acc.z : __expf(acc.z) - 1.f;
    acc.w = acc.w > 0.f ? acc.w : __expf(acc.w) - 1.f;
    *(float4*)(h + (size_t)node * HH + c) = acc;
}

// ---------------- mean pooling via binary search on sorted node_batch ----------------
__global__ void pool_k(const float* __restrict__ h, const int* __restrict__ nb,
                       float* __restrict__ emb) {
    int b = blockIdx.x, t = threadIdx.x;
    int lo = 0, hi = TN;
    while (lo < hi) { int mid = (lo + hi) >> 1; if (nb[mid] < b) lo = mid + 1; else hi = mid; }
    int start = lo;
    hi = TN;
    while (lo < hi) { int mid = (lo + hi) >> 1; if (nb[mid] < b + 1) lo = mid + 1; else hi = mid; }
    int end = lo;
    float s = 0.f;
    for (int i = start; i < end; i++) s += h[(size_t)i * HH + t];
    emb[(size_t)b * HH + t] = s / fmaxf((float)(end - start), 1.f);
}

// ---------------- concat [emb | gf[cid]] into padded rows ----------------
__global__ void concat_k(const float* __restrict__ emb, const float* __restrict__ gf,
                         const int* __restrict__ cid, float* __restrict__ cat) {
    int i = blockIdx.x * blockDim.x + threadIdx.x;
    if (i >= BB * (HH + FGN)) return;
    int b = i / (HH + FGN), j = i % (HH + FGN);
    cat[(size_t)b * CATP + j] = (j < HH) ? emb[(size_t)b * HH + j]
                                         : gf[(size_t)cid[b] * FGN + (j - HH)];
}

// ---------------- LayerNorm(128) + ReLU ----------------
__global__ void ln_relu_k(const float* __restrict__ X, const float* __restrict__ g,
                          const float* __restrict__ be, float* __restrict__ Y) {
    int row = blockIdx.x, t = threadIdx.x;
    float v = X[(size_t)row * HH + t];
    __shared__ float red[HH];
    red[t] = v; __syncthreads();
    for (int s = 64; s > 0; s >>= 1) { if (t < s) red[t] += red[t + s]; __syncthreads(); }
    float mean = red[0] / 128.f;
    __syncthreads();
    float dv = v - mean;
    red[t] = dv * dv; __syncthreads();
    for (int s = 64; s > 0; s >>= 1) { if (t < s) red[t] += red[t + s]; __syncthreads(); }
    float var = red[0] / 128.f;
    float y = dv * rsqrtf(var + 1e-5f) * g[t] + be[t];
    Y[(size_t)row * HH + t] = fmaxf(y, 0.f);
}

// ---------------- scatter fused batch embeddings into gx ----------------
__global__ void scatfused_k(float* __restrict__ gx, const float* __restrict__ fused,
                            const int* __restrict__ cid) {
    int i = blockIdx.x * blockDim.x + threadIdx.x;
    if (i >= BB * HH) return;
    int b = i >> 7;
    gx[(size_t)cid[b] * HH + (i & 127)] = fused[i];
}

// ---------------- classifier: 8 contracts per block ----------------
__global__ __launch_bounds__(256)
void classifier_k(const float* __restrict__ gx, const int* __restrict__ cid,
                  const float* __restrict__ W1, const float* __restrict__ b1,
                  const float* __restrict__ W2, const float* __restrict__ b2,
                  float* __restrict__ out) {
    __shared__ float row[4][HH];
    __shared__ float hc[4][HCN];
    int tid = threadIdx.x;
    int grp = tid >> 6, t = tid & 63;
    for (int it = 0; it < 2; it++) {
        int b = blockIdx.x * 8 + it * 4 + grp;
        __syncthreads();
        const float* srcp = gx + (size_t)cid[b] * HH;
        row[grp][t] = srcp[t];
        row[grp][t + 64] = srcp[t + 64];
        __syncthreads();
        float s = b1[t];
#pragma unroll
        for (int k = 0; k < HH; k++) s += row[grp][k] * W1[k * HCN + t];
        hc[grp][t] = fmaxf(s, 0.f);
        __syncthreads();
        if (t < CC) {
            float s2 = b2[t];
#pragma unroll
            for (int k = 0; k < HCN; k++) s2 += hc[grp][k] * W2[k * CC + t];
            out[b * CC + t] = s2;
        }
    }
}

// ---------------- launch ----------------
extern "C" void kernel_launch(void* const* d_in, const int* in_sizes, int n_in,
                              void* d_out, int out_size) {
    const float* x_local    = (const float*)d_in[0];
    const float* eattr      = (const float*)d_in[1];
    const float* gfeat      = (const float*)d_in[2];
    const float* loc_in_W   = (const float*)d_in[3];
    const float* loc_in_b   = (const float*)d_in[4];
    const float* loc_W      = (const float*)d_in[5];
    const float* loc_asrc   = (const float*)d_in[6];
    const float* loc_adst   = (const float*)d_in[7];
    const float* loc_eW     = (const float*)d_in[8];
    const float* loc_ae     = (const float*)d_in[9];
    const float* loc_b      = (const float*)d_in[10];
    const float* fp_W       = (const float*)d_in[11];
    const float* fp_b       = (const float*)d_in[12];
    const float* fp_g       = (const float*)d_in[13];
    const float* fp_beta    = (const float*)d_in[14];
    const float* gp_W       = (const float*)d_in[15];
    const float* gp_b       = (const float*)d_in[16];
    const float* gp_g       = (const float*)d_in[17];
    const float* gp_beta    = (const float*)d_in[18];
    const float* glob_W     = (const float*)d_in[19];
    const float* glob_asrc  = (const float*)d_in[20];
    const float* glob_adst  = (const float*)d_in[21];
    const float* glob_b     = (const float*)d_in[22];
    const float* cls_W1     = (const float*)d_in[23];
    const float* cls_b1     = (const float*)d_in[24];
    const float* cls_W2     = (const float*)d_in[25];
    const float* cls_b2     = (const float*)d_in[26];
    const int*   eil        = (const int*)d_in[27];
    const int*   node_batch = (const int*)d_in[28];
    const int*   cid        = (const int*)d_in[29];
    const int*   gei        = (const int*)d_in[30];

    const int* lsrc = eil;
    const int* ldst = eil + ELN;
    const int* gsrc = gei;
    const int* gdst = gei + EGN;

    float *p_h, *p_z, *p_ssrc, *p_sdst;
    float *p_emb, *p_cat, *p_tmp, *p_fused, *p_gx, *p_gz, *p_pea, *p_wtf;
    int *p_deg, *p_rowptr, *p_fill, *p_psrc, *p_bsum;
    int *p_gdeg, *p_growptr, *p_gfill, *p_gpsrc, *p_gbsum;
    cudaGetSymbolAddress((void**)&p_h, g_h);
    cudaGetSymbolAddress((void**)&p_z, g_z);
    cudaGetSymbolAddress((void**)&p_ssrc, g_ssrc);
    cudaGetSymbolAddress((void**)&p_sdst, g_sdst);
    cudaGetSymbolAddress((void**)&p_emb, g_emb);
    cudaGetSymbolAddress((void**)&p_cat, g_cat);
    cudaGetSymbolAddress((void**)&p_tmp, g_tmp);
    cudaGetSymbolAddress((void**)&p_fused, g_fused);
    cudaGetSymbolAddress((void**)&p_gx, g_gx);
    cudaGetSymbolAddress((void**)&p_gz, g_gz);
    cudaGetSymbolAddress((void**)&p_pea, g_pea);
    cudaGetSymbolAddress((void**)&p_wtf, g_wtf);
    cudaGetSymbolAddress((void**)&p_deg, g_deg);
    cudaGetSymbolAddress((void**)&p_rowptr, g_rowptr);
    cudaGetSymbolAddress((void**)&p_fill, g_fill);
    cudaGetSymbolAddress((void**)&p_psrc, g_psrc);
    cudaGetSymbolAddress((void**)&p_bsum, g_bsum);
    cudaGetSymbolAddress((void**)&p_gdeg, g_gdeg);
    cudaGetSymbolAddress((void**)&p_growptr, g_growptr);
    cudaGetSymbolAddress((void**)&p_gfill, g_gfill);
    cudaGetSymbolAddress((void**)&p_gpsrc, g_gpsrc);
    cudaGetSymbolAddress((void**)&p_gbsum, g_gbsum);

    // ---- weight pre-rounding + deg zeroing (one launch) ----
    wconv_k<<<CDIV(TN, 256), 256>>>(loc_W, fp_W, glob_W, p_wtf, p_deg, p_gdeg);

    // ---- input projection (K=4) ----
    gemm_tile<<<CDIV(TN, 128), 256>>>(x_local, loc_in_W, loc_in_b, p_h, TN, 4,
                                      nullptr, nullptr);

    // local CSR prefix (keeps gemm_mma in ncu capture slot)
    hist_k<<<CDIV(ELN, 256), 256>>>(ldst, p_deg, ELN);
    scan1_k<<<CDIV(TN, 1024), 256>>>(p_deg, p_bsum, TN);

    // ---- local layer 0 GEMM (+fused scores) — profiling target ----
    gemm_mma<4><<<CDIV(TN, 64), 256>>>(p_h, p_wtf + WT_LOC0, nullptr, p_z, TN, HH, HH,
                                       loc_asrc, loc_adst, p_ssrc, p_sdst);

    scan2_k<<<1, 32>>>(p_bsum, CDIV(TN, 1024), p_rowptr, TN, ELN);
    scan3_k<<<CDIV(TN, 1024), 256>>>(p_deg, p_bsum, p_rowptr, p_fill, TN);
    scatedge_k<<<CDIV(ELN, 256), 256>>>(lsrc, ldst, eattr, p_fill, p_psrc, p_pea, ELN);

    // global CSR
    hist_k<<<CDIV(EGN, 256), 256>>>(gdst, p_gdeg, EGN);
    scan1_k<<<CDIV(NNODE, 1024), 256>>>(p_gdeg, p_gbsum, NNODE);
    scan2_k<<<1, 32>>>(p_gbsum, CDIV(NNODE, 1024), p_growptr, NNODE, EGN);
    scan3_k<<<CDIV(NNODE, 1024), 256>>>(p_gdeg, p_gbsum, p_growptr, p_gfill, NNODE);
    scatedge_k<<<CDIV(EGN, 256), 256>>>(gsrc, gdst, (const float*)nullptr, p_gfill,
                                        p_gpsrc, (float*)nullptr, EGN);

    // ---- local layer 0 aggregate ----
    gat_fused<4, 32, true><<<CDIV(TN, 8), 256>>>(p_rowptr, p_psrc, p_pea,
                                                 loc_eW, loc_ae,
                                                 p_ssrc, p_sdst, p_z, loc_b, p_h, TN);
    // ---- local layer 1 ----
    gemm_mma<4><<<CDIV(TN, 64), 256>>>(p_h, p_wtf + WT_LOC1, nullptr, p_z, TN, HH, HH,
                                       loc_asrc + HH, loc_adst + HH, p_ssrc, p_sdst);
    gat_fused<4, 32, true><<<CDIV(TN, 8), 256>>>(p_rowptr, p_psrc, p_pea,
                                                 loc_eW + HH, loc_ae + HH,
                                                 p_ssrc, p_sdst, p_z, loc_b + HH, p_h, TN);

    // ---- contract mean pooling ----
    pool_k<<<BB, 128>>>(p_h, node_batch, p_emb);

    // ---- fused MLP (padded-lda MMA GEMM) ----
    concat_k<<<CDIV(BB * (HH + FGN), 256), 256>>>(p_emb, gfeat, cid, p_cat);
    gemm_mma<0><<<CDIV(BB, 64), 256>>>(p_cat, p_wtf + WT_FP, fp_b, p_tmp, BB,
                                       HH + FGN, CATP,
                                       nullptr, nullptr, nullptr, nullptr);
    ln_relu_k<<<BB, HH>>>(p_tmp, fp_g, fp_beta, p_fused);

    // ---- global projection (fused LN+ReLU) + scatter ----
    gemm_tile<<<CDIV(NNODE, 128), 256>>>(gfeat, gp_W, gp_b, p_gx, NNODE, FGN,
                                         gp_g, gp_beta);
    scatfused_k<<<CDIV(BB * HH, 256), 256>>>(p_gx, p_fused, cid);

    // ---- 2x global GATConv ----
    for (int l = 0; l < 2; l++) {
        gemm_mma<2><<<CDIV(NNODE, 64), 256>>>(p_gx,
                                              p_wtf + (l == 0 ? WT_G0 : WT_G1), nullptr,
                                              p_gz, NNODE, HH, HH,
                                              glob_asrc + l * HH, glob_adst + l * HH,
                                              p_ssrc, p_sdst);
        gat_fused<2, 64, false><<<CDIV(NNODE, 8), 256>>>(p_growptr, p_gpsrc, (float*)nullptr,
                                                         (float*)nullptr, (float*)nullptr,
                                                         p_ssrc, p_sdst, p_gz,
                                                         glob_b + l * HH, p_gx, NNODE);
    }

    // ---- classifier ----
    classifier_k<<<CDIV(BB, 8), 256>>>(p_gx, cid, cls_W1, cls_b1, cls_W2, cls_b2,
                                       (float*)d_out);
}

// round 11
// speedup vs baseline: 1.4054x; 1.0466x over previous
#include <cuda_runtime.h>
#include <math.h>

// ---------------- problem constants ----------------
#define TN    131072     // local tx nodes
#define ELN   524288     // local edges
#define NNODE 50000      // global contract nodes
#define EGN   400000     // global edges
#define BB    8192       // batch of contracts
#define HH    128        // hidden dim
#define FGN   7          // global feat dim
#define HCN   64         // classifier hidden
#define CC    2          // classes
#define CATP  144        // padded concat row stride (16B multiple)

#define CDIV(a,b) (((a)+(b)-1)/(b))
#define NBL  CDIV(TN, 1024)      // 128 scan blocks local
#define NBG  CDIV(NNODE, 1024)   // 49 scan blocks global

// pre-rounded weight buffer offsets (floats)
#define WT_LOC0 0
#define WT_LOC1 16384
#define WT_FP   32768
#define WT_G0   50048
#define WT_G1   66432
#define WT_TOT  82816

// ---------------- scratch (device globals) ----------------
__device__ float g_h   [TN*HH];
__device__ float g_z   [TN*HH];
__device__ float g_ssrc[TN*4];
__device__ float g_sdst[TN*4];
__device__ float g_cat [BB*CATP];
__device__ float g_tmp [BB*HH];
__device__ float g_gx  [NNODE*HH];
__device__ float g_gz  [NNODE*HH];
__device__ float g_wtf [WT_TOT];
// CSR scratch
__device__ int   g_deg   [TN];
__device__ int   g_rowptr[TN+1];
__device__ int   g_fill  [TN];
__device__ int   g_psrc  [ELN];
__device__ float g_pea   [ELN];
__device__ int   g_bsum  [256];
__device__ int   g_gdeg   [NNODE];
__device__ int   g_growptr[NNODE+1];
__device__ int   g_gfill  [NNODE];
__device__ int   g_gpsrc  [EGN];
__device__ int   g_gbsum  [256];

// ---------------- helpers ----------------
__device__ __forceinline__ unsigned f2tf32(float f) {
    unsigned r;
    asm("cvt.rna.tf32.f32 %0, %1;" : "=r"(r) : "f"(f));
    return r;
}
__device__ __forceinline__ void cp_async16(unsigned dst, const void* src, int bytes) {
    asm volatile("cp.async.cg.shared.global [%0], [%1], 16, %2;"
                 :: "r"(dst), "l"(src), "r"(bytes) : "memory");
}
__device__ __forceinline__ void cp_commit() {
    asm volatile("cp.async.commit_group;" ::: "memory");
}
__device__ __forceinline__ void cp_wait1() {
    asm volatile("cp.async.wait_group 1;" ::: "memory");
}
__device__ __forceinline__ void cp_wait0() {
    asm volatile("cp.async.wait_group 0;" ::: "memory");
}

// ---------------- weight pre-rounding + deg zeroing ----------
__global__ void wconv_k(const float* __restrict__ locW, const float* __restrict__ fpW,
                        const float* __restrict__ globW, float* __restrict__ wt,
                        int* __restrict__ deg, int* __restrict__ gdeg) {
    int i = blockIdx.x * blockDim.x + threadIdx.x;
    if (i < 32768)       wt[i] = __uint_as_float(f2tf32(locW[i]));
    else if (i < 50048)  wt[i] = __uint_as_float(f2tf32(fpW[i - 32768]));
    else if (i < WT_TOT) wt[i] = __uint_as_float(f2tf32(globW[i - 50048]));
    if (i < TN)    deg[i]  = 0;
    if (i < NNODE) gdeg[i] = 0;
}

// ================= CSR construction (both graphs fused) =================
__global__ void hist2_k(const int* __restrict__ ldst, const int* __restrict__ gdst,
                        int* __restrict__ deg, int* __restrict__ gdeg) {
    int e = blockIdx.x * blockDim.x + threadIdx.x;
    if (e < ELN) atomicAdd(&deg[ldst[e]], 1);
    else if (e < ELN + EGN) atomicAdd(&gdeg[gdst[e - ELN]], 1);
}
__global__ void scan1b_k(const int* __restrict__ deg, const int* __restrict__ gdeg,
                         int* __restrict__ bsum, int* __restrict__ gbsum) {
    __shared__ int s[256];
    int t = threadIdx.x;
    bool loc = blockIdx.x < NBL;
    const int* d = loc ? deg : gdeg;
    int n = loc ? TN : NNODE;
    int base = (loc ? blockIdx.x : blockIdx.x - NBL) * 1024;
    int sum = 0;
#pragma unroll
    for (int i = 0; i < 4; i++) {
        int idx = base + t * 4 + i;
        if (idx < n) sum += d[idx];
    }
    s[t] = sum; __syncthreads();
    for (int o = 128; o > 0; o >>= 1) { if (t < o) s[t] += s[t + o]; __syncthreads(); }
    if (t == 0) (loc ? bsum : gbsum)[loc ? blockIdx.x : blockIdx.x - NBL] = s[0];
}
__global__ void scan2b_k(int* __restrict__ bsum, int* __restrict__ gbsum,
                         int* __restrict__ rowptr, int* __restrict__ growptr) {
    if (threadIdx.x == 0) {
        int acc = 0;
        for (int i = 0; i < NBL; i++) { int v = bsum[i]; bsum[i] = acc; acc += v; }
        rowptr[TN] = ELN;
    } else if (threadIdx.x == 1) {
        int acc = 0;
        for (int i = 0; i < NBG; i++) { int v = gbsum[i]; gbsum[i] = acc; acc += v; }
        growptr[NNODE] = EGN;
    }
}
__global__ void scan3b_k(const int* __restrict__ deg, const int* __restrict__ gdeg,
                         const int* __restrict__ bsum, const int* __restrict__ gbsum,
                         int* __restrict__ rowptr, int* __restrict__ growptr,
                         int* __restrict__ fill, int* __restrict__ gfill) {
    __shared__ int s[256];
    int t = threadIdx.x;
    bool loc = blockIdx.x < NBL;
    const int* d = loc ? deg : gdeg;
    const int* bs = loc ? bsum : gbsum;
    int* rp = loc ? rowptr : growptr;
    int* fl = loc ? fill : gfill;
    int n = loc ? TN : NNODE;
    int bid = loc ? blockIdx.x : blockIdx.x - NBL;
    int base = bid * 1024;
    int v[4]; int sum = 0;
#pragma unroll
    for (int i = 0; i < 4; i++) {
        int idx = base + t * 4 + i;
        v[i] = (idx < n) ? d[idx] : 0;
        sum += v[i];
    }
    s[t] = sum; __syncthreads();
    for (int o = 1; o < 256; o <<= 1) {
        int x = (t >= o) ? s[t - o] : 0;
        __syncthreads();
        s[t] += x;
        __syncthreads();
    }
    int excl = ((t == 0) ? 0 : s[t - 1]) + bs[bid];
#pragma unroll
    for (int i = 0; i < 4; i++) {
        int idx = base + t * 4 + i;
        if (idx < n) { rp[idx] = excl; fl[idx] = excl; }
        excl += v[i];
    }
}
__global__ void scatedge2_k(const int* __restrict__ lsrc, const int* __restrict__ ldst,
                            const int* __restrict__ gsrc, const int* __restrict__ gdst,
                            const float* __restrict__ eattr,
                            int* __restrict__ fill, int* __restrict__ gfill,
                            int* __restrict__ psrc, float* __restrict__ pea,
                            int* __restrict__ gpsrc) {
    int e = blockIdx.x * blockDim.x + threadIdx.x;
    if (e < ELN) {
        int p = atomicAdd(&fill[ldst[e]], 1);
        psrc[p] = lsrc[e];
        pea[p] = eattr[e];
    } else if (e < ELN + EGN) {
        int ee = e - ELN;
        int p = atomicAdd(&gfill[gdst[ee]], 1);
        gpsrc[p] = gsrc[ee];
    }
}

// ================= tf32 MMA GEMM, cp.async 3-stage pipeline =================
#define APAD 20
#define WPAD 136
#define ABUF (64 * APAD)
#define WBUF (16 * WPAD)
template <int NH>
__global__ __launch_bounds__(256, 3)
void gemm_mma(const float* __restrict__ A, const float* __restrict__ W,
              const float* __restrict__ bias, float* __restrict__ C,
              int M, int K, int lda,
              const float* __restrict__ asrc, const float* __restrict__ adst,
              float* __restrict__ ssrc, float* __restrict__ sdst) {
    __shared__ __align__(16) float As[3 * ABUF];
    __shared__ __align__(16) float Ws[3 * WBUF];
    const int tid  = threadIdx.x;
    const int warp = tid >> 5, lane = tid & 31;
    const int bm   = blockIdx.x * 64;
    const int wm   = (warp >> 1) * 16;
    const int wn   = (warp & 1) * 64;
    const int g    = lane >> 2;
    const int ct   = lane & 3;
    const int nk   = (K + 15) / 16;

    const unsigned asb = (unsigned)__cvta_generic_to_shared(As);
    const unsigned wsb = (unsigned)__cvta_generic_to_shared(Ws);

    float c[8][4];
#pragma unroll
    for (int nt = 0; nt < 8; nt++)
#pragma unroll
        for (int r = 0; r < 4; r++) c[nt][r] = 0.f;

    auto issue = [&](int buf, int t) {
        int k0 = t * 16;
        {
            int m = tid >> 2, kq = (tid & 3) * 4;
            int gr = bm + m, gk = k0 + kq;
            int bytes = 0;
            const float* src = A;
            if (gr < M && gk < K) {
                int rem = K - gk;
                bytes = rem >= 4 ? 16 : rem * 4;
                src = A + (size_t)gr * lda + gk;
            }
            cp_async16(asb + (unsigned)(buf * ABUF + m * APAD + kq) * 4u, src, bytes);
        }
#pragma unroll
        for (int i = tid; i < 512; i += 256) {
            int k = i >> 5, nq = (i & 31) * 4;
            int gk = k0 + k;
            int bytes = (gk < K) ? 16 : 0;
            const float* src = (gk < K) ? (W + (size_t)gk * 128 + nq) : W;
            cp_async16(wsb + (unsigned)(buf * WBUF + k * WPAD + nq) * 4u, src, bytes);
        }
        cp_commit();
    };

    issue(0, 0);
    if (nk > 1) issue(1, 1);

    for (int t = 0; t < nk; t++) {
        if (t + 1 < nk) cp_wait1(); else cp_wait0();
        __syncthreads();
        if (t + 2 < nk) issue((t + 2) % 3, t + 2);

        const float* Ab = As + (t % 3) * ABUF;
        const unsigned* Wb = (const unsigned*)(Ws + (t % 3) * WBUF);
#pragma unroll
        for (int ks = 0; ks < 16; ks += 8) {
            unsigned b[8][2];
#pragma unroll
            for (int nt = 0; nt < 8; nt++) {
                int n = wn + nt * 8 + g;
                b[nt][0] = Wb[(ks + ct) * WPAD + n];
                b[nt][1] = Wb[(ks + ct + 4) * WPAD + n];
            }
            unsigned a0 = f2tf32(Ab[(wm + g) * APAD + ks + ct]);
            unsigned a1 = f2tf32(Ab[(wm + g + 8) * APAD + ks + ct]);
            unsigned a2 = f2tf32(Ab[(wm + g) * APAD + ks + ct + 4]);
            unsigned a3 = f2tf32(Ab[(wm + g + 8) * APAD + ks + ct + 4]);
#pragma unroll
            for (int nt = 0; nt < 8; nt++) {
                asm volatile(
                    "mma.sync.aligned.m16n8k8.row.col.f32.tf32.tf32.f32 "
                    "{%0,%1,%2,%3}, {%4,%5,%6,%7}, {%8,%9}, {%0,%1,%2,%3};"
                    : "+f"(c[nt][0]), "+f"(c[nt][1]), "+f"(c[nt][2]), "+f"(c[nt][3])
                    : "r"(a0), "r"(a1), "r"(a2), "r"(a3),
                      "r"(b[nt][0]), "r"(b[nt][1]));
            }
        }
        __syncthreads();
    }

    const int NH2 = (NH == 4) ? 2 : 1;
    float ps[2][2], pd[2][2];
    if (NH > 0) {
#pragma unroll
        for (int a = 0; a < 2; a++)
#pragma unroll
            for (int d = 0; d < 2; d++) { ps[a][d] = 0.f; pd[a][d] = 0.f; }
    }
    int r0 = bm + wm + g, r1 = r0 + 8;
#pragma unroll
    for (int nt = 0; nt < 8; nt++) {
        int col = wn + nt * 8 + 2 * ct;
        float b0 = bias ? bias[col] : 0.f;
        float b1 = bias ? bias[col + 1] : 0.f;
        float v00 = c[nt][0] + b0, v01 = c[nt][1] + b1;
        float v10 = c[nt][2] + b0, v11 = c[nt][3] + b1;
        if (r0 < M) *(float2*)(C + (size_t)r0 * 128 + col) = make_float2(v00, v01);
        if (r1 < M) *(float2*)(C + (size_t)r1 * 128 + col) = make_float2(v10, v11);
        if (NH > 0) {
            float a0s = asrc[col], a1s = asrc[col + 1];
            float a0d = adst[col], a1d = adst[col + 1];
            int h2 = (NH == 4) ? (nt >> 2) : 0;
            ps[0][h2] += v00 * a0s + v01 * a1s;
            ps[1][h2] += v10 * a0s + v11 * a1s;
            pd[0][h2] += v00 * a0d + v01 * a1d;
            pd[1][h2] += v10 * a0d + v11 * a1d;
        }
    }
    if (NH > 0) {
#pragma unroll
        for (int rh = 0; rh < 2; rh++)
#pragma unroll
            for (int h2 = 0; h2 < NH2; h2++) {
                float s = ps[rh][h2], d = pd[rh][h2];
                s += __shfl_xor_sync(0xffffffffu, s, 1);
                s += __shfl_xor_sync(0xffffffffu, s, 2);
                d += __shfl_xor_sync(0xffffffffu, d, 1);
                d += __shfl_xor_sync(0xffffffffu, d, 2);
                ps[rh][h2] = s; pd[rh][h2] = d;
            }
        if (ct == 0) {
            int headbase = (wn * NH) >> 7;
#pragma unroll
            for (int rh = 0; rh < 2; rh++) {
                int row = (rh == 0) ? r0 : r1;
                if (row < M) {
#pragma unroll
                    for (int h2 = 0; h2 < NH2; h2++) {
                        int head = headbase + h2;
                        ssrc[(size_t)row * NH + head] = ps[rh][h2];
                        sdst[(size_t)row * NH + head] = pd[rh][h2];
                    }
                }
            }
        }
    }
}

// ---------------- SIMT GEMM for tiny-K projections (+optional fused LN+ReLU) --------
__global__ __launch_bounds__(256, 2)
void gemm_tile(const float* __restrict__ A, const float* __restrict__ W,
               const float* __restrict__ bias, float* __restrict__ C,
               int M, int K,
               const float* __restrict__ gamma, const float* __restrict__ beta) {
    __shared__ float As[16 * 132];
    __shared__ float Ws[16 * 132];
    const int bm  = blockIdx.x * 128;
    const int tid = threadIdx.x;
    const int tr  = (tid >> 4) * 8;
    const int tc  = (tid & 15) * 8;
    float acc[8][8];
#pragma unroll
    for (int x = 0; x < 8; x++)
#pragma unroll
        for (int y = 0; y < 8; y++) acc[x][y] = 0.f;

    for (int k0 = 0; k0 < K; k0 += 16) {
        for (int i = tid; i < 128 * 16; i += 256) {
            int m = i >> 4, kk = i & 15;
            int gr = bm + m, gk = k0 + kk;
            As[kk * 132 + m] = (gr < M && gk < K) ? A[(size_t)gr * K + gk] : 0.f;
        }
        for (int i = tid; i < 16 * 128; i += 256) {
            int kk = i >> 7, n = i & 127;
            int gk = k0 + kk;
            Ws[kk * 132 + n] = (gk < K) ? W[gk * 128 + n] : 0.f;
        }
        __syncthreads();
#pragma unroll
        for (int kk = 0; kk < 16; kk++) {
            float a[8], w[8];
#pragma unroll
            for (int x = 0; x < 8; x++) a[x] = As[kk * 132 + tr + x];
#pragma unroll
            for (int y = 0; y < 8; y++) w[y] = Ws[kk * 132 + tc + y];
#pragma unroll
            for (int x = 0; x < 8; x++)
#pragma unroll
                for (int y = 0; y < 8; y++) acc[x][y] += a[x] * w[y];
        }
        __syncthreads();
    }

    if (gamma) {
#pragma unroll
        for (int x = 0; x < 8; x++) {
            int gr = bm + tr + x;
            float vv[8]; float sum = 0.f;
#pragma unroll
            for (int y = 0; y < 8; y++) {
                vv[y] = acc[x][y] + (bias ? bias[tc + y] : 0.f);
                sum += vv[y];
            }
#pragma unroll
            for (int k = 1; k < 16; k <<= 1) sum += __shfl_xor_sync(0xffffffffu, sum, k, 16);
            float mean = sum * (1.f / 128.f);
            float sq = 0.f;
#pragma unroll
            for (int y = 0; y < 8; y++) { float d = vv[y] - mean; sq += d * d; }
#pragma unroll
            for (int k = 1; k < 16; k <<= 1) sq += __shfl_xor_sync(0xffffffffu, sq, k, 16);
            float rstd = rsqrtf(sq * (1.f / 128.f) + 1e-5f);
            if (gr < M) {
#pragma unroll
                for (int y = 0; y < 8; y++) {
                    float yv = (vv[y] - mean) * rstd * gamma[tc + y] + beta[tc + y];
                    C[(size_t)gr * 128 + tc + y] = fmaxf(yv, 0.f);
                }
            }
        }
    } else {
#pragma unroll
        for (int x = 0; x < 8; x++) {
            int gr = bm + tr + x;
            if (gr < M) {
#pragma unroll
                for (int y = 0; y < 8; y++) {
                    float v = acc[x][y];
                    if (bias) v += bias[tc + y];
                    C[(size_t)gr * 128 + tc + y] = v;
                }
            }
        }
    }
}

// ---------------- fused single-pass GAT aggregation ----------------
template <int NH, int HD, bool HAS_E>
__global__ void gat_fused(const int* __restrict__ rowptr, const int* __restrict__ psrc,
                          const float* __restrict__ pea,
                          const float* __restrict__ eW, const float* __restrict__ ae,
                          const float* __restrict__ ssrc, const float* __restrict__ sdst,
                          const float* __restrict__ z, const float* __restrict__ bias,
                          float* __restrict__ h, int n) {
    __shared__ float ce_s[NH];
    if (HAS_E && threadIdx.x < NH) {
        int hh = threadIdx.x;
        float s = 0.f;
#pragma unroll
        for (int d = 0; d < HD; d++) s += eW[hh * HD + d] * ae[hh * HD + d];
        ce_s[hh] = s;
    }
    if (HAS_E) __syncthreads();

    int node = blockIdx.x * 8 + (threadIdx.x >> 5);
    if (node >= n) return;
    int lane = threadIdx.x & 31;
    int c = lane * 4;
    int head = c / HD;

    float sd = sdst[(size_t)node * NH + head];
    float ce = HAS_E ? ce_s[head] : 0.f;

    float4 acc = make_float4(0.f, 0.f, 0.f, 0.f);
    float den = 0.f;
    int lo = rowptr[node], hi = rowptr[node + 1];
    for (int j = lo; j < hi; j++) {
        int s = psrc[j];
        float sc = ssrc[(size_t)s * NH + head] + sd;
        if (HAS_E) sc += pea[j] * ce;
        sc = sc > 0.f ? sc : 0.2f * sc;
        float ex = __expf(sc);
        den += ex;
        float4 zv = *(const float4*)(z + (size_t)s * HH + c);
        acc.x += ex * zv.x; acc.y += ex * zv.y;
        acc.z += ex * zv.z; acc.w += ex * zv.w;
    }
    float inv = 1.f / fmaxf(den, 1e-16f);
    float4 hv = *(const float4*)(h + (size_t)node * HH + c);
    float4 bv = *(const float4*)(bias + c);
    acc.x = hv.x + bv.x + acc.x * inv;
    acc.y = hv.y + bv.y + acc.y * inv;
    acc.z = hv.z + bv.z + acc.z * inv;
    acc.w = hv.w + bv.w + acc.w * inv;
    acc.x = acc.x > 0.f ? acc.x : __expf(acc.x) - 1.f;
    acc.y = acc.y > 0.f ? acc.y : __expf(acc.y) - 1.f;
    acc.z = acc.z > 0.f ? acc.z : __expf(acc.z) - 1.f;
    acc.w = acc.w > 0.f ? acc.w : __expf(acc.w) - 1.f;
    *(float4*)(h + (size_t)node * HH + c) = acc;
}

// ---------------- pooling -> padded cat rows (+ gfeat tail) ----------------
__global__ void pool_cat_k(const float* __restrict__ h, const int* __restrict__ nb,
                           const float* __restrict__ gf, const int* __restrict__ cid,
                           float* __restrict__ cat) {
    int b = blockIdx.x, t = threadIdx.x;
    int lo = 0, hi = TN;
    while (lo < hi) { int mid = (lo + hi) >> 1; if (nb[mid] < b) lo = mid + 1; else hi = mid; }
    int start = lo;
    hi = TN;
    while (lo < hi) { int mid = (lo + hi) >> 1; if (nb[mid] < b + 1) lo = mid + 1; else hi = mid; }
    int end = lo;
    float s = 0.f;
    for (int i = start; i < end; i++) s += h[(size_t)i * HH + t];
    cat[(size_t)b * CATP + t] = s / fmaxf((float)(end - start), 1.f);
    if (t < FGN)
        cat[(size_t)b * CATP + HH + t] = gf[(size_t)cid[b] * FGN + t];
}

// ---------------- LayerNorm(128) + ReLU, scattered to gx[cid] ----------------
__global__ void ln_relu_scat_k(const float* __restrict__ X, const float* __restrict__ g,
                               const float* __restrict__ be, const int* __restrict__ cid,
                               float* __restrict__ gx) {
    int row = blockIdx.x, t = threadIdx.x;
    float v = X[(size_t)row * HH + t];
    __shared__ float red[HH];
    red[t] = v; __syncthreads();
    for (int s = 64; s > 0; s >>= 1) { if (t < s) red[t] += red[t + s]; __syncthreads(); }
    float mean = red[0] / 128.f;
    __syncthreads();
    float dv = v - mean;
    red[t] = dv * dv; __syncthreads();
    for (int s = 64; s > 0; s >>= 1) { if (t < s) red[t] += red[t + s]; __syncthreads(); }
    float var = red[0] / 128.f;
    float y = dv * rsqrtf(var + 1e-5f) * g[t] + be[t];
    gx[(size_t)cid[row] * HH + t] = fmaxf(y, 0.f);
}

// ---------------- classifier: 8 contracts per block ----------------
__global__ __launch_bounds__(256)
void classifier_k(const float* __restrict__ gx, const int* __restrict__ cid,
                  const float* __restrict__ W1, const float* __restrict__ b1,
                  const float* __restrict__ W2, const float* __restrict__ b2,
                  float* __restrict__ out) {
    __shared__ float row[4][HH];
    __shared__ float hc[4][HCN];
    int tid = threadIdx.x;
    int grp = tid >> 6, t = tid & 63;
    for (int it = 0; it < 2; it++) {
        int b = blockIdx.x * 8 + it * 4 + grp;
        __syncthreads();
        const float* srcp = gx + (size_t)cid[b] * HH;
        row[grp][t] = srcp[t];
        row[grp][t + 64] = srcp[t + 64];
        __syncthreads();
        float s = b1[t];
#pragma unroll
        for (int k = 0; k < HH; k++) s += row[grp][k] * W1[k * HCN + t];
        hc[grp][t] = fmaxf(s, 0.f);
        __syncthreads();
        if (t < CC) {
            float s2 = b2[t];
#pragma unroll
            for (int k = 0; k < HCN; k++) s2 += hc[grp][k] * W2[k * CC + t];
            out[b * CC + t] = s2;
        }
    }
}

// ---------------- launch ----------------
extern "C" void kernel_launch(void* const* d_in, const int* in_sizes, int n_in,
                              void* d_out, int out_size) {
    const float* x_local    = (const float*)d_in[0];
    const float* eattr      = (const float*)d_in[1];
    const float* gfeat      = (const float*)d_in[2];
    const float* loc_in_W   = (const float*)d_in[3];
    const float* loc_in_b   = (const float*)d_in[4];
    const float* loc_W      = (const float*)d_in[5];
    const float* loc_asrc   = (const float*)d_in[6];
    const float* loc_adst   = (const float*)d_in[7];
    const float* loc_eW     = (const float*)d_in[8];
    const float* loc_ae     = (const float*)d_in[9];
    const float* loc_b      = (const float*)d_in[10];
    const float* fp_W       = (const float*)d_in[11];
    const float* fp_b       = (const float*)d_in[12];
    const float* fp_g       = (const float*)d_in[13];
    const float* fp_beta    = (const float*)d_in[14];
    const float* gp_W       = (const float*)d_in[15];
    const float* gp_b       = (const float*)d_in[16];
    const float* gp_g       = (const float*)d_in[17];
    const float* gp_beta    = (const float*)d_in[18];
    const float* glob_W     = (const float*)d_in[19];
    const float* glob_asrc  = (const float*)d_in[20];
    const float* glob_adst  = (const float*)d_in[21];
    const float* glob_b     = (const float*)d_in[22];
    const float* cls_W1     = (const float*)d_in[23];
    const float* cls_b1     = (const float*)d_in[24];
    const float* cls_W2     = (const float*)d_in[25];
    const float* cls_b2     = (const float*)d_in[26];
    const int*   eil        = (const int*)d_in[27];
    const int*   node_batch = (const int*)d_in[28];
    const int*   cid        = (const int*)d_in[29];
    const int*   gei        = (const int*)d_in[30];

    const int* lsrc = eil;
    const int* ldst = eil + ELN;
    const int* gsrc = gei;
    const int* gdst = gei + EGN;

    float *p_h, *p_z, *p_ssrc, *p_sdst;
    float *p_cat, *p_tmp, *p_gx, *p_gz, *p_pea, *p_wtf;
    int *p_deg, *p_rowptr, *p_fill, *p_psrc, *p_bsum;
    int *p_gdeg, *p_growptr, *p_gfill, *p_gpsrc, *p_gbsum;
    cudaGetSymbolAddress((void**)&p_h, g_h);
    cudaGetSymbolAddress((void**)&p_z, g_z);
    cudaGetSymbolAddress((void**)&p_ssrc, g_ssrc);
    cudaGetSymbolAddress((void**)&p_sdst, g_sdst);
    cudaGetSymbolAddress((void**)&p_cat, g_cat);
    cudaGetSymbolAddress((void**)&p_tmp, g_tmp);
    cudaGetSymbolAddress((void**)&p_gx, g_gx);
    cudaGetSymbolAddress((void**)&p_gz, g_gz);
    cudaGetSymbolAddress((void**)&p_pea, g_pea);
    cudaGetSymbolAddress((void**)&p_wtf, g_wtf);
    cudaGetSymbolAddress((void**)&p_deg, g_deg);
    cudaGetSymbolAddress((void**)&p_rowptr, g_rowptr);
    cudaGetSymbolAddress((void**)&p_fill, g_fill);
    cudaGetSymbolAddress((void**)&p_psrc, g_psrc);
    cudaGetSymbolAddress((void**)&p_bsum, g_bsum);
    cudaGetSymbolAddress((void**)&p_gdeg, g_gdeg);
    cudaGetSymbolAddress((void**)&p_growptr, g_growptr);
    cudaGetSymbolAddress((void**)&p_gfill, g_gfill);
    cudaGetSymbolAddress((void**)&p_gpsrc, g_gpsrc);
    cudaGetSymbolAddress((void**)&p_gbsum, g_gbsum);

    // ---- weight pre-rounding + deg zeroing ----
    wconv_k<<<CDIV(TN, 256), 256>>>(loc_W, fp_W, glob_W, p_wtf, p_deg, p_gdeg);

    // ---- input projection (K=4) ----
    gemm_tile<<<CDIV(TN, 128), 256>>>(x_local, loc_in_W, loc_in_b, p_h, TN, 4,
                                      nullptr, nullptr);

    // ---- fused CSR build (both graphs) ----
    hist2_k<<<CDIV(ELN + EGN, 256), 256>>>(ldst, gdst, p_deg, p_gdeg);
    scan1b_k<<<NBL + NBG, 256>>>(p_deg, p_gdeg, p_bsum, p_gbsum);

    // ---- local layer 0 GEMM (+fused scores) ----
    gemm_mma<4><<<CDIV(TN, 64), 256>>>(p_h, p_wtf + WT_LOC0, nullptr, p_z, TN, HH, HH,
                                       loc_asrc, loc_adst, p_ssrc, p_sdst);

    scan2b_k<<<1, 32>>>(p_bsum, p_gbsum, p_rowptr, p_growptr);
    scan3b_k<<<NBL + NBG, 256>>>(p_deg, p_gdeg, p_bsum, p_gbsum,
                                 p_rowptr, p_growptr, p_fill, p_gfill);
    scatedge2_k<<<CDIV(ELN + EGN, 256), 256>>>(lsrc, ldst, gsrc, gdst, eattr,
                                               p_fill, p_gfill, p_psrc, p_pea, p_gpsrc);

    // ---- local layer 0 aggregate ----
    gat_fused<4, 32, true><<<CDIV(TN, 8), 256>>>(p_rowptr, p_psrc, p_pea,
                                                 loc_eW, loc_ae,
                                                 p_ssrc, p_sdst, p_z, loc_b, p_h, TN);
    // ---- local layer 1 ----
    gemm_mma<4><<<CDIV(TN, 64), 256>>>(p_h, p_wtf + WT_LOC1, nullptr, p_z, TN, HH, HH,
                                       loc_asrc + HH, loc_adst + HH, p_ssrc, p_sdst);
    gat_fused<4, 32, true><<<CDIV(TN, 8), 256>>>(p_rowptr, p_psrc, p_pea,
                                                 loc_eW + HH, loc_ae + HH,
                                                 p_ssrc, p_sdst, p_z, loc_b + HH, p_h, TN);

    // ---- pooling straight into padded cat rows ----
    pool_cat_k<<<BB, 128>>>(p_h, node_batch, gfeat, cid, p_cat);

    // ---- fused MLP ----
    gemm_mma<0><<<CDIV(BB, 64), 256>>>(p_cat, p_wtf + WT_FP, fp_b, p_tmp, BB,
                                       HH + FGN, CATP,
                                       nullptr, nullptr, nullptr, nullptr);

    // ---- global projection (all N, fused LN+ReLU), then LN+scatter of fused rows ----
    gemm_tile<<<CDIV(NNODE, 128), 256>>>(gfeat, gp_W, gp_b, p_gx, NNODE, FGN,
                                         gp_g, gp_beta);
    ln_relu_scat_k<<<BB, HH>>>(p_tmp, fp_g, fp_beta, cid, p_gx);

    // ---- 2x global GATConv ----
    for (int l = 0; l < 2; l++) {
        gemm_mma<2><<<CDIV(NNODE, 64), 256>>>(p_gx,
                                              p_wtf + (l == 0 ? WT_G0 : WT_G1), nullptr,
                                              p_gz, NNODE, HH, HH,
                                              glob_asrc + l * HH, glob_adst + l * HH,
                                              p_ssrc, p_sdst);
        gat_fused<2, 64, false><<<CDIV(NNODE, 8), 256>>>(p_growptr, p_gpsrc, (float*)nullptr,
                                                         (float*)nullptr, (float*)nullptr,
                                                         p_ssrc, p_sdst, p_gz,
                                                         glob_b + l * HH, p_gx, NNODE);
    }

    // ---- classifier ----
    classifier_k<<<CDIV(BB, 8), 256>>>(p_gx, cid, cls_W1, cls_b1, cls_W2, cls_b2,
                                       (float*)d_out);
}

// round 12
// speedup vs baseline: 1.4174x; 1.0086x over previous
#include <cuda_runtime.h>
#include <math.h>

// ---------------- problem constants ----------------
#define TN    131072     // local tx nodes
#define ELN   524288     // local edges
#define NNODE 50000      // global contract nodes
#define EGN   400000     // global edges
#define BB    8192       // batch of contracts
#define HH    128        // hidden dim
#define FGN   7          // global feat dim
#define HCN   64         // classifier hidden
#define CC    2          // classes
#define CATP  144        // padded concat row stride (16B multiple)

#define CDIV(a,b) (((a)+(b)-1)/(b))
#define NBL  CDIV(TN, 1024)      // 128 scan blocks local
#define NBG  CDIV(NNODE, 1024)   // 49 scan blocks global

// pre-rounded weight buffer offsets (floats)
#define WT_LOC0 0
#define WT_LOC1 16384
#define WT_FP   32768
#define WT_G0   50048
#define WT_G1   66432
#define WT_TOT  82816

// ---------------- scratch (device globals) ----------------
__device__ float g_h   [TN*HH];
__device__ float g_z   [TN*HH];
__device__ float g_ssrc[TN*4];
__device__ float g_sdst[TN*4];
__device__ float g_cat [BB*CATP];
__device__ float g_tmp [BB*HH];
__device__ float g_gx  [NNODE*HH];
__device__ float g_gz  [NNODE*HH];
__device__ float g_wtf [WT_TOT];
// CSR scratch
__device__ int   g_deg   [TN];
__device__ int   g_rowptr[TN+1];
__device__ int   g_fill  [TN];
__device__ int   g_psrc  [ELN];
__device__ float g_pea   [ELN];
__device__ int   g_bsum  [256];
__device__ int   g_gdeg   [NNODE];
__device__ int   g_growptr[NNODE+1];
__device__ int   g_gfill  [NNODE];
__device__ int   g_gpsrc  [EGN];
__device__ int   g_gbsum  [256];

// ---------------- helpers ----------------
__device__ __forceinline__ unsigned f2tf32(float f) {
    unsigned r;
    asm("cvt.rna.tf32.f32 %0, %1;" : "=r"(r) : "f"(f));
    return r;
}
__device__ __forceinline__ void cp_async16(unsigned dst, const void* src, int bytes) {
    asm volatile("cp.async.cg.shared.global [%0], [%1], 16, %2;"
                 :: "r"(dst), "l"(src), "r"(bytes) : "memory");
}
__device__ __forceinline__ void cp_commit() {
    asm volatile("cp.async.commit_group;" ::: "memory");
}
__device__ __forceinline__ void cp_wait0() {
    asm volatile("cp.async.wait_group 0;" ::: "memory");
}

// ---------------- weight pre-rounding + deg zeroing ----------
__global__ void wconv_k(const float* __restrict__ locW, const float* __restrict__ fpW,
                        const float* __restrict__ globW, float* __restrict__ wt,
                        int* __restrict__ deg, int* __restrict__ gdeg) {
    int i = blockIdx.x * blockDim.x + threadIdx.x;
    if (i < 32768)       wt[i] = __uint_as_float(f2tf32(locW[i]));
    else if (i < 50048)  wt[i] = __uint_as_float(f2tf32(fpW[i - 32768]));
    else if (i < WT_TOT) wt[i] = __uint_as_float(f2tf32(globW[i - 50048]));
    if (i < TN)    deg[i]  = 0;
    if (i < NNODE) gdeg[i] = 0;
}

// ================= CSR construction (both graphs fused) =================
__global__ void hist2_k(const int* __restrict__ ldst, const int* __restrict__ gdst,
                        int* __restrict__ deg, int* __restrict__ gdeg) {
    int e = blockIdx.x * blockDim.x + threadIdx.x;
    if (e < ELN) atomicAdd(&deg[ldst[e]], 1);
    else if (e < ELN + EGN) atomicAdd(&gdeg[gdst[e - ELN]], 1);
}
__global__ void scan1b_k(const int* __restrict__ deg, const int* __restrict__ gdeg,
                         int* __restrict__ bsum, int* __restrict__ gbsum) {
    __shared__ int s[256];
    int t = threadIdx.x;
    bool loc = blockIdx.x < NBL;
    const int* d = loc ? deg : gdeg;
    int n = loc ? TN : NNODE;
    int base = (loc ? blockIdx.x : blockIdx.x - NBL) * 1024;
    int sum = 0;
#pragma unroll
    for (int i = 0; i < 4; i++) {
        int idx = base + t * 4 + i;
        if (idx < n) sum += d[idx];
    }
    s[t] = sum; __syncthreads();
    for (int o = 128; o > 0; o >>= 1) { if (t < o) s[t] += s[t + o]; __syncthreads(); }
    if (t == 0) (loc ? bsum : gbsum)[loc ? blockIdx.x : blockIdx.x - NBL] = s[0];
}
__global__ void scan2b_k(int* __restrict__ bsum, int* __restrict__ gbsum,
                         int* __restrict__ rowptr, int* __restrict__ growptr) {
    if (threadIdx.x == 0) {
        int acc = 0;
        for (int i = 0; i < NBL; i++) { int v = bsum[i]; bsum[i] = acc; acc += v; }
        rowptr[TN] = ELN;
    } else if (threadIdx.x == 1) {
        int acc = 0;
        for (int i = 0; i < NBG; i++) { int v = gbsum[i]; gbsum[i] = acc; acc += v; }
        growptr[NNODE] = EGN;
    }
}
__global__ void scan3b_k(const int* __restrict__ deg, const int* __restrict__ gdeg,
                         const int* __restrict__ bsum, const int* __restrict__ gbsum,
                         int* __restrict__ rowptr, int* __restrict__ growptr,
                         int* __restrict__ fill, int* __restrict__ gfill) {
    __shared__ int s[256];
    int t = threadIdx.x;
    bool loc = blockIdx.x < NBL;
    const int* d = loc ? deg : gdeg;
    const int* bs = loc ? bsum : gbsum;
    int* rp = loc ? rowptr : growptr;
    int* fl = loc ? fill : gfill;
    int n = loc ? TN : NNODE;
    int bid = loc ? blockIdx.x : blockIdx.x - NBL;
    int base = bid * 1024;
    int v[4]; int sum = 0;
#pragma unroll
    for (int i = 0; i < 4; i++) {
        int idx = base + t * 4 + i;
        v[i] = (idx < n) ? d[idx] : 0;
        sum += v[i];
    }
    s[t] = sum; __syncthreads();
    for (int o = 1; o < 256; o <<= 1) {
        int x = (t >= o) ? s[t - o] : 0;
        __syncthreads();
        s[t] += x;
        __syncthreads();
    }
    int excl = ((t == 0) ? 0 : s[t - 1]) + bs[bid];
#pragma unroll
    for (int i = 0; i < 4; i++) {
        int idx = base + t * 4 + i;
        if (idx < n) { rp[idx] = excl; fl[idx] = excl; }
        excl += v[i];
    }
}
__global__ void scatedge2_k(const int* __restrict__ lsrc, const int* __restrict__ ldst,
                            const int* __restrict__ gsrc, const int* __restrict__ gdst,
                            const float* __restrict__ eattr,
                            int* __restrict__ fill, int* __restrict__ gfill,
                            int* __restrict__ psrc, float* __restrict__ pea,
                            int* __restrict__ gpsrc) {
    int e = blockIdx.x * blockDim.x + threadIdx.x;
    if (e < ELN) {
        int p = atomicAdd(&fill[ldst[e]], 1);
        psrc[p] = lsrc[e];
        pea[p] = eattr[e];
    } else if (e < ELN + EGN) {
        int ee = e - ELN;
        int p = atomicAdd(&gfill[gdst[ee]], 1);
        gpsrc[p] = gsrc[ee];
    }
}

// ================= tf32 MMA GEMM: BM=128 wide tile, 2-stage cp.async =============
// BM=128, BN=128, BK=16. 8 warps 4x2, warp tile 32x64 (c[2][8][4]).
// W pre-rounded tf32 bits (raw feed); A converted consume-side.
#define APAD 20
#define WPAD 136
#define ABUF (128 * APAD)   // 2560 floats
#define WBUF (16 * WPAD)    // 2176 floats
template <int NH>
__global__ __launch_bounds__(256, 2)
void gemm_mma(const float* __restrict__ A, const float* __restrict__ W,
              const float* __restrict__ bias, float* __restrict__ C,
              int M, int K, int lda,
              const float* __restrict__ asrc, const float* __restrict__ adst,
              float* __restrict__ ssrc, float* __restrict__ sdst) {
    __shared__ __align__(16) float As[2 * ABUF];
    __shared__ __align__(16) float Ws[2 * WBUF];
    const int tid  = threadIdx.x;
    const int warp = tid >> 5, lane = tid & 31;
    const int bm   = blockIdx.x * 128;
    const int wm   = (warp >> 1) * 32;
    const int wn   = (warp & 1) * 64;
    const int g    = lane >> 2;
    const int ct   = lane & 3;
    const int nk   = (K + 15) / 16;

    const unsigned asb = (unsigned)__cvta_generic_to_shared(As);
    const unsigned wsb = (unsigned)__cvta_generic_to_shared(Ws);

    float c[2][8][4];
#pragma unroll
    for (int mt = 0; mt < 2; mt++)
#pragma unroll
        for (int nt = 0; nt < 8; nt++)
#pragma unroll
            for (int r = 0; r < 4; r++) c[mt][nt][r] = 0.f;

    // stage loader: A 128x16 (512 chunks), W 16x128 (512 chunks); 2 chunks each
    auto issue = [&](int buf, int t) {
        int k0 = t * 16;
#pragma unroll
        for (int j = 0; j < 2; j++) {
            int id = tid + 256 * j;
            int m = id >> 2, kq = (id & 3) * 4;
            int gr = bm + m, gk = k0 + kq;
            int bytes = 0;
            const float* src = A;
            if (gr < M && gk < K) {
                int rem = K - gk;
                bytes = rem >= 4 ? 16 : rem * 4;
                src = A + (size_t)gr * lda + gk;
            }
            cp_async16(asb + (unsigned)(buf * ABUF + m * APAD + kq) * 4u, src, bytes);
        }
#pragma unroll
        for (int j = 0; j < 2; j++) {
            int id = tid + 256 * j;
            int k = id >> 5, nq = (id & 31) * 4;
            int gk = k0 + k;
            int bytes = (gk < K) ? 16 : 0;
            const float* src = (gk < K) ? (W + (size_t)gk * 128 + nq) : W;
            cp_async16(wsb + (unsigned)(buf * WBUF + k * WPAD + nq) * 4u, src, bytes);
        }
        cp_commit();
    };

    issue(0, 0);

    for (int t = 0; t < nk; t++) {
        cp_wait0();
        __syncthreads();
        if (t + 1 < nk) issue((t + 1) & 1, t + 1);

        const float* Ab = As + (t & 1) * ABUF;
        const unsigned* Wb = (const unsigned*)(Ws + (t & 1) * WBUF);
#pragma unroll
        for (int ks = 0; ks < 16; ks += 8) {
            unsigned b[8][2];
#pragma unroll
            for (int nt = 0; nt < 8; nt++) {
                int n = wn + nt * 8 + g;
                b[nt][0] = Wb[(ks + ct) * WPAD + n];
                b[nt][1] = Wb[(ks + ct + 4) * WPAD + n];
            }
#pragma unroll
            for (int mt = 0; mt < 2; mt++) {
                int r0 = wm + mt * 16 + g;
                unsigned a0 = f2tf32(Ab[r0 * APAD + ks + ct]);
                unsigned a1 = f2tf32(Ab[(r0 + 8) * APAD + ks + ct]);
                unsigned a2 = f2tf32(Ab[r0 * APAD + ks + ct + 4]);
                unsigned a3 = f2tf32(Ab[(r0 + 8) * APAD + ks + ct + 4]);
#pragma unroll
                for (int nt = 0; nt < 8; nt++) {
                    asm volatile(
                        "mma.sync.aligned.m16n8k8.row.col.f32.tf32.tf32.f32 "
                        "{%0,%1,%2,%3}, {%4,%5,%6,%7}, {%8,%9}, {%0,%1,%2,%3};"
                        : "+f"(c[mt][nt][0]), "+f"(c[mt][nt][1]),
                          "+f"(c[mt][nt][2]), "+f"(c[mt][nt][3])
                        : "r"(a0), "r"(a1), "r"(a2), "r"(a3),
                          "r"(b[nt][0]), "r"(b[nt][1]));
                }
            }
        }
        __syncthreads();
    }

    // epilogue: store C (+bias) and optionally fused attention scores
    const int NH2 = (NH == 4) ? 2 : 1;
    float ps[2][2][2], pd[2][2][2];
    if (NH > 0) {
#pragma unroll
        for (int a = 0; a < 2; a++)
#pragma unroll
            for (int b2 = 0; b2 < 2; b2++)
#pragma unroll
                for (int d = 0; d < 2; d++) { ps[a][b2][d] = 0.f; pd[a][b2][d] = 0.f; }
    }
#pragma unroll
    for (int mt = 0; mt < 2; mt++) {
        int row0 = bm + wm + mt * 16 + g;
        int row1 = row0 + 8;
#pragma unroll
        for (int nt = 0; nt < 8; nt++) {
            int col = wn + nt * 8 + 2 * ct;
            float b0 = bias ? bias[col] : 0.f;
            float b1 = bias ? bias[col + 1] : 0.f;
            float v00 = c[mt][nt][0] + b0, v01 = c[mt][nt][1] + b1;
            float v10 = c[mt][nt][2] + b0, v11 = c[mt][nt][3] + b1;
            if (row0 < M) *(float2*)(C + (size_t)row0 * 128 + col) = make_float2(v00, v01);
            if (row1 < M) *(float2*)(C + (size_t)row1 * 128 + col) = make_float2(v10, v11);
            if (NH > 0) {
                float a0s = asrc[col], a1s = asrc[col + 1];
                float a0d = adst[col], a1d = adst[col + 1];
                int h2 = (NH == 4) ? (nt >> 2) : 0;
                ps[mt][0][h2] += v00 * a0s + v01 * a1s;
                ps[mt][1][h2] += v10 * a0s + v11 * a1s;
                pd[mt][0][h2] += v00 * a0d + v01 * a1d;
                pd[mt][1][h2] += v10 * a0d + v11 * a1d;
            }
        }
    }
    if (NH > 0) {
#pragma unroll
        for (int mt = 0; mt < 2; mt++)
#pragma unroll
            for (int rh = 0; rh < 2; rh++)
#pragma unroll
                for (int h2 = 0; h2 < NH2; h2++) {
                    float s = ps[mt][rh][h2], d = pd[mt][rh][h2];
                    s += __shfl_xor_sync(0xffffffffu, s, 1);
                    s += __shfl_xor_sync(0xffffffffu, s, 2);
                    d += __shfl_xor_sync(0xffffffffu, d, 1);
                    d += __shfl_xor_sync(0xffffffffu, d, 2);
                    ps[mt][rh][h2] = s; pd[mt][rh][h2] = d;
                }
        if (ct == 0) {
            int headbase = (wn * NH) >> 7;
#pragma unroll
            for (int mt = 0; mt < 2; mt++)
#pragma unroll
                for (int rh = 0; rh < 2; rh++) {
                    int row = bm + wm + mt * 16 + g + rh * 8;
                    if (row < M) {
#pragma unroll
                        for (int h2 = 0; h2 < NH2; h2++) {
                            int head = headbase + h2;
                            ssrc[(size_t)row * NH + head] = ps[mt][rh][h2];
                            sdst[(size_t)row * NH + head] = pd[mt][rh][h2];
                        }
                    }
                }
        }
    }
}

// ---------------- SIMT GEMM for tiny-K projections (+optional fused LN+ReLU) --------
__global__ __launch_bounds__(256, 2)
void gemm_tile(const float* __restrict__ A, const float* __restrict__ W,
               const float* __restrict__ bias, float* __restrict__ C,
               int M, int K,
               const float* __restrict__ gamma, const float* __restrict__ beta) {
    __shared__ float As[16 * 132];
    __shared__ float Ws[16 * 132];
    const int bm  = blockIdx.x * 128;
    const int tid = threadIdx.x;
    const int tr  = (tid >> 4) * 8;
    const int tc  = (tid & 15) * 8;
    float acc[8][8];
#pragma unroll
    for (int x = 0; x < 8; x++)
#pragma unroll
        for (int y = 0; y < 8; y++) acc[x][y] = 0.f;

    for (int k0 = 0; k0 < K; k0 += 16) {
        for (int i = tid; i < 128 * 16; i += 256) {
            int m = i >> 4, kk = i & 15;
            int gr = bm + m, gk = k0 + kk;
            As[kk * 132 + m] = (gr < M && gk < K) ? A[(size_t)gr * K + gk] : 0.f;
        }
        for (int i = tid; i < 16 * 128; i += 256) {
            int kk = i >> 7, n = i & 127;
            int gk = k0 + kk;
            Ws[kk * 132 + n] = (gk < K) ? W[gk * 128 + n] : 0.f;
        }
        __syncthreads();
#pragma unroll
        for (int kk = 0; kk < 16; kk++) {
            float a[8], w[8];
#pragma unroll
            for (int x = 0; x < 8; x++) a[x] = As[kk * 132 + tr + x];
#pragma unroll
            for (int y = 0; y < 8; y++) w[y] = Ws[kk * 132 + tc + y];
#pragma unroll
            for (int x = 0; x < 8; x++)
#pragma unroll
                for (int y = 0; y < 8; y++) acc[x][y] += a[x] * w[y];
        }
        __syncthreads();
    }

    if (gamma) {
#pragma unroll
        for (int x = 0; x < 8; x++) {
            int gr = bm + tr + x;
            float vv[8]; float sum = 0.f;
#pragma unroll
            for (int y = 0; y < 8; y++) {
                vv[y] = acc[x][y] + (bias ? bias[tc + y] : 0.f);
                sum += vv[y];
            }
#pragma unroll
            for (int k = 1; k < 16; k <<= 1) sum += __shfl_xor_sync(0xffffffffu, sum, k, 16);
            float mean = sum * (1.f / 128.f);
            float sq = 0.f;
#pragma unroll
            for (int y = 0; y < 8; y++) { float d = vv[y] - mean; sq += d * d; }
#pragma unroll
            for (int k = 1; k < 16; k <<= 1) sq += __shfl_xor_sync(0xffffffffu, sq, k, 16);
            float rstd = rsqrtf(sq * (1.f / 128.f) + 1e-5f);
            if (gr < M) {
#pragma unroll
                for (int y = 0; y < 8; y++) {
                    float yv = (vv[y] - mean) * rstd * gamma[tc + y] + beta[tc + y];
                    C[(size_t)gr * 128 + tc + y] = fmaxf(yv, 0.f);
                }
            }
        }
    } else {
#pragma unroll
        for (int x = 0; x < 8; x++) {
            int gr = bm + tr + x;
            if (gr < M) {
#pragma unroll
                for (int y = 0; y < 8; y++) {
                    float v = acc[x][y];
                    if (bias) v += bias[tc + y];
                    C[(size_t)gr * 128 + tc + y] = v;
                }
            }
        }
    }
}

// ---------------- fused single-pass GAT aggregation ----------------
template <int NH, int HD, bool HAS_E>
__global__ void gat_fused(const int* __restrict__ rowptr, const int* __restrict__ psrc,
                          const float* __restrict__ pea,
                          const float* __restrict__ eW, const float* __restrict__ ae,
                          const float* __restrict__ ssrc, const float* __restrict__ sdst,
                          const float* __restrict__ z, const float* __restrict__ bias,
                          float* __restrict__ h, int n) {
    __shared__ float ce_s[NH];
    if (HAS_E && threadIdx.x < NH) {
        int hh = threadIdx.x;
        float s = 0.f;
#pragma unroll
        for (int d = 0; d < HD; d++) s += eW[hh * HD + d] * ae[hh * HD + d];
        ce_s[hh] = s;
    }
    if (HAS_E) __syncthreads();

    int node = blockIdx.x * 8 + (threadIdx.x >> 5);
    if (node >= n) return;
    int lane = threadIdx.x & 31;
    int c = lane * 4;
    int head = c / HD;

    float sd = sdst[(size_t)node * NH + head];
    float ce = HAS_E ? ce_s[head] : 0.f;

    float4 acc = make_float4(0.f, 0.f, 0.f, 0.f);
    float den = 0.f;
    int lo = rowptr[node], hi = rowptr[node + 1];
    for (int j = lo; j < hi; j++) {
        int s = psrc[j];
        float sc = ssrc[(size_t)s * NH + head] + sd;
        if (HAS_E) sc += pea[j] * ce;
        sc = sc > 0.f ? sc : 0.2f * sc;
        float ex = __expf(sc);
        den += ex;
        float4 zv = *(const float4*)(z + (size_t)s * HH + c);
        acc.x += ex * zv.x; acc.y += ex * zv.y;
        acc.z += ex * zv.z; acc.w += ex * zv.w;
    }
    float inv = 1.f / fmaxf(den, 1e-16f);
    float4 hv = *(const float4*)(h + (size_t)node * HH + c);
    float4 bv = *(const float4*)(bias + c);
    acc.x = hv.x + bv.x + acc.x * inv;
    acc.y = hv.y + bv.y + acc.y * inv;
    acc.z = hv.z + bv.z + acc.z * inv;
    acc.w = hv.w + bv.w + acc.w * inv;
    acc.x = acc.x > 0.f ? acc.x : __expf(acc.x) - 1.f;
    acc.y = acc.y > 0.f ? acc.y : __expf(acc.y) - 1.f;
    acc.z = acc.z > 0.f ? acc.z : __expf(acc.z) - 1.f;
    acc.w = acc.w > 0.f ? acc.w : __expf(acc.w) - 1.f;
    *(float4*)(h + (size_t)node * HH + c) = acc;
}

// ---------------- pooling -> padded cat rows (+ gfeat tail) ----------------
__global__ void pool_cat_k(const float* __restrict__ h, const int* __restrict__ nb,
                           const float* __restrict__ gf, const int* __restrict__ cid,
                           float* __restrict__ cat) {
    int b = blockIdx.x, t = threadIdx.x;
    int lo = 0, hi = TN;
    while (lo < hi) { int mid = (lo + hi) >> 1; if (nb[mid] < b) lo = mid + 1; else hi = mid; }
    int start = lo;
    hi = TN;
    while (lo < hi) { int mid = (lo + hi) >> 1; if (nb[mid] < b + 1) lo = mid + 1; else hi = mid; }
    int end = lo;
    float s = 0.f;
    for (int i = start; i < end; i++) s += h[(size_t)i * HH + t];
    cat[(size_t)b * CATP + t] = s / fmaxf((float)(end - start), 1.f);
    if (t < FGN)
        cat[(size_t)b * CATP + HH + t] = gf[(size_t)cid[b] * FGN + t];
}

// ---------------- LayerNorm(128) + ReLU, scattered to gx[cid] ----------------
__global__ void ln_relu_scat_k(const float* __restrict__ X, const float* __restrict__ g,
                               const float* __restrict__ be, const int* __restrict__ cid,
                               float* __restrict__ gx) {
    int row = blockIdx.x, t = threadIdx.x;
    float v = X[(size_t)row * HH + t];
    __shared__ float red[HH];
    red[t] = v; __syncthreads();
    for (int s = 64; s > 0; s >>= 1) { if (t < s) red[t] += red[t + s]; __syncthreads(); }
    float mean = red[0] / 128.f;
    __syncthreads();
    float dv = v - mean;
    red[t] = dv * dv; __syncthreads();
    for (int s = 64; s > 0; s >>= 1) { if (t < s) red[t] += red[t + s]; __syncthreads(); }
    float var = red[0] / 128.f;
    float y = dv * rsqrtf(var + 1e-5f) * g[t] + be[t];
    gx[(size_t)cid[row] * HH + t] = fmaxf(y, 0.f);
}

// ---------------- classifier: 8 contracts per block ----------------
__global__ __launch_bounds__(256)
void classifier_k(const float* __restrict__ gx, const int* __restrict__ cid,
                  const float* __restrict__ W1, const float* __restrict__ b1,
                  const float* __restrict__ W2, const float* __restrict__ b2,
                  float* __restrict__ out) {
    __shared__ float row[4][HH];
    __shared__ float hc[4][HCN];
    int tid = threadIdx.x;
    int grp = tid >> 6, t = tid & 63;
    for (int it = 0; it < 2; it++) {
        int b = blockIdx.x * 8 + it * 4 + grp;
        __syncthreads();
        const float* srcp = gx + (size_t)cid[b] * HH;
        row[grp][t] = srcp[t];
        row[grp][t + 64] = srcp[t + 64];
        __syncthreads();
        float s = b1[t];
#pragma unroll
        for (int k = 0; k < HH; k++) s += row[grp][k] * W1[k * HCN + t];
        hc[grp][t] = fmaxf(s, 0.f);
        __syncthreads();
        if (t < CC) {
            float s2 = b2[t];
#pragma unroll
            for (int k = 0; k < HCN; k++) s2 += hc[grp][k] * W2[k * CC + t];
            out[b * CC + t] = s2;
        }
    }
}

// ---------------- launch ----------------
extern "C" void kernel_launch(void* const* d_in, const int* in_sizes, int n_in,
                              void* d_out, int out_size) {
    const float* x_local    = (const float*)d_in[0];
    const float* eattr      = (const float*)d_in[1];
    const float* gfeat      = (const float*)d_in[2];
    const float* loc_in_W   = (const float*)d_in[3];
    const float* loc_in_b   = (const float*)d_in[4];
    const float* loc_W      = (const float*)d_in[5];
    const float* loc_asrc   = (const float*)d_in[6];
    const float* loc_adst   = (const float*)d_in[7];
    const float* loc_eW     = (const float*)d_in[8];
    const float* loc_ae     = (const float*)d_in[9];
    const float* loc_b      = (const float*)d_in[10];
    const float* fp_W       = (const float*)d_in[11];
    const float* fp_b       = (const float*)d_in[12];
    const float* fp_g       = (const float*)d_in[13];
    const float* fp_beta    = (const float*)d_in[14];
    const float* gp_W       = (const float*)d_in[15];
    const float* gp_b       = (const float*)d_in[16];
    const float* gp_g       = (const float*)d_in[17];
    const float* gp_beta    = (const float*)d_in[18];
    const float* glob_W     = (const float*)d_in[19];
    const float* glob_asrc  = (const float*)d_in[20];
    const float* glob_adst  = (const float*)d_in[21];
    const float* glob_b     = (const float*)d_in[22];
    const float* cls_W1     = (const float*)d_in[23];
    const float* cls_b1     = (const float*)d_in[24];
    const float* cls_W2     = (const float*)d_in[25];
    const float* cls_b2     = (const float*)d_in[26];
    const int*   eil        = (const int*)d_in[27];
    const int*   node_batch = (const int*)d_in[28];
    const int*   cid        = (const int*)d_in[29];
    const int*   gei        = (const int*)d_in[30];

    const int* lsrc = eil;
    const int* ldst = eil + ELN;
    const int* gsrc = gei;
    const int* gdst = gei + EGN;

    float *p_h, *p_z, *p_ssrc, *p_sdst;
    float *p_cat, *p_tmp, *p_gx, *p_gz, *p_pea, *p_wtf;
    int *p_deg, *p_rowptr, *p_fill, *p_psrc, *p_bsum;
    int *p_gdeg, *p_growptr, *p_gfill, *p_gpsrc, *p_gbsum;
    cudaGetSymbolAddress((void**)&p_h, g_h);
    cudaGetSymbolAddress((void**)&p_z, g_z);
    cudaGetSymbolAddress((void**)&p_ssrc, g_ssrc);
    cudaGetSymbolAddress((void**)&p_sdst, g_sdst);
    cudaGetSymbolAddress((void**)&p_cat, g_cat);
    cudaGetSymbolAddress((void**)&p_tmp, g_tmp);
    cudaGetSymbolAddress((void**)&p_gx, g_gx);
    cudaGetSymbolAddress((void**)&p_gz, g_gz);
    cudaGetSymbolAddress((void**)&p_pea, g_pea);
    cudaGetSymbolAddress((void**)&p_wtf, g_wtf);
    cudaGetSymbolAddress((void**)&p_deg, g_deg);
    cudaGetSymbolAddress((void**)&p_rowptr, g_rowptr);
    cudaGetSymbolAddress((void**)&p_fill, g_fill);
    cudaGetSymbolAddress((void**)&p_psrc, g_psrc);
    cudaGetSymbolAddress((void**)&p_bsum, g_bsum);
    cudaGetSymbolAddress((void**)&p_gdeg, g_gdeg);
    cudaGetSymbolAddress((void**)&p_growptr, g_growptr);
    cudaGetSymbolAddress((void**)&p_gfill, g_gfill);
    cudaGetSymbolAddress((void**)&p_gpsrc, g_gpsrc);
    cudaGetSymbolAddress((void**)&p_gbsum, g_gbsum);

    // ---- weight pre-rounding + deg zeroing ----
    wconv_k<<<CDIV(TN, 256), 256>>>(loc_W, fp_W, glob_W, p_wtf, p_deg, p_gdeg);

    // ---- input projection (K=4) ----
    gemm_tile<<<CDIV(TN, 128), 256>>>(x_local, loc_in_W, loc_in_b, p_h, TN, 4,
                                      nullptr, nullptr);

    // ---- fused CSR build (both graphs) ----
    hist2_k<<<CDIV(ELN + EGN, 256), 256>>>(ldst, gdst, p_deg, p_gdeg);
    scan1b_k<<<NBL + NBG, 256>>>(p_deg, p_gdeg, p_bsum, p_gbsum);

    // ---- local layer 0 GEMM (+fused scores) ----
    gemm_mma<4><<<CDIV(TN, 128), 256>>>(p_h, p_wtf + WT_LOC0, nullptr, p_z, TN, HH, HH,
                                        loc_asrc, loc_adst, p_ssrc, p_sdst);

    scan2b_k<<<1, 32>>>(p_bsum, p_gbsum, p_rowptr, p_growptr);
    scan3b_k<<<NBL + NBG, 256>>>(p_deg, p_gdeg, p_bsum, p_gbsum,
                                 p_rowptr, p_growptr, p_fill, p_gfill);
    scatedge2_k<<<CDIV(ELN + EGN, 256), 256>>>(lsrc, ldst, gsrc, gdst, eattr,
                                               p_fill, p_gfill, p_psrc, p_pea, p_gpsrc);

    // ---- local layer 0 aggregate ----
    gat_fused<4, 32, true><<<CDIV(TN, 8), 256>>>(p_rowptr, p_psrc, p_pea,
                                                 loc_eW, loc_ae,
                                                 p_ssrc, p_sdst, p_z, loc_b, p_h, TN);
    // ---- local layer 1 ----
    gemm_mma<4><<<CDIV(TN, 128), 256>>>(p_h, p_wtf + WT_LOC1, nullptr, p_z, TN, HH, HH,
                                        loc_asrc + HH, loc_adst + HH, p_ssrc, p_sdst);
    gat_fused<4, 32, true><<<CDIV(TN, 8), 256>>>(p_rowptr, p_psrc, p_pea,
                                                 loc_eW + HH, loc_ae + HH,
                                                 p_ssrc, p_sdst, p_z, loc_b + HH, p_h, TN);

    // ---- pooling straight into padded cat rows ----
    pool_cat_k<<<BB, 128>>>(p_h, node_batch, gfeat, cid, p_cat);

    // ---- fused MLP ----
    gemm_mma<0><<<CDIV(BB, 128), 256>>>(p_cat, p_wtf + WT_FP, fp_b, p_tmp, BB,
                                        HH + FGN, CATP,
                                        nullptr, nullptr, nullptr, nullptr);

    // ---- global projection (all N, fused LN+ReLU), then LN+scatter of fused rows ----
    gemm_tile<<<CDIV(NNODE, 128), 256>>>(gfeat, gp_W, gp_b, p_gx, NNODE, FGN,
                                         gp_g, gp_beta);
    ln_relu_scat_k<<<BB, HH>>>(p_tmp, fp_g, fp_beta, cid, p_gx);

    // ---- 2x global GATConv ----
    for (int l = 0; l < 2; l++) {
        gemm_mma<2><<<CDIV(NNODE, 128), 256>>>(p_gx,
                                               p_wtf + (l == 0 ? WT_G0 : WT_G1), nullptr,
                                               p_gz, NNODE, HH, HH,
                                               glob_asrc + l * HH, glob_adst + l * HH,
                                               p_ssrc, p_sdst);
        gat_fused<2, 64, false><<<CDIV(NNODE, 8), 256>>>(p_growptr, p_gpsrc, (float*)nullptr,
                                                         (float*)nullptr, (float*)nullptr,
                                                         p_ssrc, p_sdst, p_gz,
                                                         glob_b + l * HH, p_gx, NNODE);
    }

    // ---- classifier ----
    classifier_k<<<CDIV(BB, 8), 256>>>(p_gx, cid, cls_W1, cls_b1, cls_W2, cls_b2,
                                       (float*)d_out);
}

// round 13
// speedup vs baseline: 1.4415x; 1.0170x over previous
#include <cuda_runtime.h>
#include <math.h>

// ---------------- problem constants ----------------
#define TN    131072     // local tx nodes
#define ELN   524288     // local edges
#define NNODE 50000      // global contract nodes
#define EGN   400000     // global edges
#define BB    8192       // batch of contracts
#define HH    128        // hidden dim
#define FGN   7          // global feat dim
#define HCN   64         // classifier hidden
#define CC    2          // classes
#define CATP  144        // padded concat row stride (16B multiple)

#define CDIV(a,b) (((a)+(b)-1)/(b))
#define NBL  CDIV(TN, 1024)      // 128 scan blocks local
#define NBG  CDIV(NNODE, 1024)   // 49 scan blocks global

// pre-rounded weight buffer offsets (floats)
#define WT_LOC0 0
#define WT_LOC1 16384
#define WT_FP   32768
#define WT_G0   50048
#define WT_G1   66432
#define WT_TOT  82816

// ---------------- scratch (device globals) ----------------
__device__ float g_h   [TN*HH];
__device__ float g_z   [TN*HH];
__device__ float g_ssrc[TN*4];
__device__ float g_sdst[TN*4];
__device__ float g_cat [BB*CATP];
__device__ float g_tmp [BB*HH];
__device__ float g_gx  [NNODE*HH];
__device__ float g_gz  [NNODE*HH];
__device__ float g_wtf [WT_TOT];
// CSR scratch
__device__ int   g_deg   [TN];
__device__ int   g_rowptr[TN+1];
__device__ int   g_fill  [TN];
__device__ int   g_psrc  [ELN];
__device__ float g_pea   [ELN];
__device__ int   g_bsum  [256];
__device__ int   g_gdeg   [NNODE];
__device__ int   g_growptr[NNODE+1];
__device__ int   g_gfill  [NNODE];
__device__ int   g_gpsrc  [EGN];
__device__ int   g_gbsum  [256];

// ---------------- helpers ----------------
__device__ __forceinline__ unsigned f2tf32(float f) {
    unsigned r;
    asm("cvt.rna.tf32.f32 %0, %1;" : "=r"(r) : "f"(f));
    return r;
}
__device__ __forceinline__ void cp_async16(unsigned dst, const void* src, int bytes) {
    asm volatile("cp.async.cg.shared.global [%0], [%1], 16, %2;"
                 :: "r"(dst), "l"(src), "r"(bytes) : "memory");
}
__device__ __forceinline__ void cp_commit() {
    asm volatile("cp.async.commit_group;" ::: "memory");
}
__device__ __forceinline__ void cp_wait0() {
    asm volatile("cp.async.wait_group 0;" ::: "memory");
}

// ---------------- weight pre-rounding + deg zeroing ----------
__global__ void wconv_k(const float* __restrict__ locW, const float* __restrict__ fpW,
                        const float* __restrict__ globW, float* __restrict__ wt,
                        int* __restrict__ deg, int* __restrict__ gdeg) {
    int i = blockIdx.x * blockDim.x + threadIdx.x;
    if (i < 32768)       wt[i] = __uint_as_float(f2tf32(locW[i]));
    else if (i < 50048)  wt[i] = __uint_as_float(f2tf32(fpW[i - 32768]));
    else if (i < WT_TOT) wt[i] = __uint_as_float(f2tf32(globW[i - 50048]));
    if (i < TN)    deg[i]  = 0;
    if (i < NNODE) gdeg[i] = 0;
}

// ================= CSR construction (both graphs fused) =================
__global__ void hist2_k(const int* __restrict__ ldst, const int* __restrict__ gdst,
                        int* __restrict__ deg, int* __restrict__ gdeg) {
    int e = blockIdx.x * blockDim.x + threadIdx.x;
    if (e < ELN) atomicAdd(&deg[ldst[e]], 1);
    else if (e < ELN + EGN) atomicAdd(&gdeg[gdst[e - ELN]], 1);
}
__global__ void scan1b_k(const int* __restrict__ deg, const int* __restrict__ gdeg,
                         int* __restrict__ bsum, int* __restrict__ gbsum) {
    __shared__ int s[256];
    int t = threadIdx.x;
    bool loc = blockIdx.x < NBL;
    const int* d = loc ? deg : gdeg;
    int n = loc ? TN : NNODE;
    int base = (loc ? blockIdx.x : blockIdx.x - NBL) * 1024;
    int sum = 0;
#pragma unroll
    for (int i = 0; i < 4; i++) {
        int idx = base + t * 4 + i;
        if (idx < n) sum += d[idx];
    }
    s[t] = sum; __syncthreads();
    for (int o = 128; o > 0; o >>= 1) { if (t < o) s[t] += s[t + o]; __syncthreads(); }
    if (t == 0) (loc ? bsum : gbsum)[loc ? blockIdx.x : blockIdx.x - NBL] = s[0];
}
__global__ void scan2b_k(int* __restrict__ bsum, int* __restrict__ gbsum,
                         int* __restrict__ rowptr, int* __restrict__ growptr) {
    if (threadIdx.x == 0) {
        int acc = 0;
        for (int i = 0; i < NBL; i++) { int v = bsum[i]; bsum[i] = acc; acc += v; }
        rowptr[TN] = ELN;
    } else if (threadIdx.x == 1) {
        int acc = 0;
        for (int i = 0; i < NBG; i++) { int v = gbsum[i]; gbsum[i] = acc; acc += v; }
        growptr[NNODE] = EGN;
    }
}
__global__ void scan3b_k(const int* __restrict__ deg, const int* __restrict__ gdeg,
                         const int* __restrict__ bsum, const int* __restrict__ gbsum,
                         int* __restrict__ rowptr, int* __restrict__ growptr,
                         int* __restrict__ fill, int* __restrict__ gfill) {
    __shared__ int s[256];
    int t = threadIdx.x;
    bool loc = blockIdx.x < NBL;
    const int* d = loc ? deg : gdeg;
    const int* bs = loc ? bsum : gbsum;
    int* rp = loc ? rowptr : growptr;
    int* fl = loc ? fill : gfill;
    int n = loc ? TN : NNODE;
    int bid = loc ? blockIdx.x : blockIdx.x - NBL;
    int base = bid * 1024;
    int v[4]; int sum = 0;
#pragma unroll
    for (int i = 0; i < 4; i++) {
        int idx = base + t * 4 + i;
        v[i] = (idx < n) ? d[idx] : 0;
        sum += v[i];
    }
    s[t] = sum; __syncthreads();
    for (int o = 1; o < 256; o <<= 1) {
        int x = (t >= o) ? s[t - o] : 0;
        __syncthreads();
        s[t] += x;
        __syncthreads();
    }
    int excl = ((t == 0) ? 0 : s[t - 1]) + bs[bid];
#pragma unroll
    for (int i = 0; i < 4; i++) {
        int idx = base + t * 4 + i;
        if (idx < n) { rp[idx] = excl; fl[idx] = excl; }
        excl += v[i];
    }
}
__global__ void scatedge2_k(const int* __restrict__ lsrc, const int* __restrict__ ldst,
                            const int* __restrict__ gsrc, const int* __restrict__ gdst,
                            const float* __restrict__ eattr,
                            int* __restrict__ fill, int* __restrict__ gfill,
                            int* __restrict__ psrc, float* __restrict__ pea,
                            int* __restrict__ gpsrc) {
    int e = blockIdx.x * blockDim.x + threadIdx.x;
    if (e < ELN) {
        int p = atomicAdd(&fill[ldst[e]], 1);
        psrc[p] = lsrc[e];
        pea[p] = eattr[e];
    } else if (e < ELN + EGN) {
        int ee = e - ELN;
        int p = atomicAdd(&gfill[gdst[ee]], 1);
        gpsrc[p] = gsrc[ee];
    }
}

// ================= tf32 MMA GEMM: BM=128, BK=32, 2-stage cp.async ===============
// 8 warps 4x2, warp tile 32x64 (c[2][8][4]). Dynamic smem ~70KB.
// W pre-rounded tf32 bits (raw feed); A converted consume-side.
#define APAD 36
#define WPAD 136
#define ABUF (128 * APAD)   // 4608 floats
#define WBUF (32 * WPAD)    // 4352 floats
#define SMEM_MMA ((2 * ABUF + 2 * WBUF) * 4)   // 71680 bytes
template <int NH>
__global__ __launch_bounds__(256, 2)
void gemm_mma(const float* __restrict__ A, const float* __restrict__ W,
              const float* __restrict__ bias, float* __restrict__ C,
              int M, int K, int lda,
              const float* __restrict__ asrc, const float* __restrict__ adst,
              float* __restrict__ ssrc, float* __restrict__ sdst) {
    extern __shared__ __align__(16) float smem[];
    float* As = smem;                  // 2 * ABUF
    float* Ws = smem + 2 * ABUF;       // 2 * WBUF
    const int tid  = threadIdx.x;
    const int warp = tid >> 5, lane = tid & 31;
    const int bm   = blockIdx.x * 128;
    const int wm   = (warp >> 1) * 32;
    const int wn   = (warp & 1) * 64;
    const int g    = lane >> 2;
    const int ct   = lane & 3;
    const int nk   = (K + 31) / 32;

    const unsigned asb = (unsigned)__cvta_generic_to_shared(As);
    const unsigned wsb = (unsigned)__cvta_generic_to_shared(Ws);

    float c[2][8][4];
#pragma unroll
    for (int mt = 0; mt < 2; mt++)
#pragma unroll
        for (int nt = 0; nt < 8; nt++)
#pragma unroll
            for (int r = 0; r < 4; r++) c[mt][nt][r] = 0.f;

    // stage loader: A 128x32 (1024 chunks), W 32x128 (1024 chunks); 4 each per thread
    auto issue = [&](int buf, int t) {
        int k0 = t * 32;
#pragma unroll
        for (int j = 0; j < 4; j++) {
            int id = tid + 256 * j;
            int m = id >> 3, kq = (id & 7) * 4;
            int gr = bm + m, gk = k0 + kq;
            int bytes = 0;
            const float* src = A;
            if (gr < M && gk < K) {
                int rem = K - gk;
                bytes = rem >= 4 ? 16 : rem * 4;
                src = A + (size_t)gr * lda + gk;
            }
            cp_async16(asb + (unsigned)(buf * ABUF + m * APAD + kq) * 4u, src, bytes);
        }
#pragma unroll
        for (int j = 0; j < 4; j++) {
            int id = tid + 256 * j;
            int k = id >> 5, nq = (id & 31) * 4;
            int gk = k0 + k;
            int bytes = (gk < K) ? 16 : 0;
            const float* src = (gk < K) ? (W + (size_t)gk * 128 + nq) : W;
            cp_async16(wsb + (unsigned)(buf * WBUF + k * WPAD + nq) * 4u, src, bytes);
        }
        cp_commit();
    };

    issue(0, 0);

    for (int t = 0; t < nk; t++) {
        cp_wait0();
        __syncthreads();
        if (t + 1 < nk) issue((t + 1) & 1, t + 1);

        const float* Ab = As + (t & 1) * ABUF;
        const unsigned* Wb = (const unsigned*)(Ws + (t & 1) * WBUF);
#pragma unroll
        for (int ks = 0; ks < 32; ks += 8) {
            unsigned b[8][2];
#pragma unroll
            for (int nt = 0; nt < 8; nt++) {
                int n = wn + nt * 8 + g;
                b[nt][0] = Wb[(ks + ct) * WPAD + n];
                b[nt][1] = Wb[(ks + ct + 4) * WPAD + n];
            }
#pragma unroll
            for (int mt = 0; mt < 2; mt++) {
                int r0 = wm + mt * 16 + g;
                unsigned a0 = f2tf32(Ab[r0 * APAD + ks + ct]);
                unsigned a1 = f2tf32(Ab[(r0 + 8) * APAD + ks + ct]);
                unsigned a2 = f2tf32(Ab[r0 * APAD + ks + ct + 4]);
                unsigned a3 = f2tf32(Ab[(r0 + 8) * APAD + ks + ct + 4]);
#pragma unroll
                for (int nt = 0; nt < 8; nt++) {
                    asm volatile(
                        "mma.sync.aligned.m16n8k8.row.col.f32.tf32.tf32.f32 "
                        "{%0,%1,%2,%3}, {%4,%5,%6,%7}, {%8,%9}, {%0,%1,%2,%3};"
                        : "+f"(c[mt][nt][0]), "+f"(c[mt][nt][1]),
                          "+f"(c[mt][nt][2]), "+f"(c[mt][nt][3])
                        : "r"(a0), "r"(a1), "r"(a2), "r"(a3),
                          "r"(b[nt][0]), "r"(b[nt][1]));
                }
            }
        }
        __syncthreads();
    }

    // epilogue: store C (+bias) and optionally fused attention scores
    const int NH2 = (NH == 4) ? 2 : 1;
    float ps[2][2][2], pd[2][2][2];
    if (NH > 0) {
#pragma unroll
        for (int a = 0; a < 2; a++)
#pragma unroll
            for (int b2 = 0; b2 < 2; b2++)
#pragma unroll
                for (int d = 0; d < 2; d++) { ps[a][b2][d] = 0.f; pd[a][b2][d] = 0.f; }
    }
#pragma unroll
    for (int mt = 0; mt < 2; mt++) {
        int row0 = bm + wm + mt * 16 + g;
        int row1 = row0 + 8;
#pragma unroll
        for (int nt = 0; nt < 8; nt++) {
            int col = wn + nt * 8 + 2 * ct;
            float b0 = bias ? bias[col] : 0.f;
            float b1 = bias ? bias[col + 1] : 0.f;
            float v00 = c[mt][nt][0] + b0, v01 = c[mt][nt][1] + b1;
            float v10 = c[mt][nt][2] + b0, v11 = c[mt][nt][3] + b1;
            if (row0 < M) *(float2*)(C + (size_t)row0 * 128 + col) = make_float2(v00, v01);
            if (row1 < M) *(float2*)(C + (size_t)row1 * 128 + col) = make_float2(v10, v11);
            if (NH > 0) {
                float a0s = asrc[col], a1s = asrc[col + 1];
                float a0d = adst[col], a1d = adst[col + 1];
                int h2 = (NH == 4) ? (nt >> 2) : 0;
                ps[mt][0][h2] += v00 * a0s + v01 * a1s;
                ps[mt][1][h2] += v10 * a0s + v11 * a1s;
                pd[mt][0][h2] += v00 * a0d + v01 * a1d;
                pd[mt][1][h2] += v10 * a0d + v11 * a1d;
            }
        }
    }
    if (NH > 0) {
#pragma unroll
        for (int mt = 0; mt < 2; mt++)
#pragma unroll
            for (int rh = 0; rh < 2; rh++)
#pragma unroll
                for (int h2 = 0; h2 < NH2; h2++) {
                    float s = ps[mt][rh][h2], d = pd[mt][rh][h2];
                    s += __shfl_xor_sync(0xffffffffu, s, 1);
                    s += __shfl_xor_sync(0xffffffffu, s, 2);
                    d += __shfl_xor_sync(0xffffffffu, d, 1);
                    d += __shfl_xor_sync(0xffffffffu, d, 2);
                    ps[mt][rh][h2] = s; pd[mt][rh][h2] = d;
                }
        if (ct == 0) {
            int headbase = (wn * NH) >> 7;
#pragma unroll
            for (int mt = 0; mt < 2; mt++)
#pragma unroll
                for (int rh = 0; rh < 2; rh++) {
                    int row = bm + wm + mt * 16 + g + rh * 8;
                    if (row < M) {
#pragma unroll
                        for (int h2 = 0; h2 < NH2; h2++) {
                            int head = headbase + h2;
                            ssrc[(size_t)row * NH + head] = ps[mt][rh][h2];
                            sdst[(size_t)row * NH + head] = pd[mt][rh][h2];
                        }
                    }
                }
        }
    }
}

// ---------------- SIMT GEMM for tiny-K projections (+optional fused LN+ReLU) --------
__global__ __launch_bounds__(256, 2)
void gemm_tile(const float* __restrict__ A, const float* __restrict__ W,
               const float* __restrict__ bias, float* __restrict__ C,
               int M, int K,
               const float* __restrict__ gamma, const float* __restrict__ beta) {
    __shared__ float As[16 * 132];
    __shared__ float Ws[16 * 132];
    const int bm  = blockIdx.x * 128;
    const int tid = threadIdx.x;
    const int tr  = (tid >> 4) * 8;
    const int tc  = (tid & 15) * 8;
    float acc[8][8];
#pragma unroll
    for (int x = 0; x < 8; x++)
#pragma unroll
        for (int y = 0; y < 8; y++) acc[x][y] = 0.f;

    for (int k0 = 0; k0 < K; k0 += 16) {
        for (int i = tid; i < 128 * 16; i += 256) {
            int m = i >> 4, kk = i & 15;
            int gr = bm + m, gk = k0 + kk;
            As[kk * 132 + m] = (gr < M && gk < K) ? A[(size_t)gr * K + gk] : 0.f;
        }
        for (int i = tid; i < 16 * 128; i += 256) {
            int kk = i >> 7, n = i & 127;
            int gk = k0 + kk;
            Ws[kk * 132 + n] = (gk < K) ? W[gk * 128 + n] : 0.f;
        }
        __syncthreads();
#pragma unroll
        for (int kk = 0; kk < 16; kk++) {
            float a[8], w[8];
#pragma unroll
            for (int x = 0; x < 8; x++) a[x] = As[kk * 132 + tr + x];
#pragma unroll
            for (int y = 0; y < 8; y++) w[y] = Ws[kk * 132 + tc + y];
#pragma unroll
            for (int x = 0; x < 8; x++)
#pragma unroll
                for (int y = 0; y < 8; y++) acc[x][y] += a[x] * w[y];
        }
        __syncthreads();
    }

    if (gamma) {
#pragma unroll
        for (int x = 0; x < 8; x++) {
            int gr = bm + tr + x;
            float vv[8]; float sum = 0.f;
#pragma unroll
            for (int y = 0; y < 8; y++) {
                vv[y] = acc[x][y] + (bias ? bias[tc + y] : 0.f);
                sum += vv[y];
            }
#pragma unroll
            for (int k = 1; k < 16; k <<= 1) sum += __shfl_xor_sync(0xffffffffu, sum, k, 16);
            float mean = sum * (1.f / 128.f);
            float sq = 0.f;
#pragma unroll
            for (int y = 0; y < 8; y++) { float d = vv[y] - mean; sq += d * d; }
#pragma unroll
            for (int k = 1; k < 16; k <<= 1) sq += __shfl_xor_sync(0xffffffffu, sq, k, 16);
            float rstd = rsqrtf(sq * (1.f / 128.f) + 1e-5f);
            if (gr < M) {
#pragma unroll
                for (int y = 0; y < 8; y++) {
                    float yv = (vv[y] - mean) * rstd * gamma[tc + y] + beta[tc + y];
                    C[(size_t)gr * 128 + tc + y] = fmaxf(yv, 0.f);
                }
            }
        }
    } else {
#pragma unroll
        for (int x = 0; x < 8; x++) {
            int gr = bm + tr + x;
            if (gr < M) {
#pragma unroll
                for (int y = 0; y < 8; y++) {
                    float v = acc[x][y];
                    if (bias) v += bias[tc + y];
                    C[(size_t)gr * 128 + tc + y] = v;
                }
            }
        }
    }
}

// ---------------- fused single-pass GAT aggregation ----------------
template <int NH, int HD, bool HAS_E>
__global__ void gat_fused(const int* __restrict__ rowptr, const int* __restrict__ psrc,
                          const float* __restrict__ pea,
                          const float* __restrict__ eW, const float* __restrict__ ae,
                          const float* __restrict__ ssrc, const float* __restrict__ sdst,
                          const float* __restrict__ z, const float* __restrict__ bias,
                          float* __restrict__ h, int n) {
    __shared__ float ce_s[NH];
    if (HAS_E && threadIdx.x < NH) {
        int hh = threadIdx.x;
        float s = 0.f;
#pragma unroll
        for (int d = 0; d < HD; d++) s += eW[hh * HD + d] * ae[hh * HD + d];
        ce_s[hh] = s;
    }
    if (HAS_E) __syncthreads();

    int node = blockIdx.x * 8 + (threadIdx.x >> 5);
    if (node >= n) return;
    int lane = threadIdx.x & 31;
    int c = lane * 4;
    int head = c / HD;

    float sd = sdst[(size_t)node * NH + head];
    float ce = HAS_E ? ce_s[head] : 0.f;

    float4 acc = make_float4(0.f, 0.f, 0.f, 0.f);
    float den = 0.f;
    int lo = rowptr[node], hi = rowptr[node + 1];
    for (int j = lo; j < hi; j++) {
        int s = psrc[j];
        float sc = ssrc[(size_t)s * NH + head] + sd;
        if (HAS_E) sc += pea[j] * ce;
        sc = sc > 0.f ? sc : 0.2f * sc;
        float ex = __expf(sc);
        den += ex;
        float4 zv = *(const float4*)(z + (size_t)s * HH + c);
        acc.x += ex * zv.x; acc.y += ex * zv.y;
        acc.z += ex * zv.z; acc.w += ex * zv.w;
    }
    float inv = 1.f / fmaxf(den, 1e-16f);
    float4 hv = *(const float4*)(h + (size_t)node * HH + c);
    float4 bv = *(const float4*)(bias + c);
    acc.x = hv.x + bv.x + acc.x * inv;
    acc.y = hv.y + bv.y + acc.y * inv;
    acc.z = hv.z + bv.z + acc.z * inv;
    acc.w = hv.w + bv.w + acc.w * inv;
    acc.x = acc.x > 0.f ? acc.x : __expf(acc.x) - 1.f;
    acc.y = acc.y > 0.f ? acc.y : __expf(acc.y) - 1.f;
    acc.z = acc.z > 0.f ? acc.z : __expf(acc.z) - 1.f;
    acc.w = acc.w > 0.f ? acc.w : __expf(acc.w) - 1.f;
    *(float4*)(h + (size_t)node * HH + c) = acc;
}

// ---------------- pooling -> padded cat rows (+ gfeat tail) ----------------
__global__ void pool_cat_k(const float* __restrict__ h, const int* __restrict__ nb,
                           const float* __restrict__ gf, const int* __restrict__ cid,
                           float* __restrict__ cat) {
    int b = blockIdx.x, t = threadIdx.x;
    int lo = 0, hi = TN;
    while (lo < hi) { int mid = (lo + hi) >> 1; if (nb[mid] < b) lo = mid + 1; else hi = mid; }
    int start = lo;
    hi = TN;
    while (lo < hi) { int mid = (lo + hi) >> 1; if (nb[mid] < b + 1) lo = mid + 1; else hi = mid; }
    int end = lo;
    float s = 0.f;
    for (int i = start; i < end; i++) s += h[(size_t)i * HH + t];
    cat[(size_t)b * CATP + t] = s / fmaxf((float)(end - start), 1.f);
    if (t < FGN)
        cat[(size_t)b * CATP + HH + t] = gf[(size_t)cid[b] * FGN + t];
}

// ---------------- LayerNorm(128) + ReLU, scattered to gx[cid] ----------------
__global__ void ln_relu_scat_k(const float* __restrict__ X, const float* __restrict__ g,
                               const float* __restrict__ be, const int* __restrict__ cid,
                               float* __restrict__ gx) {
    int row = blockIdx.x, t = threadIdx.x;
    float v = X[(size_t)row * HH + t];
    __shared__ float red[HH];
    red[t] = v; __syncthreads();
    for (int s = 64; s > 0; s >>= 1) { if (t < s) red[t] += red[t + s]; __syncthreads(); }
    float mean = red[0] / 128.f;
    __syncthreads();
    float dv = v - mean;
    red[t] = dv * dv; __syncthreads();
    for (int s = 64; s > 0; s >>= 1) { if (t < s) red[t] += red[t + s]; __syncthreads(); }
    float var = red[0] / 128.f;
    float y = dv * rsqrtf(var + 1e-5f) * g[t] + be[t];
    gx[(size_t)cid[row] * HH + t] = fmaxf(y, 0.f);
}

// ---------------- classifier: 8 contracts per block ----------------
__global__ __launch_bounds__(256)
void classifier_k(const float* __restrict__ gx, const int* __restrict__ cid,
                  const float* __restrict__ W1, const float* __restrict__ b1,
                  const float* __restrict__ W2, const float* __restrict__ b2,
                  float* __restrict__ out) {
    __shared__ float row[4][HH];
    __shared__ float hc[4][HCN];
    int tid = threadIdx.x;
    int grp = tid >> 6, t = tid & 63;
    for (int it = 0; it < 2; it++) {
        int b = blockIdx.x * 8 + it * 4 + grp;
        __syncthreads();
        const float* srcp = gx + (size_t)cid[b] * HH;
        row[grp][t] = srcp[t];
        row[grp][t + 64] = srcp[t + 64];
        __syncthreads();
        float s = b1[t];
#pragma unroll
        for (int k = 0; k < HH; k++) s += row[grp][k] * W1[k * HCN + t];
        hc[grp][t] = fmaxf(s, 0.f);
        __syncthreads();
        if (t < CC) {
            float s2 = b2[t];
#pragma unroll
            for (int k = 0; k < HCN; k++) s2 += hc[grp][k] * W2[k * CC + t];
            out[b * CC + t] = s2;
        }
    }
}

// ---------------- launch ----------------
extern "C" void kernel_launch(void* const* d_in, const int* in_sizes, int n_in,
                              void* d_out, int out_size) {
    const float* x_local    = (const float*)d_in[0];
    const float* eattr      = (const float*)d_in[1];
    const float* gfeat      = (const float*)d_in[2];
    const float* loc_in_W   = (const float*)d_in[3];
    const float* loc_in_b   = (const float*)d_in[4];
    const float* loc_W      = (const float*)d_in[5];
    const float* loc_asrc   = (const float*)d_in[6];
    const float* loc_adst   = (const float*)d_in[7];
    const float* loc_eW     = (const float*)d_in[8];
    const float* loc_ae     = (const float*)d_in[9];
    const float* loc_b      = (const float*)d_in[10];
    const float* fp_W       = (const float*)d_in[11];
    const float* fp_b       = (const float*)d_in[12];
    const float* fp_g       = (const float*)d_in[13];
    const float* fp_beta    = (const float*)d_in[14];
    const float* gp_W       = (const float*)d_in[15];
    const float* gp_b       = (const float*)d_in[16];
    const float* gp_g       = (const float*)d_in[17];
    const float* gp_beta    = (const float*)d_in[18];
    const float* glob_W     = (const float*)d_in[19];
    const float* glob_asrc  = (const float*)d_in[20];
    const float* glob_adst  = (const float*)d_in[21];
    const float* glob_b     = (const float*)d_in[22];
    const float* cls_W1     = (const float*)d_in[23];
    const float* cls_b1     = (const float*)d_in[24];
    const float* cls_W2     = (const float*)d_in[25];
    const float* cls_b2     = (const float*)d_in[26];
    const int*   eil        = (const int*)d_in[27];
    const int*   node_batch = (const int*)d_in[28];
    const int*   cid        = (const int*)d_in[29];
    const int*   gei        = (const int*)d_in[30];

    const int* lsrc = eil;
    const int* ldst = eil + ELN;
    const int* gsrc = gei;
    const int* gdst = gei + EGN;

    float *p_h, *p_z, *p_ssrc, *p_sdst;
    float *p_cat, *p_tmp, *p_gx, *p_gz, *p_pea, *p_wtf;
    int *p_deg, *p_rowptr, *p_fill, *p_psrc, *p_bsum;
    int *p_gdeg, *p_growptr, *p_gfill, *p_gpsrc, *p_gbsum;
    cudaGetSymbolAddress((void**)&p_h, g_h);
    cudaGetSymbolAddress((void**)&p_z, g_z);
    cudaGetSymbolAddress((void**)&p_ssrc, g_ssrc);
    cudaGetSymbolAddress((void**)&p_sdst, g_sdst);
    cudaGetSymbolAddress((void**)&p_cat, g_cat);
    cudaGetSymbolAddress((void**)&p_tmp, g_tmp);
    cudaGetSymbolAddress((void**)&p_gx, g_gx);
    cudaGetSymbolAddress((void**)&p_gz, g_gz);
    cudaGetSymbolAddress((void**)&p_pea, g_pea);
    cudaGetSymbolAddress((void**)&p_wtf, g_wtf);
    cudaGetSymbolAddress((void**)&p_deg, g_deg);
    cudaGetSymbolAddress((void**)&p_rowptr, g_rowptr);
    cudaGetSymbolAddress((void**)&p_fill, g_fill);
    cudaGetSymbolAddress((void**)&p_psrc, g_psrc);
    cudaGetSymbolAddress((void**)&p_bsum, g_bsum);
    cudaGetSymbolAddress((void**)&p_gdeg, g_gdeg);
    cudaGetSymbolAddress((void**)&p_growptr, g_growptr);
    cudaGetSymbolAddress((void**)&p_gfill, g_gfill);
    cudaGetSymbolAddress((void**)&p_gpsrc, g_gpsrc);
    cudaGetSymbolAddress((void**)&p_gbsum, g_gbsum);

    // dynamic smem opt-in for the MMA GEMMs (70KB)
    cudaFuncSetAttribute(gemm_mma<4>, cudaFuncAttributeMaxDynamicSharedMemorySize, SMEM_MMA);
    cudaFuncSetAttribute(gemm_mma<2>, cudaFuncAttributeMaxDynamicSharedMemorySize, SMEM_MMA);
    cudaFuncSetAttribute(gemm_mma<0>, cudaFuncAttributeMaxDynamicSharedMemorySize, SMEM_MMA);

    // ---- weight pre-rounding + deg zeroing ----
    wconv_k<<<CDIV(TN, 256), 256>>>(loc_W, fp_W, glob_W, p_wtf, p_deg, p_gdeg);

    // ---- input projection (K=4) ----
    gemm_tile<<<CDIV(TN, 128), 256>>>(x_local, loc_in_W, loc_in_b, p_h, TN, 4,
                                      nullptr, nullptr);

    // ---- CSR hist (both graphs) ----
    hist2_k<<<CDIV(ELN + EGN, 256), 256>>>(ldst, gdst, p_deg, p_gdeg);

    // ---- local layer 0 GEMM (+fused scores) — ncu capture slot #4 ----
    gemm_mma<4><<<CDIV(TN, 128), 256, SMEM_MMA>>>(p_h, p_wtf + WT_LOC0, nullptr, p_z,
                                                  TN, HH, HH,
                                                  loc_asrc, loc_adst, p_ssrc, p_sdst);

    scan1b_k<<<NBL + NBG, 256>>>(p_deg, p_gdeg, p_bsum, p_gbsum);
    scan2b_k<<<1, 32>>>(p_bsum, p_gbsum, p_rowptr, p_growptr);
    scan3b_k<<<NBL + NBG, 256>>>(p_deg, p_gdeg, p_bsum, p_gbsum,
                                 p_rowptr, p_growptr, p_fill, p_gfill);
    scatedge2_k<<<CDIV(ELN + EGN, 256), 256>>>(lsrc, ldst, gsrc, gdst, eattr,
                                               p_fill, p_gfill, p_psrc, p_pea, p_gpsrc);

    // ---- local layer 0 aggregate ----
    gat_fused<4, 32, true><<<CDIV(TN, 8), 256>>>(p_rowptr, p_psrc, p_pea,
                                                 loc_eW, loc_ae,
                                                 p_ssrc, p_sdst, p_z, loc_b, p_h, TN);
    // ---- local layer 1 ----
    gemm_mma<4><<<CDIV(TN, 128), 256, SMEM_MMA>>>(p_h, p_wtf + WT_LOC1, nullptr, p_z,
                                                  TN, HH, HH,
                                                  loc_asrc + HH, loc_adst + HH,
                                                  p_ssrc, p_sdst);
    gat_fused<4, 32, true><<<CDIV(TN, 8), 256>>>(p_rowptr, p_psrc, p_pea,
                                                 loc_eW + HH, loc_ae + HH,
                                                 p_ssrc, p_sdst, p_z, loc_b + HH, p_h, TN);

    // ---- pooling straight into padded cat rows ----
    pool_cat_k<<<BB, 128>>>(p_h, node_batch, gfeat, cid, p_cat);

    // ---- fused MLP ----
    gemm_mma<0><<<CDIV(BB, 128), 256, SMEM_MMA>>>(p_cat, p_wtf + WT_FP, fp_b, p_tmp,
                                                  BB, HH + FGN, CATP,
                                                  nullptr, nullptr, nullptr, nullptr);

    // ---- global projection (all N, fused LN+ReLU), then LN+scatter of fused rows ----
    gemm_tile<<<CDIV(NNODE, 128), 256>>>(gfeat, gp_W, gp_b, p_gx, NNODE, FGN,
                                         gp_g, gp_beta);
    ln_relu_scat_k<<<BB, HH>>>(p_tmp, fp_g, fp_beta, cid, p_gx);

    // ---- 2x global GATConv ----
    for (int l = 0; l < 2; l++) {
        gemm_mma<2><<<CDIV(NNODE, 128), 256, SMEM_MMA>>>(p_gx,
                                              p_wtf + (l == 0 ? WT_G0 : WT_G1), nullptr,
                                              p_gz, NNODE, HH, HH,
                                              glob_asrc + l * HH, glob_adst + l * HH,
                                              p_ssrc, p_sdst);
        gat_fused<2, 64, false><<<CDIV(NNODE, 8), 256>>>(p_growptr, p_gpsrc, (float*)nullptr,
                                                         (float*)nullptr, (float*)nullptr,
                                                         p_ssrc, p_sdst, p_gz,
                                                         glob_b + l * HH, p_gx, NNODE);
    }

    // ---- classifier ----
    classifier_k<<<CDIV(BB, 8), 256>>>(p_gx, cid, cls_W1, cls_b1, cls_W2, cls_b2,
                                       (float*)d_out);
}

// round 14
// speedup vs baseline: 1.5746x; 1.0923x over previous
#include <cuda_runtime.h>
#include <math.h>

// ---------------- problem constants ----------------
#define TN    131072     // local tx nodes
#define ELN   524288     // local edges
#define NNODE 50000      // global contract nodes
#define EGN   400000     // global edges
#define BB    8192       // batch of contracts
#define HH    128        // hidden dim
#define FGN   7          // global feat dim
#define HCN   64         // classifier hidden
#define CC    2          // classes
#define CATP  144        // padded concat row stride (16B multiple)

#define CDIV(a,b) (((a)+(b)-1)/(b))
#define NBL  CDIV(TN, 1024)
#define NBG  CDIV(NNODE, 1024)

// pre-rounded weight buffer offsets (floats)
#define WT_LOC0 0
#define WT_LOC1 16384
#define WT_FP   32768
#define WT_G0   50048
#define WT_G1   66432
#define WT_TOT  82816

// ---------------- scratch (device globals) ----------------
__device__ float g_h   [TN*HH];
__device__ float g_z   [TN*HH];
__device__ float g_ssrc[TN*4];
__device__ float g_sdst[TN*4];
__device__ float g_cat [BB*CATP];
__device__ float g_tmp [BB*HH];
__device__ float g_gx  [NNODE*HH];
__device__ float g_gz  [NNODE*HH];
__device__ float g_wtf [WT_TOT];
// CSR scratch
__device__ int   g_deg   [TN];
__device__ int   g_rowptr[TN+1];
__device__ int   g_fill  [TN];
__device__ int   g_psrc  [ELN];
__device__ float g_pea   [ELN];
__device__ int   g_bsum  [256];
__device__ int   g_gdeg   [NNODE];
__device__ int   g_growptr[NNODE+1];
__device__ int   g_gfill  [NNODE];
__device__ int   g_gpsrc  [EGN];
__device__ int   g_gbsum  [256];

// ---------------- helpers ----------------
__device__ __forceinline__ unsigned f2tf32(float f) {
    unsigned r;
    asm("cvt.rna.tf32.f32 %0, %1;" : "=r"(r) : "f"(f));
    return r;
}
__device__ __forceinline__ void cp_async16(unsigned dst, const void* src, int bytes) {
    asm volatile("cp.async.cg.shared.global [%0], [%1], 16, %2;"
                 :: "r"(dst), "l"(src), "r"(bytes) : "memory");
}
__device__ __forceinline__ void cp_commit() {
    asm volatile("cp.async.commit_group;" ::: "memory");
}
__device__ __forceinline__ void cp_wait0() {
    asm volatile("cp.async.wait_group 0;" ::: "memory");
}

// ---------------- weight pre-rounding + deg zeroing ----------
__global__ void wconv_k(const float* __restrict__ locW, const float* __restrict__ fpW,
                        const float* __restrict__ globW, float* __restrict__ wt,
                        int* __restrict__ deg, int* __restrict__ gdeg) {
    int i = blockIdx.x * blockDim.x + threadIdx.x;
    if (i < 32768)       wt[i] = __uint_as_float(f2tf32(locW[i]));
    else if (i < 50048)  wt[i] = __uint_as_float(f2tf32(fpW[i - 32768]));
    else if (i < WT_TOT) wt[i] = __uint_as_float(f2tf32(globW[i - 50048]));
    if (i < TN)    deg[i]  = 0;
    if (i < NNODE) gdeg[i] = 0;
}

// ================= CSR construction (both graphs fused) =================
__global__ void hist2_k(const int* __restrict__ ldst, const int* __restrict__ gdst,
                        int* __restrict__ deg, int* __restrict__ gdeg) {
    int e = blockIdx.x * blockDim.x + threadIdx.x;
    if (e < ELN) atomicAdd(&deg[ldst[e]], 1);
    else if (e < ELN + EGN) atomicAdd(&gdeg[gdst[e - ELN]], 1);
}
__global__ void scan1b_k(const int* __restrict__ deg, const int* __restrict__ gdeg,
                         int* __restrict__ bsum, int* __restrict__ gbsum) {
    __shared__ int s[256];
    int t = threadIdx.x;
    bool loc = blockIdx.x < NBL;
    const int* d = loc ? deg : gdeg;
    int n = loc ? TN : NNODE;
    int base = (loc ? blockIdx.x : blockIdx.x - NBL) * 1024;
    int sum = 0;
#pragma unroll
    for (int i = 0; i < 4; i++) {
        int idx = base + t * 4 + i;
        if (idx < n) sum += d[idx];
    }
    s[t] = sum; __syncthreads();
    for (int o = 128; o > 0; o >>= 1) { if (t < o) s[t] += s[t + o]; __syncthreads(); }
    if (t == 0) (loc ? bsum : gbsum)[loc ? blockIdx.x : blockIdx.x - NBL] = s[0];
}
__global__ void scan2b_k(int* __restrict__ bsum, int* __restrict__ gbsum,
                         int* __restrict__ rowptr, int* __restrict__ growptr) {
    if (threadIdx.x == 0) {
        int acc = 0;
        for (int i = 0; i < NBL; i++) { int v = bsum[i]; bsum[i] = acc; acc += v; }
        rowptr[TN] = ELN;
    } else if (threadIdx.x == 1) {
        int acc = 0;
        for (int i = 0; i < NBG; i++) { int v = gbsum[i]; gbsum[i] = acc; acc += v; }
        growptr[NNODE] = EGN;
    }
}
__global__ void scan3b_k(const int* __restrict__ deg, const int* __restrict__ gdeg,
                         const int* __restrict__ bsum, const int* __restrict__ gbsum,
                         int* __restrict__ rowptr, int* __restrict__ growptr,
                         int* __restrict__ fill, int* __restrict__ gfill) {
    __shared__ int s[256];
    int t = threadIdx.x;
    bool loc = blockIdx.x < NBL;
    const int* d = loc ? deg : gdeg;
    const int* bs = loc ? bsum : gbsum;
    int* rp = loc ? rowptr : growptr;
    int* fl = loc ? fill : gfill;
    int n = loc ? TN : NNODE;
    int bid = loc ? blockIdx.x : blockIdx.x - NBL;
    int base = bid * 1024;
    int v[4]; int sum = 0;
#pragma unroll
    for (int i = 0; i < 4; i++) {
        int idx = base + t * 4 + i;
        v[i] = (idx < n) ? d[idx] : 0;
        sum += v[i];
    }
    s[t] = sum; __syncthreads();
    for (int o = 1; o < 256; o <<= 1) {
        int x = (t >= o) ? s[t - o] : 0;
        __syncthreads();
        s[t] += x;
        __syncthreads();
    }
    int excl = ((t == 0) ? 0 : s[t - 1]) + bs[bid];
#pragma unroll
    for (int i = 0; i < 4; i++) {
        int idx = base + t * 4 + i;
        if (idx < n) { rp[idx] = excl; fl[idx] = excl; }
        excl += v[i];
    }
}
__global__ void scatedge2_k(const int* __restrict__ lsrc, const int* __restrict__ ldst,
                            const int* __restrict__ gsrc, const int* __restrict__ gdst,
                            const float* __restrict__ eattr,
                            int* __restrict__ fill, int* __restrict__ gfill,
                            int* __restrict__ psrc, float* __restrict__ pea,
                            int* __restrict__ gpsrc) {
    int e = blockIdx.x * blockDim.x + threadIdx.x;
    if (e < ELN) {
        int p = atomicAdd(&fill[ldst[e]], 1);
        psrc[p] = lsrc[e];
        pea[p] = eattr[e];
    } else if (e < ELN + EGN) {
        int ee = e - ELN;
        int p = atomicAdd(&gfill[gdst[ee]], 1);
        gpsrc[p] = gsrc[ee];
    }
}

// ================= tf32 MMA GEMM: BM=128, BK=32, 2-stage cp.async ===============
// IP=true: first compute h = x@Win + bin for this block's rows, store to hout
// (=A), fence, then run the standard pipeline reading A from L2.
#define APAD 36
#define WPAD 136
#define ABUF (128 * APAD)
#define WBUF (32 * WPAD)
#define SMEM_MMA ((2 * ABUF + 2 * WBUF) * 4)   // 71680 bytes
template <int NH, bool IP>
__global__ __launch_bounds__(256, 2)
void gemm_mma(const float* __restrict__ A, const float* __restrict__ W,
              const float* __restrict__ bias, float* __restrict__ C,
              int M, int K, int lda,
              const float* __restrict__ asrc, const float* __restrict__ adst,
              float* __restrict__ ssrc, float* __restrict__ sdst,
              const float* __restrict__ x, const float* __restrict__ Win,
              const float* __restrict__ binp, float* __restrict__ hout) {
    extern __shared__ __align__(16) float smem[];
    float* As = smem;
    float* Ws = smem + 2 * ABUF;
    const int tid  = threadIdx.x;
    const int warp = tid >> 5, lane = tid & 31;
    const int bm   = blockIdx.x * 128;
    const int wm   = (warp >> 1) * 32;
    const int wn   = (warp & 1) * 64;
    const int g    = lane >> 2;
    const int ct   = lane & 3;
    const int nk   = (K + 31) / 32;

    if (IP) {
        // input projection prologue: h_tile = x_tile(128x4) @ Win(4x128) + bin
        float* xs   = As;        // 512 floats
        float* WinS = Ws;        // 512 floats
        float* binS = Ws + 512;  // 128 floats
        for (int i = tid; i < 512; i += 256) {
            int m = i >> 2, j = i & 3;
            int gr = bm + m;
            xs[i] = (gr < M) ? x[(size_t)gr * 4 + j] : 0.f;
            WinS[i] = Win[i];
        }
        if (tid < 128) binS[tid] = binp[tid];
        __syncthreads();
        for (int i = tid; i < 128 * 128; i += 256) {
            int m = i >> 7, k = i & 127;
            float v = binS[k]
                    + xs[m * 4 + 0] * WinS[k]
                    + xs[m * 4 + 1] * WinS[128 + k]
                    + xs[m * 4 + 2] * WinS[256 + k]
                    + xs[m * 4 + 3] * WinS[384 + k];
            int gr = bm + m;
            if (gr < M) hout[(size_t)gr * 128 + k] = v;
        }
        __threadfence();      // make h visible in L2 before cp.async (L1-bypass) reads
        __syncthreads();
    }

    const unsigned asb = (unsigned)__cvta_generic_to_shared(As);
    const unsigned wsb = (unsigned)__cvta_generic_to_shared(Ws);

    float c[2][8][4];
#pragma unroll
    for (int mt = 0; mt < 2; mt++)
#pragma unroll
        for (int nt = 0; nt < 8; nt++)
#pragma unroll
            for (int r = 0; r < 4; r++) c[mt][nt][r] = 0.f;

    auto issue = [&](int buf, int t) {
        int k0 = t * 32;
#pragma unroll
        for (int j = 0; j < 4; j++) {
            int id = tid + 256 * j;
            int m = id >> 3, kq = (id & 7) * 4;
            int gr = bm + m, gk = k0 + kq;
            int bytes = 0;
            const float* src = A;
            if (gr < M && gk < K) {
                int rem = K - gk;
                bytes = rem >= 4 ? 16 : rem * 4;
                src = A + (size_t)gr * lda + gk;
            }
            cp_async16(asb + (unsigned)(buf * ABUF + m * APAD + kq) * 4u, src, bytes);
        }
#pragma unroll
        for (int j = 0; j < 4; j++) {
            int id = tid + 256 * j;
            int k = id >> 5, nq = (id & 31) * 4;
            int gk = k0 + k;
            int bytes = (gk < K) ? 16 : 0;
            const float* src = (gk < K) ? (W + (size_t)gk * 128 + nq) : W;
            cp_async16(wsb + (unsigned)(buf * WBUF + k * WPAD + nq) * 4u, src, bytes);
        }
        cp_commit();
    };

    issue(0, 0);

    for (int t = 0; t < nk; t++) {
        cp_wait0();
        __syncthreads();
        if (t + 1 < nk) issue((t + 1) & 1, t + 1);

        const float* Ab = As + (t & 1) * ABUF;
        const unsigned* Wb = (const unsigned*)(Ws + (t & 1) * WBUF);
#pragma unroll
        for (int ks = 0; ks < 32; ks += 8) {
            unsigned b[8][2];
#pragma unroll
            for (int nt = 0; nt < 8; nt++) {
                int n = wn + nt * 8 + g;
                b[nt][0] = Wb[(ks + ct) * WPAD + n];
                b[nt][1] = Wb[(ks + ct + 4) * WPAD + n];
            }
#pragma unroll
            for (int mt = 0; mt < 2; mt++) {
                int r0 = wm + mt * 16 + g;
                unsigned a0 = f2tf32(Ab[r0 * APAD + ks + ct]);
                unsigned a1 = f2tf32(Ab[(r0 + 8) * APAD + ks + ct]);
                unsigned a2 = f2tf32(Ab[r0 * APAD + ks + ct + 4]);
                unsigned a3 = f2tf32(Ab[(r0 + 8) * APAD + ks + ct + 4]);
#pragma unroll
                for (int nt = 0; nt < 8; nt++) {
                    asm volatile(
                        "mma.sync.aligned.m16n8k8.row.col.f32.tf32.tf32.f32 "
                        "{%0,%1,%2,%3}, {%4,%5,%6,%7}, {%8,%9}, {%0,%1,%2,%3};"
                        : "+f"(c[mt][nt][0]), "+f"(c[mt][nt][1]),
                          "+f"(c[mt][nt][2]), "+f"(c[mt][nt][3])
                        : "r"(a0), "r"(a1), "r"(a2), "r"(a3),
                          "r"(b[nt][0]), "r"(b[nt][1]));
                }
            }
        }
        __syncthreads();
    }

    // epilogue: store C (+bias) and optionally fused attention scores
    const int NH2 = (NH == 4) ? 2 : 1;
    float ps[2][2][2], pd[2][2][2];
    if (NH > 0) {
#pragma unroll
        for (int a = 0; a < 2; a++)
#pragma unroll
            for (int b2 = 0; b2 < 2; b2++)
#pragma unroll
                for (int d = 0; d < 2; d++) { ps[a][b2][d] = 0.f; pd[a][b2][d] = 0.f; }
    }
#pragma unroll
    for (int mt = 0; mt < 2; mt++) {
        int row0 = bm + wm + mt * 16 + g;
        int row1 = row0 + 8;
#pragma unroll
        for (int nt = 0; nt < 8; nt++) {
            int col = wn + nt * 8 + 2 * ct;
            float b0 = bias ? bias[col] : 0.f;
            float b1 = bias ? bias[col + 1] : 0.f;
            float v00 = c[mt][nt][0] + b0, v01 = c[mt][nt][1] + b1;
            float v10 = c[mt][nt][2] + b0, v11 = c[mt][nt][3] + b1;
            if (row0 < M) *(float2*)(C + (size_t)row0 * 128 + col) = make_float2(v00, v01);
            if (row1 < M) *(float2*)(C + (size_t)row1 * 128 + col) = make_float2(v10, v11);
            if (NH > 0) {
                float a0s = asrc[col], a1s = asrc[col + 1];
                float a0d = adst[col], a1d = adst[col + 1];
                int h2 = (NH == 4) ? (nt >> 2) : 0;
                ps[mt][0][h2] += v00 * a0s + v01 * a1s;
                ps[mt][1][h2] += v10 * a0s + v11 * a1s;
                pd[mt][0][h2] += v00 * a0d + v01 * a1d;
                pd[mt][1][h2] += v10 * a0d + v11 * a1d;
            }
        }
    }
    if (NH > 0) {
#pragma unroll
        for (int mt = 0; mt < 2; mt++)
#pragma unroll
            for (int rh = 0; rh < 2; rh++)
#pragma unroll
                for (int h2 = 0; h2 < NH2; h2++) {
                    float s = ps[mt][rh][h2], d = pd[mt][rh][h2];
                    s += __shfl_xor_sync(0xffffffffu, s, 1);
                    s += __shfl_xor_sync(0xffffffffu, s, 2);
                    d += __shfl_xor_sync(0xffffffffu, d, 1);
                    d += __shfl_xor_sync(0xffffffffu, d, 2);
                    ps[mt][rh][h2] = s; pd[mt][rh][h2] = d;
                }
        if (ct == 0) {
            int headbase = (wn * NH) >> 7;
#pragma unroll
            for (int mt = 0; mt < 2; mt++)
#pragma unroll
                for (int rh = 0; rh < 2; rh++) {
                    int row = bm + wm + mt * 16 + g + rh * 8;
                    if (row < M) {
#pragma unroll
                        for (int h2 = 0; h2 < NH2; h2++) {
                            int head = headbase + h2;
                            ssrc[(size_t)row * NH + head] = ps[mt][rh][h2];
                            sdst[(size_t)row * NH + head] = pd[mt][rh][h2];
                        }
                    }
                }
        }
    }
}

// ---------------- SIMT GEMM for tiny-K projections (+optional fused LN+ReLU) --------
__global__ __launch_bounds__(256, 2)
void gemm_tile(const float* __restrict__ A, const float* __restrict__ W,
               const float* __restrict__ bias, float* __restrict__ C,
               int M, int K,
               const float* __restrict__ gamma, const float* __restrict__ beta) {
    __shared__ float As[16 * 132];
    __shared__ float Ws[16 * 132];
    const int bm  = blockIdx.x * 128;
    const int tid = threadIdx.x;
    const int tr  = (tid >> 4) * 8;
    const int tc  = (tid & 15) * 8;
    float acc[8][8];
#pragma unroll
    for (int x = 0; x < 8; x++)
#pragma unroll
        for (int y = 0; y < 8; y++) acc[x][y] = 0.f;

    for (int k0 = 0; k0 < K; k0 += 16) {
        for (int i = tid; i < 128 * 16; i += 256) {
            int m = i >> 4, kk = i & 15;
            int gr = bm + m, gk = k0 + kk;
            As[kk * 132 + m] = (gr < M && gk < K) ? A[(size_t)gr * K + gk] : 0.f;
        }
        for (int i = tid; i < 16 * 128; i += 256) {
            int kk = i >> 7, n = i & 127;
            int gk = k0 + kk;
            Ws[kk * 132 + n] = (gk < K) ? W[gk * 128 + n] : 0.f;
        }
        __syncthreads();
#pragma unroll
        for (int kk = 0; kk < 16; kk++) {
            float a[8], w[8];
#pragma unroll
            for (int x = 0; x < 8; x++) a[x] = As[kk * 132 + tr + x];
#pragma unroll
            for (int y = 0; y < 8; y++) w[y] = Ws[kk * 132 + tc + y];
#pragma unroll
            for (int x = 0; x < 8; x++)
#pragma unroll
                for (int y = 0; y < 8; y++) acc[x][y] += a[x] * w[y];
        }
        __syncthreads();
    }

    if (gamma) {
#pragma unroll
        for (int x = 0; x < 8; x++) {
            int gr = bm + tr + x;
            float vv[8]; float sum = 0.f;
#pragma unroll
            for (int y = 0; y < 8; y++) {
                vv[y] = acc[x][y] + (bias ? bias[tc + y] : 0.f);
                sum += vv[y];
            }
#pragma unroll
            for (int k = 1; k < 16; k <<= 1) sum += __shfl_xor_sync(0xffffffffu, sum, k, 16);
            float mean = sum * (1.f / 128.f);
            float sq = 0.f;
#pragma unroll
            for (int y = 0; y < 8; y++) { float d = vv[y] - mean; sq += d * d; }
#pragma unroll
            for (int k = 1; k < 16; k <<= 1) sq += __shfl_xor_sync(0xffffffffu, sq, k, 16);
            float rstd = rsqrtf(sq * (1.f / 128.f) + 1e-5f);
            if (gr < M) {
#pragma unroll
                for (int y = 0; y < 8; y++) {
                    float yv = (vv[y] - mean) * rstd * gamma[tc + y] + beta[tc + y];
                    C[(size_t)gr * 128 + tc + y] = fmaxf(yv, 0.f);
                }
            }
        }
    } else {
#pragma unroll
        for (int x = 0; x < 8; x++) {
            int gr = bm + tr + x;
            if (gr < M) {
#pragma unroll
                for (int y = 0; y < 8; y++) {
                    float v = acc[x][y];
                    if (bias) v += bias[tc + y];
                    C[(size_t)gr * 128 + tc + y] = v;
                }
            }
        }
    }
}

// ---------------- fused single-pass GAT aggregation ----------------
template <int NH, int HD, bool HAS_E>
__global__ void gat_fused(const int* __restrict__ rowptr, const int* __restrict__ psrc,
                          const float* __restrict__ pea,
                          const float* __restrict__ eW, const float* __restrict__ ae,
                          const float* __restrict__ ssrc, const float* __restrict__ sdst,
                          const float* __restrict__ z, const float* __restrict__ bias,
                          float* __restrict__ h, int n) {
    __shared__ float ce_s[NH];
    if (HAS_E && threadIdx.x < NH) {
        int hh = threadIdx.x;
        float s = 0.f;
#pragma unroll
        for (int d = 0; d < HD; d++) s += eW[hh * HD + d] * ae[hh * HD + d];
        ce_s[hh] = s;
    }
    if (HAS_E) __syncthreads();

    int node = blockIdx.x * 8 + (threadIdx.x >> 5);
    if (node >= n) return;
    int lane = threadIdx.x & 31;
    int c = lane * 4;
    int head = c / HD;

    float sd = sdst[(size_t)node * NH + head];
    float ce = HAS_E ? ce_s[head] : 0.f;

    float4 acc = make_float4(0.f, 0.f, 0.f, 0.f);
    float den = 0.f;
    int lo = rowptr[node], hi = rowptr[node + 1];
    for (int j = lo; j < hi; j++) {
        int s = psrc[j];
        float sc = ssrc[(size_t)s * NH + head] + sd;
        if (HAS_E) sc += pea[j] * ce;
        sc = sc > 0.f ? sc : 0.2f * sc;
        float ex = __expf(sc);
        den += ex;
        float4 zv = *(const float4*)(z + (size_t)s * HH + c);
        acc.x += ex * zv.x; acc.y += ex * zv.y;
        acc.z += ex * zv.z; acc.w += ex * zv.w;
    }
    float inv = 1.f / fmaxf(den, 1e-16f);
    float4 hv = *(const float4*)(h + (size_t)node * HH + c);
    float4 bv = *(const float4*)(bias + c);
    acc.x = hv.x + bv.x + acc.x * inv;
    acc.y = hv.y + bv.y + acc.y * inv;
    acc.z = hv.z + bv.z + acc.z * inv;
    acc.w = hv.w + bv.w + acc.w * inv;
    acc.x = acc.x > 0.f ? acc.x : __expf(acc.x) - 1.f;
    acc.y = acc.y > 0.f ? acc.y : __expf(acc.y) - 1.f;
    acc.z = acc.z > 0.f ? acc.z : __expf(acc.z) - 1.f;
    acc.w = acc.w > 0.f ? acc.w : __expf(acc.w) - 1.f;
    *(float4*)(h + (size_t)node * HH + c) = acc;
}

// ---------------- pooling -> padded cat rows (+ gfeat tail) ----------------
__global__ void pool_cat_k(const float* __restrict__ h, const int* __restrict__ nb,
                           const float* __restrict__ gf, const int* __restrict__ cid,
                           float* __restrict__ cat) {
    int b = blockIdx.x, t = threadIdx.x;
    int lo = 0, hi = TN;
    while (lo < hi) { int mid = (lo + hi) >> 1; if (nb[mid] < b) lo = mid + 1; else hi = mid; }
    int start = lo;
    hi = TN;
    while (lo < hi) { int mid = (lo + hi) >> 1; if (nb[mid] < b + 1) lo = mid + 1; else hi = mid; }
    int end = lo;
    float s = 0.f;
    for (int i = start; i < end; i++) s += h[(size_t)i * HH + t];
    cat[(size_t)b * CATP + t] = s / fmaxf((float)(end - start), 1.f);
    if (t < FGN)
        cat[(size_t)b * CATP + HH + t] = gf[(size_t)cid[b] * FGN + t];
}

// ---------------- LayerNorm(128) + ReLU, scattered to gx[cid] ----------------
__global__ void ln_relu_scat_k(const float* __restrict__ X, const float* __restrict__ g,
                               const float* __restrict__ be, const int* __restrict__ cid,
                               float* __restrict__ gx) {
    int row = blockIdx.x, t = threadIdx.x;
    float v = X[(size_t)row * HH + t];
    __shared__ float red[HH];
    red[t] = v; __syncthreads();
    for (int s = 64; s > 0; s >>= 1) { if (t < s) red[t] += red[t + s]; __syncthreads(); }
    float mean = red[0] / 128.f;
    __syncthreads();
    float dv = v - mean;
    red[t] = dv * dv; __syncthreads();
    for (int s = 64; s > 0; s >>= 1) { if (t < s) red[t] += red[t + s]; __syncthreads(); }
    float var = red[0] / 128.f;
    float y = dv * rsqrtf(var + 1e-5f) * g[t] + be[t];
    gx[(size_t)cid[row] * HH + t] = fmaxf(y, 0.f);
}

// ---------------- classifier: 8 contracts per block ----------------
__global__ __launch_bounds__(256)
void classifier_k(const float* __restrict__ gx, const int* __restrict__ cid,
                  const float* __restrict__ W1, const float* __restrict__ b1,
                  const float* __restrict__ W2, const float* __restrict__ b2,
                  float* __restrict__ out) {
    __shared__ float row[4][HH];
    __shared__ float hc[4][HCN];
    int tid = threadIdx.x;
    int grp = tid >> 6, t = tid & 63;
    for (int it = 0; it < 2; it++) {
        int b = blockIdx.x * 8 + it * 4 + grp;
        __syncthreads();
        const float* srcp = gx + (size_t)cid[b] * HH;
        row[grp][t] = srcp[t];
        row[grp][t + 64] = srcp[t + 64];
        __syncthreads();
        float s = b1[t];
#pragma unroll
        for (int k = 0; k < HH; k++) s += row[grp][k] * W1[k * HCN + t];
        hc[grp][t] = fmaxf(s, 0.f);
        __syncthreads();
        if (t < CC) {
            float s2 = b2[t];
#pragma unroll
            for (int k = 0; k < HCN; k++) s2 += hc[grp][k] * W2[k * CC + t];
            out[b * CC + t] = s2;
        }
    }
}

// ---------------- launch ----------------
extern "C" void kernel_launch(void* const* d_in, const int* in_sizes, int n_in,
                              void* d_out, int out_size) {
    const float* x_local    = (const float*)d_in[0];
    const float* eattr      = (const float*)d_in[1];
    const float* gfeat      = (const float*)d_in[2];
    const float* loc_in_W   = (const float*)d_in[3];
    const float* loc_in_b   = (const float*)d_in[4];
    const float* loc_W      = (const float*)d_in[5];
    const float* loc_asrc   = (const float*)d_in[6];
    const float* loc_adst   = (const float*)d_in[7];
    const float* loc_eW     = (const float*)d_in[8];
    const float* loc_ae     = (const float*)d_in[9];
    const float* loc_b      = (const float*)d_in[10];
    const float* fp_W       = (const float*)d_in[11];
    const float* fp_b       = (const float*)d_in[12];
    const float* fp_g       = (const float*)d_in[13];
    const float* fp_beta    = (const float*)d_in[14];
    const float* gp_W       = (const float*)d_in[15];
    const float* gp_b       = (const float*)d_in[16];
    const float* gp_g       = (const float*)d_in[17];
    const float* gp_beta    = (const float*)d_in[18];
    const float* glob_W     = (const float*)d_in[19];
    const float* glob_asrc  = (const float*)d_in[20];
    const float* glob_adst  = (const float*)d_in[21];
    const float* glob_b     = (const float*)d_in[22];
    const float* cls_W1     = (const float*)d_in[23];
    const float* cls_b1     = (const float*)d_in[24];
    const float* cls_W2     = (const float*)d_in[25];
    const float* cls_b2     = (const float*)d_in[26];
    const int*   eil        = (const int*)d_in[27];
    const int*   node_batch = (const int*)d_in[28];
    const int*   cid        = (const int*)d_in[29];
    const int*   gei        = (const int*)d_in[30];

    const int* lsrc = eil;
    const int* ldst = eil + ELN;
    const int* gsrc = gei;
    const int* gdst = gei + EGN;

    float *p_h, *p_z, *p_ssrc, *p_sdst;
    float *p_cat, *p_tmp, *p_gx, *p_gz, *p_pea, *p_wtf;
    int *p_deg, *p_rowptr, *p_fill, *p_psrc, *p_bsum;
    int *p_gdeg, *p_growptr, *p_gfill, *p_gpsrc, *p_gbsum;
    cudaGetSymbolAddress((void**)&p_h, g_h);
    cudaGetSymbolAddress((void**)&p_z, g_z);
    cudaGetSymbolAddress((void**)&p_ssrc, g_ssrc);
    cudaGetSymbolAddress((void**)&p_sdst, g_sdst);
    cudaGetSymbolAddress((void**)&p_cat, g_cat);
    cudaGetSymbolAddress((void**)&p_tmp, g_tmp);
    cudaGetSymbolAddress((void**)&p_gx, g_gx);
    cudaGetSymbolAddress((void**)&p_gz, g_gz);
    cudaGetSymbolAddress((void**)&p_pea, g_pea);
    cudaGetSymbolAddress((void**)&p_wtf, g_wtf);
    cudaGetSymbolAddress((void**)&p_deg, g_deg);
    cudaGetSymbolAddress((void**)&p_rowptr, g_rowptr);
    cudaGetSymbolAddress((void**)&p_fill, g_fill);
    cudaGetSymbolAddress((void**)&p_psrc, g_psrc);
    cudaGetSymbolAddress((void**)&p_bsum, g_bsum);
    cudaGetSymbolAddress((void**)&p_gdeg, g_gdeg);
    cudaGetSymbolAddress((void**)&p_growptr, g_growptr);
    cudaGetSymbolAddress((void**)&p_gfill, g_gfill);
    cudaGetSymbolAddress((void**)&p_gpsrc, g_gpsrc);
    cudaGetSymbolAddress((void**)&p_gbsum, g_gbsum);

    // dynamic smem opt-in
    cudaFuncSetAttribute((const void*)gemm_mma<4, true>,
                         cudaFuncAttributeMaxDynamicSharedMemorySize, SMEM_MMA);
    cudaFuncSetAttribute((const void*)gemm_mma<4, false>,
                         cudaFuncAttributeMaxDynamicSharedMemorySize, SMEM_MMA);
    cudaFuncSetAttribute((const void*)gemm_mma<2, false>,
                         cudaFuncAttributeMaxDynamicSharedMemorySize, SMEM_MMA);
    cudaFuncSetAttribute((const void*)gemm_mma<0, false>,
                         cudaFuncAttributeMaxDynamicSharedMemorySize, SMEM_MMA);

    // ---- weight pre-rounding + deg zeroing ----
    wconv_k<<<CDIV(TN, 256), 256>>>(loc_W, fp_W, glob_W, p_wtf, p_deg, p_gdeg);

    // ---- CSR hist (both graphs) ----
    hist2_k<<<CDIV(ELN + EGN, 256), 256>>>(ldst, gdst, p_deg, p_gdeg);
    scan1b_k<<<NBL + NBG, 256>>>(p_deg, p_gdeg, p_bsum, p_gbsum);

    // ---- local layer 0: fused input projection + GEMM (+scores) — ncu slot #4 ----
    gemm_mma<4, true><<<CDIV(TN, 128), 256, SMEM_MMA>>>(
        p_h, p_wtf + WT_LOC0, nullptr, p_z, TN, HH, HH,
        loc_asrc, loc_adst, p_ssrc, p_sdst,
        x_local, loc_in_W, loc_in_b, p_h);

    scan2b_k<<<1, 32>>>(p_bsum, p_gbsum, p_rowptr, p_growptr);
    scan3b_k<<<NBL + NBG, 256>>>(p_deg, p_gdeg, p_bsum, p_gbsum,
                                 p_rowptr, p_growptr, p_fill, p_gfill);
    scatedge2_k<<<CDIV(ELN + EGN, 256), 256>>>(lsrc, ldst, gsrc, gdst, eattr,
                                               p_fill, p_gfill, p_psrc, p_pea, p_gpsrc);

    // ---- local layer 0 aggregate ----
    gat_fused<4, 32, true><<<CDIV(TN, 8), 256>>>(p_rowptr, p_psrc, p_pea,
                                                 loc_eW, loc_ae,
                                                 p_ssrc, p_sdst, p_z, loc_b, p_h, TN);
    // ---- local layer 1 ----
    gemm_mma<4, false><<<CDIV(TN, 128), 256, SMEM_MMA>>>(
        p_h, p_wtf + WT_LOC1, nullptr, p_z, TN, HH, HH,
        loc_asrc + HH, loc_adst + HH, p_ssrc, p_sdst,
        nullptr, nullptr, nullptr, nullptr);
    gat_fused<4, 32, true><<<CDIV(TN, 8), 256>>>(p_rowptr, p_psrc, p_pea,
                                                 loc_eW + HH, loc_ae + HH,
                                                 p_ssrc, p_sdst, p_z, loc_b + HH, p_h, TN);

    // ---- pooling straight into padded cat rows ----
    pool_cat_k<<<BB, 128>>>(p_h, node_batch, gfeat, cid, p_cat);

    // ---- fused MLP ----
    gemm_mma<0, false><<<CDIV(BB, 128), 256, SMEM_MMA>>>(
        p_cat, p_wtf + WT_FP, fp_b, p_tmp, BB, HH + FGN, CATP,
        nullptr, nullptr, nullptr, nullptr,
        nullptr, nullptr, nullptr, nullptr);

    // ---- global projection (all N, fused LN+ReLU), then LN+scatter of fused rows ----
    gemm_tile<<<CDIV(NNODE, 128), 256>>>(gfeat, gp_W, gp_b, p_gx, NNODE, FGN,
                                         gp_g, gp_beta);
    ln_relu_scat_k<<<BB, HH>>>(p_tmp, fp_g, fp_beta, cid, p_gx);

    // ---- 2x global GATConv ----
    for (int l = 0; l < 2; l++) {
        gemm_mma<2, false><<<CDIV(NNODE, 128), 256, SMEM_MMA>>>(
            p_gx, p_wtf + (l == 0 ? WT_G0 : WT_G1), nullptr,
            p_gz, NNODE, HH, HH,
            glob_asrc + l * HH, glob_adst + l * HH, p_ssrc, p_sdst,
            nullptr, nullptr, nullptr, nullptr);
        gat_fused<2, 64, false><<<CDIV(NNODE, 8), 256>>>(p_growptr, p_gpsrc, (float*)nullptr,
                                                         (float*)nullptr, (float*)nullptr,
                                                         p_ssrc, p_sdst, p_gz,
                                                         glob_b + l * HH, p_gx, NNODE);
    }

    // ---- classifier ----
    classifier_k<<<CDIV(BB, 8), 256>>>(p_gx, cid, cls_W1, cls_b1, cls_W2, cls_b2,
                                       (float*)d_out);
}